// round 4
// baseline (speedup 1.0000x reference)
#include <cuda_runtime.h>
#include <cstdint>
#include <cmath>

// Problem constants
#define T_TOK 1024
#define HDIM  2048
#define NEXP  64
#define IDIM  1024
#define SIDIM 4096
#define KSEL  8
#define NROWS (T_TOK * KSEL)

// GEMM tile config
#define BM 128
#define BN 128                   // B rows per tile (ACT: 64 gate + 64 up)
#define BK 32
#define NSTAGE 3
#define STAGE_BYTES ((BM + BN) * BK * 4)            // 32768
#define GEMM_SMEM (NSTAGE * STAGE_BYTES + 512)      // 98816

// ---------------------------------------------------------------------------
// Device-global scratch
// ---------------------------------------------------------------------------
__device__ float g_h[(size_t)NROWS * IDIM];       // MoE silu*mul      [8192, 1024]
__device__ float g_down[(size_t)NROWS * HDIM];    // MoE down out      [8192, 2048]
__device__ float g_h_s[(size_t)T_TOK * SIDIM];    // shared act        [1024, 4096]
__device__ float g_sh_out[(size_t)T_TOK * HDIM];  // shared MLP out    [1024, 2048]

__device__ int   g_counts[NEXP];
__device__ int   g_offsets[NEXP];
__device__ int   g_fill[NEXP];
__device__ int   g_rowmap[NROWS];
__device__ int   g_row_of_tk[NROWS];
__device__ int   g_top_e[NROWS];
__device__ float g_top_w[NROWS];

// ---------------------------------------------------------------------------
// Helpers
// ---------------------------------------------------------------------------
__device__ __forceinline__ void cp_async16(void* smem, const void* gmem, int src_bytes) {
    uint32_t s = (uint32_t)__cvta_generic_to_shared(smem);
    asm volatile("cp.async.cg.shared.global [%0], [%1], 16, %2;\n"
                 :: "r"(s), "l"(gmem), "r"(src_bytes));
}
__device__ __forceinline__ void cp_commit() { asm volatile("cp.async.commit_group;\n"); }
__device__ __forceinline__ void cp_wait1()  { asm volatile("cp.async.wait_group 1;\n"); }

__device__ __forceinline__ uint32_t f2tf(float f) {
    uint32_t r;
    asm("cvt.rna.tf32.f32 %0, %1;" : "=r"(r) : "f"(f));
    return r;
}

__device__ __forceinline__ void mma_tf32(float c[4],
                                         uint32_t a0, uint32_t a1, uint32_t a2, uint32_t a3,
                                         uint32_t b0, uint32_t b1) {
    asm volatile(
        "mma.sync.aligned.m16n8k8.row.col.f32.tf32.tf32.f32 "
        "{%0,%1,%2,%3},{%4,%5,%6,%7},{%8,%9},{%0,%1,%2,%3};\n"
        : "+f"(c[0]), "+f"(c[1]), "+f"(c[2]), "+f"(c[3])
        : "r"(a0), "r"(a1), "r"(a2), "r"(a3), "r"(b0), "r"(b1));
}

__device__ __forceinline__ float silu_mul(float g, float u) {
    return g * u / (1.f + expf(-g));
}

// ---------------------------------------------------------------------------
// Routing kernels
// ---------------------------------------------------------------------------
__global__ void init_k() {
    int i = threadIdx.x;
    if (i < NEXP) g_counts[i] = 0;
}

__global__ void router_k(const float* __restrict__ x, const float* __restrict__ wg) {
    int t = blockIdx.x;
    __shared__ float xs[HDIM];
    __shared__ float sc[NEXP];
    for (int d = threadIdx.x; d < HDIM; d += blockDim.x) xs[d] = x[(size_t)t * HDIM + d];
    __syncthreads();

    int w = threadIdx.x >> 5, lane = threadIdx.x & 31;
    for (int e = w * 8; e < w * 8 + 8; e++) {
        const float* wr = wg + (size_t)e * HDIM;
        float s = 0.f;
        for (int d = lane; d < HDIM; d += 32) s += xs[d] * wr[d];
        #pragma unroll
        for (int o = 16; o; o >>= 1) s += __shfl_xor_sync(0xffffffffu, s, o);
        if (lane == 0) sc[e] = 1.f / (1.f + expf(-s));
    }
    __syncthreads();

    if (threadIdx.x == 0) {
        for (int k = 0; k < KSEL; k++) {
            int best = 0; float bv = sc[0];
            for (int e = 1; e < NEXP; e++)
                if (sc[e] > bv) { bv = sc[e]; best = e; }
            g_top_e[t * KSEL + k] = best;
            g_top_w[t * KSEL + k] = bv;
            atomicAdd(&g_counts[best], 1);
            sc[best] = -1.f;
        }
    }
}

__global__ void scan_k() {
    if (threadIdx.x == 0) {
        int acc = 0;
        for (int e = 0; e < NEXP; e++) {
            g_offsets[e] = acc;
            g_fill[e] = acc;
            acc += g_counts[e];
        }
    }
}

__global__ void assign_k() {
    int idx = blockIdx.x * blockDim.x + threadIdx.x;
    if (idx >= NROWS) return;
    int e = g_top_e[idx];
    int r = atomicAdd(&g_fill[e], 1);
    g_rowmap[r] = idx >> 3;
    g_row_of_tk[idx] = r;
}

// ---------------------------------------------------------------------------
// TF32 mma.sync GEMM. BM=128, BN=128, BK=32, 3-stage cp.async ring.
// SMEM layout per stage: 256 rows (128 A then 128 B) x 128 bytes, with the
// 16B-chunk index XOR-swizzled by (row & 7): conflict-free for both the
// cp.async store phases and the fragment LDS loads.
//   C[m,n] = sum_k A[m,k] * B[n,k]
//   8 warps = 4(M) x 2(N); warp tile 32 x 64.
// ---------------------------------------------------------------------------
template <bool GATHER, bool EXPERT, bool ACT>
__global__ void __launch_bounds__(256, 2)
gemm3(const float* __restrict__ A, const float* __restrict__ Bw, float* __restrict__ C,
      int Kd, int Nout, long strideBe, int upOff, int Mdense)
{
    extern __shared__ char sm[];
    int e = EXPERT ? blockIdx.z : 0;
    int M, off;
    if (EXPERT) { M = g_counts[e]; off = g_offsets[e]; }
    else        { M = Mdense;      off = 0; }
    int m0 = blockIdx.y * BM;
    if (m0 >= M) return;
    int nb = blockIdx.x;
    const float* B = Bw + (long)e * strideBe;

    int tid = threadIdx.x, warp = tid >> 5, lane = tid & 31;
    int* arows = (int*)(sm + NSTAGE * STAGE_BYTES);

    if (tid < BM) {
        int gr = m0 + tid;
        int ar = -1;
        if (gr < M) ar = GATHER ? g_rowmap[off + gr] : (off + gr);
        arows[tid] = ar;
    }
    __syncthreads();

    // ---- producer: thread tid owns smem row tid (0-127 A, 128-255 B) and
    //      copies its 128B (8 x 16B chunks, XOR-swizzled) per stage.
    const float* srcp;
    bool srcok = true;
    if (tid < BM) {
        int ar = arows[tid];
        srcok = (ar >= 0);
        if (!srcok) ar = arows[0] >= 0 ? arows[0] : 0;   // clamp; masked in epilogue
        srcp = A + (size_t)ar * Kd;
    } else {
        int prow = tid - BM;
        int brglob;
        if (ACT) brglob = (prow < 64) ? (nb * 64 + prow) : (upOff + nb * 64 + (prow - 64));
        else     brglob = nb * BN + prow;
        srcp = B + (size_t)brglob * Kd;
    }
    int rs = tid & 7;                            // row swizzle key
    char* myrow = sm + tid * 128;                // stage-0 row base

    auto stage_load = [&](int kt, int s) {
        const float* g = srcp + kt * BK;
        char* d = myrow + s * STAGE_BYTES;
        #pragma unroll
        for (int c = 0; c < 8; c++)
            cp_async16(d + ((c ^ rs) << 4), g + c * 4, 16);
    };

    // ---- consumer constants
    int wm = warp & 3;               // M slice (32 rows)
    int wn = warp >> 2;              // N slice (64 B rows)
    int g  = lane >> 2, tg = lane & 3;
    uint32_t tg4 = tg * 4;

    float acc[2][8][4];
    #pragma unroll
    for (int i = 0; i < 2; i++)
        #pragma unroll
        for (int j = 0; j < 8; j++)
            #pragma unroll
            for (int q = 0; q < 4; q++) acc[i][j][q] = 0.f;

    int ktiles = Kd / BK;

    stage_load(0, 0); cp_commit();
    stage_load(1, 1); cp_commit();

    for (int kt = 0; kt < ktiles; kt++) {
        cp_wait1();
        __syncthreads();
        char* stg = sm + (kt % NSTAGE) * STAGE_BYTES;
        char* Bst = stg + BM * 128;

        #pragma unroll
        for (int kk = 0; kk < BK; kk += 8) {
            int c0 = kk >> 2, c1 = c0 + 1;
            uint32_t o0 = ((c0 ^ g) << 4) + tg4;      // row&7 == g for all frag rows
            uint32_t o1 = ((c1 ^ g) << 4) + tg4;

            uint32_t afr[2][4];
            #pragma unroll
            for (int mi = 0; mi < 2; mi++) {
                int rb = wm * 32 + mi * 16;
                char* r0 = stg + (rb + g) * 128;
                char* r8 = stg + (rb + g + 8) * 128;
                afr[mi][0] = f2tf(*(const float*)(r0 + o0));
                afr[mi][1] = f2tf(*(const float*)(r8 + o0));
                afr[mi][2] = f2tf(*(const float*)(r0 + o1));
                afr[mi][3] = f2tf(*(const float*)(r8 + o1));
            }
            #pragma unroll
            for (int ni = 0; ni < 8; ni++) {
                int brow;
                if (ACT) brow = (ni < 4) ? (wn * 32 + ni * 8) : (64 + wn * 32 + (ni - 4) * 8);
                else     brow = wn * 64 + ni * 8;
                char* br = Bst + (brow + g) * 128;
                uint32_t b0 = f2tf(*(const float*)(br + o0));
                uint32_t b1 = f2tf(*(const float*)(br + o1));
                mma_tf32(acc[0][ni], afr[0][0], afr[0][1], afr[0][2], afr[0][3], b0, b1);
                mma_tf32(acc[1][ni], afr[1][0], afr[1][1], afr[1][2], afr[1][3], b0, b1);
            }
        }
        if (kt + 2 < ktiles) stage_load(kt + 2, (kt + 2) % NSTAGE);
        cp_commit();
    }

    // ---- epilogue
    #pragma unroll
    for (int mi = 0; mi < 2; mi++) {
        int r0 = m0 + wm * 32 + mi * 16 + g;
        bool v0 = r0 < M, v1 = (r0 + 8) < M;
        size_t base0 = (size_t)(off + r0) * Nout;
        size_t base1 = (size_t)(off + r0 + 8) * Nout;
        if (ACT) {
            #pragma unroll
            for (int ni = 0; ni < 4; ni++) {
                int col = nb * 64 + wn * 32 + ni * 8 + tg * 2;
                if (v0) {
                    float2 o;
                    o.x = silu_mul(acc[mi][ni][0], acc[mi][ni + 4][0]);
                    o.y = silu_mul(acc[mi][ni][1], acc[mi][ni + 4][1]);
                    *(float2*)(C + base0 + col) = o;
                }
                if (v1) {
                    float2 o;
                    o.x = silu_mul(acc[mi][ni][2], acc[mi][ni + 4][2]);
                    o.y = silu_mul(acc[mi][ni][3], acc[mi][ni + 4][3]);
                    *(float2*)(C + base1 + col) = o;
                }
            }
        } else {
            #pragma unroll
            for (int ni = 0; ni < 8; ni++) {
                int col = nb * BN + wn * 64 + ni * 8 + tg * 2;
                if (v0) {
                    float2 o; o.x = acc[mi][ni][0]; o.y = acc[mi][ni][1];
                    *(float2*)(C + base0 + col) = o;
                }
                if (v1) {
                    float2 o; o.x = acc[mi][ni][2]; o.y = acc[mi][ni][3];
                    *(float2*)(C + base1 + col) = o;
                }
            }
        }
    }
}

// ---------------------------------------------------------------------------
// Combine
// ---------------------------------------------------------------------------
__global__ void combine_k(float* __restrict__ out) {
    int t = blockIdx.x;
    __shared__ int   rws[KSEL];
    __shared__ float ws[KSEL];
    if (threadIdx.x < KSEL) {
        rws[threadIdx.x] = g_row_of_tk[t * KSEL + threadIdx.x];
        ws[threadIdx.x]  = g_top_w[t * KSEL + threadIdx.x];
    }
    __syncthreads();
    for (int d = threadIdx.x; d < HDIM; d += blockDim.x) {
        float a = g_sh_out[(size_t)t * HDIM + d];
        float m = 0.f;
        #pragma unroll
        for (int k = 0; k < KSEL; k++)
            m += ws[k] * g_down[(size_t)rws[k] * HDIM + d];
        out[(size_t)t * HDIM + d] = (a + 8.f * m) * (1.f / 9.f);
    }
}

// ---------------------------------------------------------------------------
// kernel_launch — graph-capturable, allocation-free.
// Launch order puts the shared-MLP GEMMs in slots 3-4 so ncu (-s 5 -c 1)
// profiles a real GEMM instead of assign_k.
// ---------------------------------------------------------------------------
extern "C" void kernel_launch(void* const* d_in, const int* in_sizes, int n_in,
                              void* d_out, int out_size)
{
    const float* x      = (const float*)d_in[0];
    const float* w_gate = (const float*)d_in[1];
    const float* w13    = (const float*)d_in[2];
    const float* w2     = (const float*)d_in[3];
    const float* wsg    = (const float*)d_in[4];
    const float* wsd    = (const float*)d_in[5];
    float* out = (float*)d_out;

    float *p_h, *p_down, *p_h_s, *p_sh_out;
    cudaGetSymbolAddress((void**)&p_h,      g_h);
    cudaGetSymbolAddress((void**)&p_down,   g_down);
    cudaGetSymbolAddress((void**)&p_h_s,    g_h_s);
    cudaGetSymbolAddress((void**)&p_sh_out, g_sh_out);

    cudaFuncSetAttribute(gemm3<true,  true,  true >, cudaFuncAttributeMaxDynamicSharedMemorySize, GEMM_SMEM);
    cudaFuncSetAttribute(gemm3<false, true,  false>, cudaFuncAttributeMaxDynamicSharedMemorySize, GEMM_SMEM);
    cudaFuncSetAttribute(gemm3<false, false, true >, cudaFuncAttributeMaxDynamicSharedMemorySize, GEMM_SMEM);
    cudaFuncSetAttribute(gemm3<false, false, false>, cudaFuncAttributeMaxDynamicSharedMemorySize, GEMM_SMEM);

    // slots 0-2: routing prep
    init_k<<<1, 64>>>();
    router_k<<<T_TOK, 256>>>(x, w_gate);
    scan_k<<<1, 32>>>();

    // slots 3-4: shared MLP (independent of routing) — profiled by ncu
    gemm3<false, false, true><<<dim3(SIDIM / 64, T_TOK / BM, 1), 256, GEMM_SMEM>>>(
        x, wsg, p_h_s, HDIM, SIDIM, 0, SIDIM, T_TOK);
    gemm3<false, false, false><<<dim3(HDIM / BN, T_TOK / BM, 1), 256, GEMM_SMEM>>>(
        p_h_s, wsd, p_sh_out, SIDIM, HDIM, 0, 0, T_TOK);

    // routing finalize + MoE
    assign_k<<<NROWS / 256, 256>>>();

    gemm3<true, true, true><<<dim3(IDIM / 64, 8, NEXP), 256, GEMM_SMEM>>>(
        x, w13, p_h, HDIM, IDIM, (long)2 * IDIM * HDIM, IDIM, 0);

    gemm3<false, true, false><<<dim3(HDIM / BN, 8, NEXP), 256, GEMM_SMEM>>>(
        p_h, w2, p_down, IDIM, HDIM, (long)HDIM * IDIM, 0, 0);

    // Combine
    combine_k<<<T_TOK, 256>>>(out);
}

// round 5
// speedup vs baseline: 1.0550x; 1.0550x over previous
#include <cuda_runtime.h>
#include <cstdint>
#include <cmath>

// Problem constants
#define T_TOK 1024
#define HDIM  2048
#define NEXP  64
#define IDIM  1024
#define SIDIM 4096
#define KSEL  8
#define NROWS (T_TOK * KSEL)

// GEMM tile config
#define BM 128
#define BN 128                   // B rows per tile (ACT: 64 gate + 64 up)
#define BK 32
#define NSTAGE 3
#define STAGE_BYTES ((BM + BN) * BK * 4)            // 32768
#define GEMM_SMEM (NSTAGE * STAGE_BYTES + 512)      // 98816

// ---------------------------------------------------------------------------
// Device-global scratch
// ---------------------------------------------------------------------------
__device__ float g_h[(size_t)NROWS * IDIM];       // MoE silu*mul      [8192, 1024]
__device__ float g_down[(size_t)NROWS * HDIM];    // MoE down out      [8192, 2048]
__device__ float g_h_s[(size_t)T_TOK * SIDIM];    // shared act        [1024, 4096]
__device__ float g_sh_out[(size_t)T_TOK * HDIM];  // shared MLP out    [1024, 2048]

__device__ int   g_counts[NEXP];
__device__ int   g_offsets[NEXP];
__device__ int   g_fill[NEXP];
__device__ int   g_rowmap[NROWS];
__device__ int   g_row_of_tk[NROWS];
__device__ int   g_top_e[NROWS];
__device__ float g_top_w[NROWS];

// ---------------------------------------------------------------------------
// Helpers
// ---------------------------------------------------------------------------
__device__ __forceinline__ void cp_async16(void* smem, const void* gmem, int src_bytes) {
    uint32_t s = (uint32_t)__cvta_generic_to_shared(smem);
    asm volatile("cp.async.cg.shared.global [%0], [%1], 16, %2;\n"
                 :: "r"(s), "l"(gmem), "r"(src_bytes));
}
__device__ __forceinline__ void cp_commit() { asm volatile("cp.async.commit_group;\n"); }
__device__ __forceinline__ void cp_wait1()  { asm volatile("cp.async.wait_group 1;\n"); }

__device__ __forceinline__ uint32_t f2tf(uint32_t bits) {
    uint32_t r;
    asm("cvt.rna.tf32.f32 %0, %1;" : "=r"(r) : "f"(__uint_as_float(bits)));
    return r;
}

__device__ __forceinline__ void ldm_x4(uint32_t& r0, uint32_t& r1, uint32_t& r2, uint32_t& r3,
                                       uint32_t addr) {
    asm volatile("ldmatrix.sync.aligned.m8n8.x4.shared.b16 {%0,%1,%2,%3}, [%4];"
                 : "=r"(r0), "=r"(r1), "=r"(r2), "=r"(r3) : "r"(addr));
}

__device__ __forceinline__ void mma_tf32(float c[4],
                                         uint32_t a0, uint32_t a1, uint32_t a2, uint32_t a3,
                                         uint32_t b0, uint32_t b1) {
    asm volatile(
        "mma.sync.aligned.m16n8k8.row.col.f32.tf32.tf32.f32 "
        "{%0,%1,%2,%3},{%4,%5,%6,%7},{%8,%9},{%0,%1,%2,%3};\n"
        : "+f"(c[0]), "+f"(c[1]), "+f"(c[2]), "+f"(c[3])
        : "r"(a0), "r"(a1), "r"(a2), "r"(a3), "r"(b0), "r"(b1));
}

__device__ __forceinline__ float silu_mul(float g, float u) {
    return g * u / (1.f + expf(-g));
}

// ---------------------------------------------------------------------------
// Routing kernels
// ---------------------------------------------------------------------------
__global__ void init_k() {
    int i = threadIdx.x;
    if (i < NEXP) g_counts[i] = 0;
}

__global__ void router_k(const float* __restrict__ x, const float* __restrict__ wg) {
    int t = blockIdx.x;
    __shared__ float xs[HDIM];
    __shared__ float sc[NEXP];
    for (int d = threadIdx.x; d < HDIM; d += blockDim.x) xs[d] = x[(size_t)t * HDIM + d];
    __syncthreads();

    int w = threadIdx.x >> 5, lane = threadIdx.x & 31;
    for (int e = w * 8; e < w * 8 + 8; e++) {
        const float* wr = wg + (size_t)e * HDIM;
        float s = 0.f;
        for (int d = lane; d < HDIM; d += 32) s += xs[d] * wr[d];
        #pragma unroll
        for (int o = 16; o; o >>= 1) s += __shfl_xor_sync(0xffffffffu, s, o);
        if (lane == 0) sc[e] = 1.f / (1.f + expf(-s));
    }
    __syncthreads();

    if (threadIdx.x == 0) {
        for (int k = 0; k < KSEL; k++) {
            int best = 0; float bv = sc[0];
            for (int e = 1; e < NEXP; e++)
                if (sc[e] > bv) { bv = sc[e]; best = e; }
            g_top_e[t * KSEL + k] = best;
            g_top_w[t * KSEL + k] = bv;
            atomicAdd(&g_counts[best], 1);
            sc[best] = -1.f;
        }
    }
}

__global__ void scan_k() {
    if (threadIdx.x == 0) {
        int acc = 0;
        for (int e = 0; e < NEXP; e++) {
            g_offsets[e] = acc;
            g_fill[e] = acc;
            acc += g_counts[e];
        }
    }
}

__global__ void assign_k() {
    int idx = blockIdx.x * blockDim.x + threadIdx.x;
    if (idx >= NROWS) return;
    int e = g_top_e[idx];
    int r = atomicAdd(&g_fill[e], 1);
    g_rowmap[r] = idx >> 3;
    g_row_of_tk[idx] = r;
}

// ---------------------------------------------------------------------------
// TF32 mma.sync GEMM. BM=128, BN=128, BK=32, 3-stage cp.async ring.
// Per-stage SMEM: 256 rows (128 A then 128 B) x 128B; 16B-chunk index
// XOR-swizzled by (row & 7). Fragments loaded with ldmatrix.m8n8.x4.b16
// (tf32 element mapping == mma fragment layout), cvt.rna on regs, then mma.
//   C[m,n] = sum_k A[m,k] * B[n,k];  8 warps = 4(M) x 2(N); warp tile 32x64.
// ---------------------------------------------------------------------------
template <bool GATHER, bool EXPERT, bool ACT>
__global__ void __launch_bounds__(256, 2)
gemm3(const float* __restrict__ A, const float* __restrict__ Bw, float* __restrict__ C,
      int Kd, int Nout, long strideBe, int upOff, int Mdense)
{
    extern __shared__ char sm[];
    int e = EXPERT ? blockIdx.z : 0;
    int M, off;
    if (EXPERT) { M = g_counts[e]; off = g_offsets[e]; }
    else        { M = Mdense;      off = 0; }
    int m0 = blockIdx.y * BM;
    if (m0 >= M) return;
    int nb = blockIdx.x;
    const float* B = Bw + (long)e * strideBe;

    int tid = threadIdx.x, warp = tid >> 5, lane = tid & 31;
    int* arows = (int*)(sm + NSTAGE * STAGE_BYTES);

    if (tid < BM) {
        int gr = m0 + tid;
        int ar = -1;
        if (gr < M) ar = GATHER ? g_rowmap[off + gr] : (off + gr);
        arows[tid] = ar;
    }
    __syncthreads();

    // ---- producer: thread tid owns smem row tid (0-127 A, 128-255 B);
    //      copies 128B (8 x 16B chunks, XOR-swizzled) per stage via cp.async.
    const float* srcp;
    if (tid < BM) {
        int ar = arows[tid];
        if (ar < 0) ar = arows[0] >= 0 ? arows[0] : 0;   // clamp; masked in epilogue
        srcp = A + (size_t)ar * Kd;
    } else {
        int prow = tid - BM;
        int brglob;
        if (ACT) brglob = (prow < 64) ? (nb * 64 + prow) : (upOff + nb * 64 + (prow - 64));
        else     brglob = nb * BN + prow;
        srcp = B + (size_t)brglob * Kd;
    }
    int rs = tid & 7;                            // row swizzle key
    char* myrow = sm + tid * 128;                // stage-0 row base

    auto stage_load = [&](int kt, int s) {
        const float* g = srcp + kt * BK;
        char* d = myrow + s * STAGE_BYTES;
        #pragma unroll
        for (int c = 0; c < 8; c++)
            cp_async16(d + ((c ^ rs) << 4), g + c * 4, 16);
    };

    // ---- consumer constants
    int wm = warp & 3;               // M slice (32 rows)
    int wn = warp >> 2;              // N slice (64 B rows)
    int g  = lane >> 2, tg = lane & 3;

    uint32_t smem_base = (uint32_t)__cvta_generic_to_shared(sm);

    // ldmatrix lane addressing.
    // A x4 tiles, in reg order a0,a1,a2,a3: {rb..rb+7,c0},{rb+8..15,c0},{rb..+7,c1},{rb+8..15,c1}
    //   lane -> row = rb + (lane&7) + ((lane>>3)&1)*8 ; chunk = c0 + (lane>>4)
    // B x4 tiles, order b0(ni),b1(ni),b0(ni+1),b1(ni+1): {n..n+7,c0},{n..n+7,c1},{n+8..15,c0},{n+8..15,c1}
    //   lane -> row = n + (lane&7) + ((lane>>4)&1)*8 ; chunk = c0 + ((lane>>3)&1)
    int aro  = (lane & 7) + ((lane >> 3) & 1) * 8;   // A row offset within 16
    int acs  = (lane >> 4) & 1;                      // A chunk select
    int bro  = (lane & 7) + ((lane >> 4) & 1) * 8;   // B row offset within 16
    int bcs  = (lane >> 3) & 1;                      // B chunk select

    uint32_t aRow[2], aMod[2];
    #pragma unroll
    for (int mi = 0; mi < 2; mi++) {
        int r = wm * 32 + mi * 16 + aro;
        aRow[mi] = (uint32_t)r * 128u;
        aMod[mi] = (uint32_t)(r & 7);
    }
    uint32_t bRow[4], bMod[4];
    #pragma unroll
    for (int p = 0; p < 4; p++) {
        int base;
        if (ACT) base = (p < 2) ? (wn * 32 + p * 16) : (64 + wn * 32 + (p - 2) * 16);
        else     base = wn * 64 + p * 16;
        int r = base + bro;
        bRow[p] = (uint32_t)(BM * 128 + r * 128);
        bMod[p] = (uint32_t)(r & 7);
    }

    float acc[2][8][4];
    #pragma unroll
    for (int i = 0; i < 2; i++)
        #pragma unroll
        for (int j = 0; j < 8; j++)
            #pragma unroll
            for (int q = 0; q < 4; q++) acc[i][j][q] = 0.f;

    int ktiles = Kd / BK;

    stage_load(0, 0); cp_commit();
    stage_load(1, 1); cp_commit();

    for (int kt = 0; kt < ktiles; kt++) {
        cp_wait1();
        __syncthreads();
        uint32_t stg = smem_base + (uint32_t)((kt % NSTAGE) * STAGE_BYTES);

        #pragma unroll
        for (int kk = 0; kk < BK; kk += 8) {
            uint32_t c0 = (uint32_t)(kk >> 2);

            uint32_t afr[2][4];
            #pragma unroll
            for (int mi = 0; mi < 2; mi++) {
                uint32_t addr = stg + aRow[mi] + ((((c0 + acs) ^ aMod[mi])) << 4);
                ldm_x4(afr[mi][0], afr[mi][1], afr[mi][2], afr[mi][3], addr);
            }
            uint32_t bfr[4][4];
            #pragma unroll
            for (int p = 0; p < 4; p++) {
                uint32_t addr = stg + bRow[p] + ((((c0 + bcs) ^ bMod[p])) << 4);
                ldm_x4(bfr[p][0], bfr[p][1], bfr[p][2], bfr[p][3], addr);
            }
            // cvt.rna f32 -> tf32 on register values
            #pragma unroll
            for (int mi = 0; mi < 2; mi++)
                #pragma unroll
                for (int q = 0; q < 4; q++) afr[mi][q] = f2tf(afr[mi][q]);
            #pragma unroll
            for (int p = 0; p < 4; p++)
                #pragma unroll
                for (int q = 0; q < 4; q++) bfr[p][q] = f2tf(bfr[p][q]);

            #pragma unroll
            for (int p = 0; p < 4; p++) {
                #pragma unroll
                for (int h = 0; h < 2; h++) {
                    int ni = p * 2 + h;
                    uint32_t b0 = bfr[p][2 * h], b1 = bfr[p][2 * h + 1];
                    mma_tf32(acc[0][ni], afr[0][0], afr[0][1], afr[0][2], afr[0][3], b0, b1);
                    mma_tf32(acc[1][ni], afr[1][0], afr[1][1], afr[1][2], afr[1][3], b0, b1);
                }
            }
        }
        if (kt + 2 < ktiles) stage_load(kt + 2, (kt + 2) % NSTAGE);
        cp_commit();
    }

    // ---- epilogue
    #pragma unroll
    for (int mi = 0; mi < 2; mi++) {
        int r0 = m0 + wm * 32 + mi * 16 + g;
        bool v0 = r0 < M, v1 = (r0 + 8) < M;
        size_t base0 = (size_t)(off + r0) * Nout;
        size_t base1 = (size_t)(off + r0 + 8) * Nout;
        if (ACT) {
            #pragma unroll
            for (int ni = 0; ni < 4; ni++) {
                int col = nb * 64 + wn * 32 + ni * 8 + tg * 2;
                if (v0) {
                    float2 o;
                    o.x = silu_mul(acc[mi][ni][0], acc[mi][ni + 4][0]);
                    o.y = silu_mul(acc[mi][ni][1], acc[mi][ni + 4][1]);
                    *(float2*)(C + base0 + col) = o;
                }
                if (v1) {
                    float2 o;
                    o.x = silu_mul(acc[mi][ni][2], acc[mi][ni + 4][2]);
                    o.y = silu_mul(acc[mi][ni][3], acc[mi][ni + 4][3]);
                    *(float2*)(C + base1 + col) = o;
                }
            }
        } else {
            #pragma unroll
            for (int ni = 0; ni < 8; ni++) {
                int col = nb * BN + wn * 64 + ni * 8 + tg * 2;
                if (v0) {
                    float2 o; o.x = acc[mi][ni][0]; o.y = acc[mi][ni][1];
                    *(float2*)(C + base0 + col) = o;
                }
                if (v1) {
                    float2 o; o.x = acc[mi][ni][2]; o.y = acc[mi][ni][3];
                    *(float2*)(C + base1 + col) = o;
                }
            }
        }
    }
}

// ---------------------------------------------------------------------------
// Combine
// ---------------------------------------------------------------------------
__global__ void combine_k(float* __restrict__ out) {
    int t = blockIdx.x;
    __shared__ int   rws[KSEL];
    __shared__ float ws[KSEL];
    if (threadIdx.x < KSEL) {
        rws[threadIdx.x] = g_row_of_tk[t * KSEL + threadIdx.x];
        ws[threadIdx.x]  = g_top_w[t * KSEL + threadIdx.x];
    }
    __syncthreads();
    for (int d = threadIdx.x; d < HDIM; d += blockDim.x) {
        float a = g_sh_out[(size_t)t * HDIM + d];
        float m = 0.f;
        #pragma unroll
        for (int k = 0; k < KSEL; k++)
            m += ws[k] * g_down[(size_t)rws[k] * HDIM + d];
        out[(size_t)t * HDIM + d] = (a + 8.f * m) * (1.f / 9.f);
    }
}

// ---------------------------------------------------------------------------
// kernel_launch — graph-capturable, allocation-free.
// Shared-MLP GEMMs in slots 3-4 so ncu (-s 5 -c 1) profiles a real GEMM.
// ---------------------------------------------------------------------------
extern "C" void kernel_launch(void* const* d_in, const int* in_sizes, int n_in,
                              void* d_out, int out_size)
{
    const float* x      = (const float*)d_in[0];
    const float* w_gate = (const float*)d_in[1];
    const float* w13    = (const float*)d_in[2];
    const float* w2     = (const float*)d_in[3];
    const float* wsg    = (const float*)d_in[4];
    const float* wsd    = (const float*)d_in[5];
    float* out = (float*)d_out;

    float *p_h, *p_down, *p_h_s, *p_sh_out;
    cudaGetSymbolAddress((void**)&p_h,      g_h);
    cudaGetSymbolAddress((void**)&p_down,   g_down);
    cudaGetSymbolAddress((void**)&p_h_s,    g_h_s);
    cudaGetSymbolAddress((void**)&p_sh_out, g_sh_out);

    cudaFuncSetAttribute(gemm3<true,  true,  true >, cudaFuncAttributeMaxDynamicSharedMemorySize, GEMM_SMEM);
    cudaFuncSetAttribute(gemm3<false, true,  false>, cudaFuncAttributeMaxDynamicSharedMemorySize, GEMM_SMEM);
    cudaFuncSetAttribute(gemm3<false, false, true >, cudaFuncAttributeMaxDynamicSharedMemorySize, GEMM_SMEM);
    cudaFuncSetAttribute(gemm3<false, false, false>, cudaFuncAttributeMaxDynamicSharedMemorySize, GEMM_SMEM);

    // slots 0-2: routing prep
    init_k<<<1, 64>>>();
    router_k<<<T_TOK, 256>>>(x, w_gate);
    scan_k<<<1, 32>>>();

    // slots 3-4: shared MLP (independent of routing) — profiled by ncu
    gemm3<false, false, true><<<dim3(SIDIM / 64, T_TOK / BM, 1), 256, GEMM_SMEM>>>(
        x, wsg, p_h_s, HDIM, SIDIM, 0, SIDIM, T_TOK);
    gemm3<false, false, false><<<dim3(HDIM / BN, T_TOK / BM, 1), 256, GEMM_SMEM>>>(
        p_h_s, wsd, p_sh_out, SIDIM, HDIM, 0, 0, T_TOK);

    // routing finalize + MoE
    assign_k<<<NROWS / 256, 256>>>();

    gemm3<true, true, true><<<dim3(IDIM / 64, 8, NEXP), 256, GEMM_SMEM>>>(
        x, w13, p_h, HDIM, IDIM, (long)2 * IDIM * HDIM, IDIM, 0);

    gemm3<false, true, false><<<dim3(HDIM / BN, 8, NEXP), 256, GEMM_SMEM>>>(
        p_h, w2, p_down, IDIM, HDIM, (long)HDIM * IDIM, 0, 0);

    // Combine
    combine_k<<<T_TOK, 256>>>(out);
}

// round 6
// speedup vs baseline: 1.2078x; 1.1449x over previous
#include <cuda_runtime.h>
#include <cstdint>
#include <cmath>

// Problem constants
#define T_TOK 1024
#define HDIM  2048
#define NEXP  64
#define IDIM  1024
#define SIDIM 4096
#define KSEL  8
#define NROWS (T_TOK * KSEL)

// GEMM tile config: CTA 128x128, 4 warps, warp tile 64x64
#define BM 128
#define BN 128                   // B rows per tile (ACT: 64 gate + 64 up)
#define BK 32
#define NSTAGE 3
#define STAGE_BYTES ((BM + BN) * BK * 4)            // 32768
#define GEMM_SMEM (NSTAGE * STAGE_BYTES + 512)      // 98816

// ---------------------------------------------------------------------------
// Device-global scratch
// ---------------------------------------------------------------------------
__device__ float g_h[(size_t)NROWS * IDIM];       // MoE silu*mul      [8192, 1024]
__device__ float g_down[(size_t)NROWS * HDIM];    // MoE down out      [8192, 2048]
__device__ float g_h_s[(size_t)T_TOK * SIDIM];    // shared act        [1024, 4096]
__device__ float g_sh_out[(size_t)T_TOK * HDIM];  // shared MLP out    [1024, 2048]

__device__ int   g_counts[NEXP];
__device__ int   g_offsets[NEXP];
__device__ int   g_fill[NEXP];
__device__ int   g_rowmap[NROWS];
__device__ int   g_row_of_tk[NROWS];
__device__ int   g_top_e[NROWS];
__device__ float g_top_w[NROWS];

// ---------------------------------------------------------------------------
// Helpers
// ---------------------------------------------------------------------------
__device__ __forceinline__ void cp_async16(void* smem, const void* gmem, int src_bytes) {
    uint32_t s = (uint32_t)__cvta_generic_to_shared(smem);
    asm volatile("cp.async.cg.shared.global [%0], [%1], 16, %2;\n"
                 :: "r"(s), "l"(gmem), "r"(src_bytes));
}
__device__ __forceinline__ void cp_commit() { asm volatile("cp.async.commit_group;\n"); }
__device__ __forceinline__ void cp_wait1()  { asm volatile("cp.async.wait_group 1;\n"); }

__device__ __forceinline__ uint32_t f2tf(uint32_t bits) {
    uint32_t r;
    asm("cvt.rna.tf32.f32 %0, %1;" : "=r"(r) : "f"(__uint_as_float(bits)));
    return r;
}

__device__ __forceinline__ void ldm_x4(uint32_t& r0, uint32_t& r1, uint32_t& r2, uint32_t& r3,
                                       uint32_t addr) {
    asm volatile("ldmatrix.sync.aligned.m8n8.x4.shared.b16 {%0,%1,%2,%3}, [%4];"
                 : "=r"(r0), "=r"(r1), "=r"(r2), "=r"(r3) : "r"(addr));
}

__device__ __forceinline__ void mma_tf32(float c[4],
                                         uint32_t a0, uint32_t a1, uint32_t a2, uint32_t a3,
                                         uint32_t b0, uint32_t b1) {
    asm volatile(
        "mma.sync.aligned.m16n8k8.row.col.f32.tf32.tf32.f32 "
        "{%0,%1,%2,%3},{%4,%5,%6,%7},{%8,%9},{%0,%1,%2,%3};\n"
        : "+f"(c[0]), "+f"(c[1]), "+f"(c[2]), "+f"(c[3])
        : "r"(a0), "r"(a1), "r"(a2), "r"(a3), "r"(b0), "r"(b1));
}

__device__ __forceinline__ float silu_mul(float g, float u) {
    return g * u / (1.f + expf(-g));
}

// ---------------------------------------------------------------------------
// Routing kernels
// ---------------------------------------------------------------------------
__global__ void init_k() {
    int i = threadIdx.x;
    if (i < NEXP) g_counts[i] = 0;
}

__global__ void router_k(const float* __restrict__ x, const float* __restrict__ wg) {
    int t = blockIdx.x;
    __shared__ float xs[HDIM];
    __shared__ float sc[NEXP];
    for (int d = threadIdx.x; d < HDIM; d += blockDim.x) xs[d] = x[(size_t)t * HDIM + d];
    __syncthreads();

    int w = threadIdx.x >> 5, lane = threadIdx.x & 31;
    for (int e = w * 8; e < w * 8 + 8; e++) {
        const float* wr = wg + (size_t)e * HDIM;
        float s = 0.f;
        for (int d = lane; d < HDIM; d += 32) s += xs[d] * wr[d];
        #pragma unroll
        for (int o = 16; o; o >>= 1) s += __shfl_xor_sync(0xffffffffu, s, o);
        if (lane == 0) sc[e] = 1.f / (1.f + expf(-s));
    }
    __syncthreads();

    if (threadIdx.x == 0) {
        for (int k = 0; k < KSEL; k++) {
            int best = 0; float bv = sc[0];
            for (int e = 1; e < NEXP; e++)
                if (sc[e] > bv) { bv = sc[e]; best = e; }
            g_top_e[t * KSEL + k] = best;
            g_top_w[t * KSEL + k] = bv;
            atomicAdd(&g_counts[best], 1);
            sc[best] = -1.f;
        }
    }
}

__global__ void scan_k() {
    if (threadIdx.x == 0) {
        int acc = 0;
        for (int e = 0; e < NEXP; e++) {
            g_offsets[e] = acc;
            g_fill[e] = acc;
            acc += g_counts[e];
        }
    }
}

__global__ void assign_k() {
    int idx = blockIdx.x * blockDim.x + threadIdx.x;
    if (idx >= NROWS) return;
    int e = g_top_e[idx];
    int r = atomicAdd(&g_fill[e], 1);
    g_rowmap[r] = idx >> 3;
    g_row_of_tk[idx] = r;
}

// ---------------------------------------------------------------------------
// TF32 mma.sync GEMM. CTA tile 128x128, 4 warps (2Mx2N), warp tile 64x64.
// BK=32, 3-stage cp.async ring. SMEM per stage: 256 rows x 128B, 16B-chunk
// index XOR-swizzled by (row & 7). Fragments via ldmatrix.m8n8.x4.b16,
// cvt.rna on regs, then mma.  C[m,n] = sum_k A[m,k] * B[n,k].
// ---------------------------------------------------------------------------
template <bool GATHER, bool EXPERT, bool ACT>
__global__ void __launch_bounds__(128, 2)
gemm4(const float* __restrict__ A, const float* __restrict__ Bw, float* __restrict__ C,
      int Kd, int Nout, long strideBe, int upOff, int Mdense)
{
    extern __shared__ char sm[];
    int e = EXPERT ? blockIdx.z : 0;
    int M, off;
    if (EXPERT) { M = g_counts[e]; off = g_offsets[e]; }
    else        { M = Mdense;      off = 0; }
    int m0 = blockIdx.y * BM;
    if (m0 >= M) return;
    int nb = blockIdx.x;
    const float* B = Bw + (long)e * strideBe;

    int tid = threadIdx.x, warp = tid >> 5, lane = tid & 31;
    int* arows = (int*)(sm + NSTAGE * STAGE_BYTES);

    {
        int gr = m0 + tid;
        int ar = -1;
        if (gr < M) ar = GATHER ? g_rowmap[off + gr] : (off + gr);
        arows[tid] = ar;
    }
    __syncthreads();

    // ---- producer: thread tid owns smem rows tid (A) and 128+tid (B);
    //      copies 2 x 128B (8 x 16B chunks each, XOR-swizzled) per stage.
    const float *srcA, *srcB;
    {
        int ar = arows[tid];
        if (ar < 0) ar = arows[0] >= 0 ? arows[0] : 0;   // clamp; masked in epilogue
        srcA = A + (size_t)ar * Kd;
        int prow = tid;
        int brglob;
        if (ACT) brglob = (prow < 64) ? (nb * 64 + prow) : (upOff + nb * 64 + (prow - 64));
        else     brglob = nb * BN + prow;
        srcB = B + (size_t)brglob * Kd;
    }
    int rs = tid & 7;                            // row swizzle key (same for both rows)
    char* myA = sm + tid * 128;
    char* myB = sm + (BM + tid) * 128;

    auto stage_load = [&](int kt, int s) {
        const float* ga = srcA + kt * BK;
        const float* gb = srcB + kt * BK;
        char* dA = myA + s * STAGE_BYTES;
        char* dB = myB + s * STAGE_BYTES;
        #pragma unroll
        for (int c = 0; c < 8; c++)
            cp_async16(dA + ((c ^ rs) << 4), ga + c * 4, 16);
        #pragma unroll
        for (int c = 0; c < 8; c++)
            cp_async16(dB + ((c ^ rs) << 4), gb + c * 4, 16);
    };

    // ---- consumer constants
    int wm = warp & 1;               // M slice (64 rows)
    int wn = warp >> 1;              // N slice (64 B rows / 32 out cols for ACT)
    int g  = lane >> 2, tg = lane & 3;

    uint32_t smem_base = (uint32_t)__cvta_generic_to_shared(sm);

    int aro  = (lane & 7) + ((lane >> 3) & 1) * 8;   // A row offset within 16
    int acs  = (lane >> 4) & 1;                      // A chunk select
    int bro  = (lane & 7) + ((lane >> 4) & 1) * 8;   // B row offset within 16
    int bcs  = (lane >> 3) & 1;                      // B chunk select

    uint32_t aRow[4], aMod[4];
    #pragma unroll
    for (int mi = 0; mi < 4; mi++) {
        int r = wm * 64 + mi * 16 + aro;
        aRow[mi] = (uint32_t)r * 128u;
        aMod[mi] = (uint32_t)(r & 7);
    }
    uint32_t bRow[4], bMod[4];
    #pragma unroll
    for (int p = 0; p < 4; p++) {
        int base;
        if (ACT) base = (p < 2) ? (wn * 32 + p * 16) : (64 + wn * 32 + (p - 2) * 16);
        else     base = wn * 64 + p * 16;
        int r = base + bro;
        bRow[p] = (uint32_t)(BM * 128 + r * 128);
        bMod[p] = (uint32_t)(r & 7);
    }

    float acc[4][8][4];
    #pragma unroll
    for (int i = 0; i < 4; i++)
        #pragma unroll
        for (int j = 0; j < 8; j++)
            #pragma unroll
            for (int q = 0; q < 4; q++) acc[i][j][q] = 0.f;

    int ktiles = Kd / BK;

    stage_load(0, 0); cp_commit();
    stage_load(1, 1); cp_commit();

    for (int kt = 0; kt < ktiles; kt++) {
        cp_wait1();
        __syncthreads();
        uint32_t stg = smem_base + (uint32_t)((kt % NSTAGE) * STAGE_BYTES);

        #pragma unroll
        for (int kk = 0; kk < BK; kk += 8) {
            uint32_t c0 = (uint32_t)(kk >> 2);

            uint32_t afr[4][4];
            #pragma unroll
            for (int mi = 0; mi < 4; mi++) {
                uint32_t addr = stg + aRow[mi] + ((((c0 + acs) ^ aMod[mi])) << 4);
                ldm_x4(afr[mi][0], afr[mi][1], afr[mi][2], afr[mi][3], addr);
            }
            uint32_t bfr[4][4];
            #pragma unroll
            for (int p = 0; p < 4; p++) {
                uint32_t addr = stg + bRow[p] + ((((c0 + bcs) ^ bMod[p])) << 4);
                ldm_x4(bfr[p][0], bfr[p][1], bfr[p][2], bfr[p][3], addr);
            }
            #pragma unroll
            for (int mi = 0; mi < 4; mi++)
                #pragma unroll
                for (int q = 0; q < 4; q++) afr[mi][q] = f2tf(afr[mi][q]);
            #pragma unroll
            for (int p = 0; p < 4; p++)
                #pragma unroll
                for (int q = 0; q < 4; q++) bfr[p][q] = f2tf(bfr[p][q]);

            #pragma unroll
            for (int p = 0; p < 4; p++) {
                #pragma unroll
                for (int h = 0; h < 2; h++) {
                    int ni = p * 2 + h;
                    uint32_t b0 = bfr[p][2 * h], b1 = bfr[p][2 * h + 1];
                    #pragma unroll
                    for (int mi = 0; mi < 4; mi++)
                        mma_tf32(acc[mi][ni], afr[mi][0], afr[mi][1], afr[mi][2], afr[mi][3], b0, b1);
                }
            }
        }
        if (kt + 2 < ktiles) stage_load(kt + 2, (kt + 2) % NSTAGE);
        cp_commit();
    }

    // ---- epilogue
    #pragma unroll
    for (int mi = 0; mi < 4; mi++) {
        int r0 = m0 + wm * 64 + mi * 16 + g;
        bool v0 = r0 < M, v1 = (r0 + 8) < M;
        size_t base0 = (size_t)(off + r0) * Nout;
        size_t base1 = (size_t)(off + r0 + 8) * Nout;
        if (ACT) {
            #pragma unroll
            for (int ni = 0; ni < 4; ni++) {
                int col = nb * 64 + wn * 32 + ni * 8 + tg * 2;
                if (v0) {
                    float2 o;
                    o.x = silu_mul(acc[mi][ni][0], acc[mi][ni + 4][0]);
                    o.y = silu_mul(acc[mi][ni][1], acc[mi][ni + 4][1]);
                    *(float2*)(C + base0 + col) = o;
                }
                if (v1) {
                    float2 o;
                    o.x = silu_mul(acc[mi][ni][2], acc[mi][ni + 4][2]);
                    o.y = silu_mul(acc[mi][ni][3], acc[mi][ni + 4][3]);
                    *(float2*)(C + base1 + col) = o;
                }
            }
        } else {
            #pragma unroll
            for (int ni = 0; ni < 8; ni++) {
                int col = nb * BN + wn * 64 + ni * 8 + tg * 2;
                if (v0) {
                    float2 o; o.x = acc[mi][ni][0]; o.y = acc[mi][ni][1];
                    *(float2*)(C + base0 + col) = o;
                }
                if (v1) {
                    float2 o; o.x = acc[mi][ni][2]; o.y = acc[mi][ni][3];
                    *(float2*)(C + base1 + col) = o;
                }
            }
        }
    }
}

// ---------------------------------------------------------------------------
// Combine
// ---------------------------------------------------------------------------
__global__ void combine_k(float* __restrict__ out) {
    int t = blockIdx.x;
    __shared__ int   rws[KSEL];
    __shared__ float ws[KSEL];
    if (threadIdx.x < KSEL) {
        rws[threadIdx.x] = g_row_of_tk[t * KSEL + threadIdx.x];
        ws[threadIdx.x]  = g_top_w[t * KSEL + threadIdx.x];
    }
    __syncthreads();
    for (int d = threadIdx.x; d < HDIM; d += blockDim.x) {
        float a = g_sh_out[(size_t)t * HDIM + d];
        float m = 0.f;
        #pragma unroll
        for (int k = 0; k < KSEL; k++)
            m += ws[k] * g_down[(size_t)rws[k] * HDIM + d];
        out[(size_t)t * HDIM + d] = (a + 8.f * m) * (1.f / 9.f);
    }
}

// ---------------------------------------------------------------------------
// kernel_launch — graph-capturable, allocation-free.
// Shared-MLP chain runs on a second stream (event fork/join DAG) so it
// overlaps the MoE chain. moe_gu sits in profile slot 6 for ncu (-s 5 -c 1).
// ---------------------------------------------------------------------------
extern "C" void kernel_launch(void* const* d_in, const int* in_sizes, int n_in,
                              void* d_out, int out_size)
{
    const float* x      = (const float*)d_in[0];
    const float* w_gate = (const float*)d_in[1];
    const float* w13    = (const float*)d_in[2];
    const float* w2     = (const float*)d_in[3];
    const float* wsg    = (const float*)d_in[4];
    const float* wsd    = (const float*)d_in[5];
    float* out = (float*)d_out;

    float *p_h, *p_down, *p_h_s, *p_sh_out;
    cudaGetSymbolAddress((void**)&p_h,      g_h);
    cudaGetSymbolAddress((void**)&p_down,   g_down);
    cudaGetSymbolAddress((void**)&p_h_s,    g_h_s);
    cudaGetSymbolAddress((void**)&p_sh_out, g_sh_out);

    cudaFuncSetAttribute(gemm4<true,  true,  true >, cudaFuncAttributeMaxDynamicSharedMemorySize, GEMM_SMEM);
    cudaFuncSetAttribute(gemm4<false, true,  false>, cudaFuncAttributeMaxDynamicSharedMemorySize, GEMM_SMEM);
    cudaFuncSetAttribute(gemm4<false, false, true >, cudaFuncAttributeMaxDynamicSharedMemorySize, GEMM_SMEM);
    cudaFuncSetAttribute(gemm4<false, false, false>, cudaFuncAttributeMaxDynamicSharedMemorySize, GEMM_SMEM);

    // Second stream + fork/join events (created once, outside any capture)
    static cudaStream_t s2 = nullptr;
    static cudaEvent_t evFork = nullptr, evJoin = nullptr;
    if (!s2) {
        cudaStreamCreateWithFlags(&s2, cudaStreamNonBlocking);
        cudaEventCreateWithFlags(&evFork, cudaEventDisableTiming);
        cudaEventCreateWithFlags(&evJoin, cudaEventDisableTiming);
    }

    // fork: s2 inherits the capture dependency
    cudaEventRecord(evFork, 0);
    cudaStreamWaitEvent(s2, evFork, 0);

    // MoE routing chain (stream 0): launches 1-4
    init_k<<<1, 64>>>();
    router_k<<<T_TOK, 256>>>(x, w_gate);
    scan_k<<<1, 32>>>();
    assign_k<<<NROWS / 256, 256>>>();

    // launch 5 (s2): shared gate_up (+act)
    gemm4<false, false, true><<<dim3(SIDIM / 64, T_TOK / BM, 1), 128, GEMM_SMEM, s2>>>(
        x, wsg, p_h_s, HDIM, SIDIM, 0, SIDIM, T_TOK);

    // launch 6 (stream 0): MoE gate_up (+act) — profiled by ncu
    gemm4<true, true, true><<<dim3(IDIM / 64, 8, NEXP), 128, GEMM_SMEM>>>(
        x, w13, p_h, HDIM, IDIM, (long)2 * IDIM * HDIM, IDIM, 0);

    // launch 7 (s2): shared down
    gemm4<false, false, false><<<dim3(HDIM / BN, T_TOK / BM, 1), 128, GEMM_SMEM, s2>>>(
        p_h_s, wsd, p_sh_out, SIDIM, HDIM, 0, 0, T_TOK);

    // launch 8 (stream 0): MoE down
    gemm4<false, true, false><<<dim3(HDIM / BN, 8, NEXP), 128, GEMM_SMEM>>>(
        p_h, w2, p_down, IDIM, HDIM, (long)HDIM * IDIM, 0, 0);

    // join: combine needs both chains
    cudaEventRecord(evJoin, s2);
    cudaStreamWaitEvent(0, evJoin, 0);

    // launch 9: combine
    combine_k<<<T_TOK, 256>>>(out);
}

// round 8
// speedup vs baseline: 1.3142x; 1.0881x over previous
#include <cuda_runtime.h>
#include <cuda_fp16.h>
#include <cstdint>
#include <cmath>

// Problem constants
#define T_TOK 1024
#define HDIM  2048
#define NEXP  64
#define IDIM  1024
#define SIDIM 4096
#define KSEL  8
#define NROWS (T_TOK * KSEL)

// Shared tile config (both GEMMs): CTA 128x128, 4 warps (2Mx2N), 128B k-rows
#define BM 128
#define BN 128
#define NSTAGE 3
#define STAGE_BYTES ((BM + BN) * 128)                // 32768
#define GEMM_SMEM (NSTAGE * STAGE_BYTES + 512)       // 98816

// ---------------------------------------------------------------------------
// Device-global scratch
// ---------------------------------------------------------------------------
__device__ __align__(256) float  g_h   [(size_t)NROWS * IDIM];     // MoE act (fp32, tf32 path)
__device__ __align__(256) float  g_down[(size_t)NROWS * HDIM];
__device__ __align__(256) __half g_xh  [(size_t)T_TOK * HDIM];     // shared A (fp16)
__device__ __align__(256) __half g_wsgh[(size_t)2 * SIDIM * HDIM];
__device__ __align__(256) __half g_wsdh[(size_t)HDIM * SIDIM];
__device__ __align__(256) __half g_h_s [(size_t)T_TOK * SIDIM];
__device__ __align__(256) float  g_sh_out[(size_t)T_TOK * HDIM];

__device__ int   g_counts[NEXP];
__device__ int   g_offsets[NEXP];
__device__ int   g_fill[NEXP];
__device__ int   g_rowmap[NROWS];
__device__ int   g_row_of_tk[NROWS];
__device__ int   g_top_e[NROWS];
__device__ float g_top_w[NROWS];

// ---------------------------------------------------------------------------
// Helpers
// ---------------------------------------------------------------------------
__device__ __forceinline__ void cp_async16(void* smem, const void* gmem) {
    uint32_t s = (uint32_t)__cvta_generic_to_shared(smem);
    asm volatile("cp.async.cg.shared.global [%0], [%1], 16;\n" :: "r"(s), "l"(gmem));
}
__device__ __forceinline__ void cp_commit() { asm volatile("cp.async.commit_group;\n"); }
__device__ __forceinline__ void cp_wait1()  { asm volatile("cp.async.wait_group 1;\n"); }

__device__ __forceinline__ uint32_t f2tf(uint32_t bits) {
    uint32_t r;
    asm("cvt.rna.tf32.f32 %0, %1;" : "=r"(r) : "f"(__uint_as_float(bits)));
    return r;
}

__device__ __forceinline__ void ldm_x4(uint32_t& r0, uint32_t& r1, uint32_t& r2, uint32_t& r3,
                                       uint32_t addr) {
    asm volatile("ldmatrix.sync.aligned.m8n8.x4.shared.b16 {%0,%1,%2,%3}, [%4];"
                 : "=r"(r0), "=r"(r1), "=r"(r2), "=r"(r3) : "r"(addr));
}

__device__ __forceinline__ void mma_tf32(float c[4],
                                         uint32_t a0, uint32_t a1, uint32_t a2, uint32_t a3,
                                         uint32_t b0, uint32_t b1) {
    asm volatile(
        "mma.sync.aligned.m16n8k8.row.col.f32.tf32.tf32.f32 "
        "{%0,%1,%2,%3},{%4,%5,%6,%7},{%8,%9},{%0,%1,%2,%3};\n"
        : "+f"(c[0]), "+f"(c[1]), "+f"(c[2]), "+f"(c[3])
        : "r"(a0), "r"(a1), "r"(a2), "r"(a3), "r"(b0), "r"(b1));
}

__device__ __forceinline__ void mma_f16(float c[4],
                                        uint32_t a0, uint32_t a1, uint32_t a2, uint32_t a3,
                                        uint32_t b0, uint32_t b1) {
    asm volatile(
        "mma.sync.aligned.m16n8k16.row.col.f32.f16.f16.f32 "
        "{%0,%1,%2,%3},{%4,%5,%6,%7},{%8,%9},{%0,%1,%2,%3};\n"
        : "+f"(c[0]), "+f"(c[1]), "+f"(c[2]), "+f"(c[3])
        : "r"(a0), "r"(a1), "r"(a2), "r"(a3), "r"(b0), "r"(b1));
}

__device__ __forceinline__ float silu_mul(float g, float u) {
    return g * u / (1.f + expf(-g));
}

// ---------------------------------------------------------------------------
// fp32 -> fp16 convert (pure bandwidth)
// ---------------------------------------------------------------------------
__global__ void cvt_k(const float4* __restrict__ in, uint2* __restrict__ outp, long n4) {
    long i = (long)blockIdx.x * blockDim.x + threadIdx.x;
    long stride = (long)gridDim.x * blockDim.x;
    for (; i < n4; i += stride) {
        float4 v = in[i];
        __half2 h0 = __floats2half2_rn(v.x, v.y);
        __half2 h1 = __floats2half2_rn(v.z, v.w);
        uint2 o;
        o.x = *(uint32_t*)&h0;
        o.y = *(uint32_t*)&h1;
        outp[i] = o;
    }
}

// ---------------------------------------------------------------------------
// Routing kernels
// ---------------------------------------------------------------------------
__global__ void init_k() {
    int i = threadIdx.x;
    if (i < NEXP) g_counts[i] = 0;
}

__global__ void router_k(const float* __restrict__ x, const float* __restrict__ wg) {
    int t = blockIdx.x;
    __shared__ float xs[HDIM];
    __shared__ float sc[NEXP];
    for (int d = threadIdx.x; d < HDIM; d += blockDim.x) xs[d] = x[(size_t)t * HDIM + d];
    __syncthreads();

    int w = threadIdx.x >> 5, lane = threadIdx.x & 31;
    for (int e = w * 8; e < w * 8 + 8; e++) {
        const float* wr = wg + (size_t)e * HDIM;
        float s = 0.f;
        for (int d = lane; d < HDIM; d += 32) s += xs[d] * wr[d];
        #pragma unroll
        for (int o = 16; o; o >>= 1) s += __shfl_xor_sync(0xffffffffu, s, o);
        if (lane == 0) sc[e] = 1.f / (1.f + expf(-s));
    }
    __syncthreads();

    if (threadIdx.x == 0) {
        for (int k = 0; k < KSEL; k++) {
            int best = 0; float bv = sc[0];
            for (int e = 1; e < NEXP; e++)
                if (sc[e] > bv) { bv = sc[e]; best = e; }
            g_top_e[t * KSEL + k] = best;
            g_top_w[t * KSEL + k] = bv;
            atomicAdd(&g_counts[best], 1);
            sc[best] = -1.f;
        }
    }
}

// merged scan + assign (single block) so MoE gate_up is host-launch slot 4
__global__ void scan_assign_k() {
    if (threadIdx.x == 0) {
        int acc = 0;
        for (int e = 0; e < NEXP; e++) {
            g_offsets[e] = acc;
            g_fill[e] = acc;
            acc += g_counts[e];
        }
    }
    __syncthreads();
    for (int idx = threadIdx.x; idx < NROWS; idx += blockDim.x) {
        int e = g_top_e[idx];
        int r = atomicAdd(&g_fill[e], 1);
        g_rowmap[r] = idx >> 3;
        g_row_of_tk[idx] = r;
    }
}

// ---------------------------------------------------------------------------
// gemm4 — TF32 mma.sync (round-6 verified, verbatim). fp32 in / fp32 out.
// CTA 128x128, 4 warps (2Mx2N), warp tile 64x64, BK=32 fp32 (128B rows).
// ---------------------------------------------------------------------------
template <bool GATHER, bool EXPERT, bool ACT>
__global__ void __launch_bounds__(128, 2)
gemm4(const float* __restrict__ A, const float* __restrict__ Bw, float* __restrict__ C,
      int Kd, int Nout, long strideBe, int upOff, int Mdense)
{
    extern __shared__ char sm[];
    int e = EXPERT ? blockIdx.z : 0;
    int M, off;
    if (EXPERT) { M = g_counts[e]; off = g_offsets[e]; }
    else        { M = Mdense;      off = 0; }
    int m0 = blockIdx.y * BM;
    if (m0 >= M) return;
    int nb = blockIdx.x;
    const float* B = Bw + (long)e * strideBe;

    int tid = threadIdx.x, warp = tid >> 5, lane = tid & 31;
    int* arows = (int*)(sm + NSTAGE * STAGE_BYTES);

    {
        int gr = m0 + tid;
        int ar = -1;
        if (gr < M) ar = GATHER ? g_rowmap[off + gr] : (off + gr);
        arows[tid] = ar;
    }
    __syncthreads();

    const float *srcA, *srcB;
    {
        int ar = arows[tid];
        if (ar < 0) ar = arows[0] >= 0 ? arows[0] : 0;
        srcA = A + (size_t)ar * Kd;
        int prow = tid;
        int brglob;
        if (ACT) brglob = (prow < 64) ? (nb * 64 + prow) : (upOff + nb * 64 + (prow - 64));
        else     brglob = nb * BN + prow;
        srcB = B + (size_t)brglob * Kd;
    }
    int rs = tid & 7;
    char* myA = sm + tid * 128;
    char* myB = sm + (BM + tid) * 128;

    auto stage_load = [&](int kt, int s) {
        const float* ga = srcA + kt * 32;
        const float* gb = srcB + kt * 32;
        char* dA = myA + s * STAGE_BYTES;
        char* dB = myB + s * STAGE_BYTES;
        #pragma unroll
        for (int c = 0; c < 8; c++)
            cp_async16(dA + ((c ^ rs) << 4), ga + c * 4);
        #pragma unroll
        for (int c = 0; c < 8; c++)
            cp_async16(dB + ((c ^ rs) << 4), gb + c * 4);
    };

    int wm = warp & 1;
    int wn = warp >> 1;
    int g  = lane >> 2, tg = lane & 3;

    uint32_t smem_base = (uint32_t)__cvta_generic_to_shared(sm);

    int aro  = (lane & 7) + ((lane >> 3) & 1) * 8;
    int acs  = (lane >> 4) & 1;
    int bro  = (lane & 7) + ((lane >> 4) & 1) * 8;
    int bcs  = (lane >> 3) & 1;

    uint32_t aRow[4], aMod[4];
    #pragma unroll
    for (int mi = 0; mi < 4; mi++) {
        int r = wm * 64 + mi * 16 + aro;
        aRow[mi] = (uint32_t)r * 128u;
        aMod[mi] = (uint32_t)(r & 7);
    }
    uint32_t bRow[4], bMod[4];
    #pragma unroll
    for (int p = 0; p < 4; p++) {
        int base;
        if (ACT) base = (p < 2) ? (wn * 32 + p * 16) : (64 + wn * 32 + (p - 2) * 16);
        else     base = wn * 64 + p * 16;
        int r = base + bro;
        bRow[p] = (uint32_t)(BM * 128 + r * 128);
        bMod[p] = (uint32_t)(r & 7);
    }

    float acc[4][8][4];
    #pragma unroll
    for (int i = 0; i < 4; i++)
        #pragma unroll
        for (int j = 0; j < 8; j++)
            #pragma unroll
            for (int q = 0; q < 4; q++) acc[i][j][q] = 0.f;

    int ktiles = Kd / 32;

    stage_load(0, 0); cp_commit();
    stage_load(1, 1); cp_commit();

    for (int kt = 0; kt < ktiles; kt++) {
        cp_wait1();
        __syncthreads();
        uint32_t stg = smem_base + (uint32_t)((kt % NSTAGE) * STAGE_BYTES);

        #pragma unroll
        for (int kk = 0; kk < 32; kk += 8) {
            uint32_t c0 = (uint32_t)(kk >> 2);

            uint32_t afr[4][4];
            #pragma unroll
            for (int mi = 0; mi < 4; mi++) {
                uint32_t addr = stg + aRow[mi] + ((((c0 + acs) ^ aMod[mi])) << 4);
                ldm_x4(afr[mi][0], afr[mi][1], afr[mi][2], afr[mi][3], addr);
            }
            uint32_t bfr[4][4];
            #pragma unroll
            for (int p = 0; p < 4; p++) {
                uint32_t addr = stg + bRow[p] + ((((c0 + bcs) ^ bMod[p])) << 4);
                ldm_x4(bfr[p][0], bfr[p][1], bfr[p][2], bfr[p][3], addr);
            }
            #pragma unroll
            for (int mi = 0; mi < 4; mi++)
                #pragma unroll
                for (int q = 0; q < 4; q++) afr[mi][q] = f2tf(afr[mi][q]);
            #pragma unroll
            for (int p = 0; p < 4; p++)
                #pragma unroll
                for (int q = 0; q < 4; q++) bfr[p][q] = f2tf(bfr[p][q]);

            #pragma unroll
            for (int p = 0; p < 4; p++) {
                #pragma unroll
                for (int h = 0; h < 2; h++) {
                    int ni = p * 2 + h;
                    uint32_t b0 = bfr[p][2 * h], b1 = bfr[p][2 * h + 1];
                    #pragma unroll
                    for (int mi = 0; mi < 4; mi++)
                        mma_tf32(acc[mi][ni], afr[mi][0], afr[mi][1], afr[mi][2], afr[mi][3], b0, b1);
                }
            }
        }
        if (kt + 2 < ktiles) stage_load(kt + 2, (kt + 2) % NSTAGE);
        cp_commit();
    }

    #pragma unroll
    for (int mi = 0; mi < 4; mi++) {
        int r0 = m0 + wm * 64 + mi * 16 + g;
        bool v0 = r0 < M, v1 = (r0 + 8) < M;
        size_t base0 = (size_t)(off + r0) * Nout;
        size_t base1 = (size_t)(off + r0 + 8) * Nout;
        if (ACT) {
            #pragma unroll
            for (int ni = 0; ni < 4; ni++) {
                int col = nb * 64 + wn * 32 + ni * 8 + tg * 2;
                if (v0) {
                    float2 o;
                    o.x = silu_mul(acc[mi][ni][0], acc[mi][ni + 4][0]);
                    o.y = silu_mul(acc[mi][ni][1], acc[mi][ni + 4][1]);
                    *(float2*)(C + base0 + col) = o;
                }
                if (v1) {
                    float2 o;
                    o.x = silu_mul(acc[mi][ni][2], acc[mi][ni + 4][2]);
                    o.y = silu_mul(acc[mi][ni][3], acc[mi][ni + 4][3]);
                    *(float2*)(C + base1 + col) = o;
                }
            }
        } else {
            #pragma unroll
            for (int ni = 0; ni < 8; ni++) {
                int col = nb * BN + wn * 64 + ni * 8 + tg * 2;
                if (v0) {
                    float2 o; o.x = acc[mi][ni][0]; o.y = acc[mi][ni][1];
                    *(float2*)(C + base0 + col) = o;
                }
                if (v1) {
                    float2 o; o.x = acc[mi][ni][2]; o.y = acc[mi][ni][3];
                    *(float2*)(C + base1 + col) = o;
                }
            }
        }
    }
}

// ---------------------------------------------------------------------------
// gemm5 — FP16 mma.sync (under test; dense non-gather use only this round).
// Same tiles; BK=64 fp16 (128B rows). ACT writes __half, non-ACT writes fp32.
// ---------------------------------------------------------------------------
template <bool ACT>
__global__ void __launch_bounds__(128, 2)
gemm5(const __half* __restrict__ A, const __half* __restrict__ Bw, void* __restrict__ Cv,
      int Kd, int Nout, int upOff, int Mdense)
{
    extern __shared__ char sm[];
    int M = Mdense, off = 0;
    int m0 = blockIdx.y * BM;
    if (m0 >= M) return;
    int nb = blockIdx.x;
    const __half* B = Bw;

    int tid = threadIdx.x, warp = tid >> 5, lane = tid & 31;

    const __half *srcA, *srcB;
    {
        int gr = m0 + tid;
        int ar = (gr < M) ? gr : 0;
        srcA = A + (size_t)ar * Kd;
        int prow = tid;
        int brglob;
        if (ACT) brglob = (prow < 64) ? (nb * 64 + prow) : (upOff + nb * 64 + (prow - 64));
        else     brglob = nb * BN + prow;
        srcB = B + (size_t)brglob * Kd;
    }
    int rs = tid & 7;
    char* myA = sm + tid * 128;
    char* myB = sm + (BM + tid) * 128;

    auto stage_load = [&](int kt, int s) {
        const __half* ga = srcA + kt * 64;
        const __half* gb = srcB + kt * 64;
        char* dA = myA + s * STAGE_BYTES;
        char* dB = myB + s * STAGE_BYTES;
        #pragma unroll
        for (int c = 0; c < 8; c++)
            cp_async16(dA + ((c ^ rs) << 4), ga + c * 8);
        #pragma unroll
        for (int c = 0; c < 8; c++)
            cp_async16(dB + ((c ^ rs) << 4), gb + c * 8);
    };

    int wm = warp & 1;
    int wn = warp >> 1;
    int g  = lane >> 2, tg = lane & 3;

    uint32_t smem_base = (uint32_t)__cvta_generic_to_shared(sm);

    int aro  = (lane & 7) + ((lane >> 3) & 1) * 8;
    int acs  = (lane >> 4) & 1;
    int bro  = (lane & 7) + ((lane >> 4) & 1) * 8;
    int bcs  = (lane >> 3) & 1;

    uint32_t aRow[4], aMod[4];
    #pragma unroll
    for (int mi = 0; mi < 4; mi++) {
        int r = wm * 64 + mi * 16 + aro;
        aRow[mi] = (uint32_t)r * 128u;
        aMod[mi] = (uint32_t)(r & 7);
    }
    uint32_t bRow[4], bMod[4];
    #pragma unroll
    for (int p = 0; p < 4; p++) {
        int base;
        if (ACT) base = (p < 2) ? (wn * 32 + p * 16) : (64 + wn * 32 + (p - 2) * 16);
        else     base = wn * 64 + p * 16;
        int r = base + bro;
        bRow[p] = (uint32_t)(BM * 128 + r * 128);
        bMod[p] = (uint32_t)(r & 7);
    }

    float acc[4][8][4];
    #pragma unroll
    for (int i = 0; i < 4; i++)
        #pragma unroll
        for (int j = 0; j < 8; j++)
            #pragma unroll
            for (int q = 0; q < 4; q++) acc[i][j][q] = 0.f;

    int ktiles = Kd / 64;

    stage_load(0, 0); cp_commit();
    stage_load(1, 1); cp_commit();

    for (int kt = 0; kt < ktiles; kt++) {
        cp_wait1();
        __syncthreads();
        uint32_t stg = smem_base + (uint32_t)((kt % NSTAGE) * STAGE_BYTES);

        #pragma unroll
        for (int kk = 0; kk < 4; kk++) {
            uint32_t c0 = (uint32_t)(kk * 2);

            uint32_t afr[4][4];
            #pragma unroll
            for (int mi = 0; mi < 4; mi++) {
                uint32_t addr = stg + aRow[mi] + ((((c0 + acs) ^ aMod[mi])) << 4);
                ldm_x4(afr[mi][0], afr[mi][1], afr[mi][2], afr[mi][3], addr);
            }
            uint32_t bfr[4][4];
            #pragma unroll
            for (int p = 0; p < 4; p++) {
                uint32_t addr = stg + bRow[p] + ((((c0 + bcs) ^ bMod[p])) << 4);
                ldm_x4(bfr[p][0], bfr[p][1], bfr[p][2], bfr[p][3], addr);
            }
            #pragma unroll
            for (int p = 0; p < 4; p++) {
                #pragma unroll
                for (int h = 0; h < 2; h++) {
                    int ni = p * 2 + h;
                    uint32_t b0 = bfr[p][2 * h], b1 = bfr[p][2 * h + 1];
                    #pragma unroll
                    for (int mi = 0; mi < 4; mi++)
                        mma_f16(acc[mi][ni], afr[mi][0], afr[mi][1], afr[mi][2], afr[mi][3], b0, b1);
                }
            }
        }
        if (kt + 2 < ktiles) stage_load(kt + 2, (kt + 2) % NSTAGE);
        cp_commit();
    }

    #pragma unroll
    for (int mi = 0; mi < 4; mi++) {
        int r0 = m0 + wm * 64 + mi * 16 + g;
        bool v0 = r0 < M, v1 = (r0 + 8) < M;
        size_t base0 = (size_t)(off + r0) * Nout;
        size_t base1 = (size_t)(off + r0 + 8) * Nout;
        if (ACT) {
            __half* Ch = (__half*)Cv;
            #pragma unroll
            for (int ni = 0; ni < 4; ni++) {
                int col = nb * 64 + wn * 32 + ni * 8 + tg * 2;
                if (v0) {
                    __half2 o = __floats2half2_rn(
                        silu_mul(acc[mi][ni][0], acc[mi][ni + 4][0]),
                        silu_mul(acc[mi][ni][1], acc[mi][ni + 4][1]));
                    *(__half2*)(Ch + base0 + col) = o;
                }
                if (v1) {
                    __half2 o = __floats2half2_rn(
                        silu_mul(acc[mi][ni][2], acc[mi][ni + 4][2]),
                        silu_mul(acc[mi][ni][3], acc[mi][ni + 4][3]));
                    *(__half2*)(Ch + base1 + col) = o;
                }
            }
        } else {
            float* Cf = (float*)Cv;
            #pragma unroll
            for (int ni = 0; ni < 8; ni++) {
                int col = nb * BN + wn * 64 + ni * 8 + tg * 2;
                if (v0) {
                    float2 o; o.x = acc[mi][ni][0]; o.y = acc[mi][ni][1];
                    *(float2*)(Cf + base0 + col) = o;
                }
                if (v1) {
                    float2 o; o.x = acc[mi][ni][2]; o.y = acc[mi][ni][3];
                    *(float2*)(Cf + base1 + col) = o;
                }
            }
        }
    }
}

// ---------------------------------------------------------------------------
// Combine
// ---------------------------------------------------------------------------
__global__ void combine_k(float* __restrict__ out) {
    int t = blockIdx.x;
    __shared__ int   rws[KSEL];
    __shared__ float ws[KSEL];
    if (threadIdx.x < KSEL) {
        rws[threadIdx.x] = g_row_of_tk[t * KSEL + threadIdx.x];
        ws[threadIdx.x]  = g_top_w[t * KSEL + threadIdx.x];
    }
    __syncthreads();
    for (int d = threadIdx.x; d < HDIM; d += blockDim.x) {
        float a = g_sh_out[(size_t)t * HDIM + d];
        float m = 0.f;
        #pragma unroll
        for (int k = 0; k < KSEL; k++)
            m += ws[k] * g_down[(size_t)rws[k] * HDIM + d];
        out[(size_t)t * HDIM + d] = (a + 8.f * m) * (1.f / 9.f);
    }
}

// ---------------------------------------------------------------------------
// kernel_launch — graph-capturable, allocation-free, two-stream DAG.
// Host-launch slot 4 = MoE gate_up (tf32) so ncu profiles it.
// ---------------------------------------------------------------------------
extern "C" void kernel_launch(void* const* d_in, const int* in_sizes, int n_in,
                              void* d_out, int out_size)
{
    const float* x      = (const float*)d_in[0];
    const float* w_gate = (const float*)d_in[1];
    const float* w13    = (const float*)d_in[2];
    const float* w2     = (const float*)d_in[3];
    const float* wsg    = (const float*)d_in[4];
    const float* wsd    = (const float*)d_in[5];
    float* out = (float*)d_out;

    float  *p_h, *p_down, *p_sh_out;
    __half *p_xh, *p_wsgh, *p_wsdh, *p_h_s;
    cudaGetSymbolAddress((void**)&p_h,      g_h);
    cudaGetSymbolAddress((void**)&p_down,   g_down);
    cudaGetSymbolAddress((void**)&p_xh,     g_xh);
    cudaGetSymbolAddress((void**)&p_wsgh,   g_wsgh);
    cudaGetSymbolAddress((void**)&p_wsdh,   g_wsdh);
    cudaGetSymbolAddress((void**)&p_h_s,    g_h_s);
    cudaGetSymbolAddress((void**)&p_sh_out, g_sh_out);

    cudaFuncSetAttribute(gemm4<true,  true,  true >, cudaFuncAttributeMaxDynamicSharedMemorySize, GEMM_SMEM);
    cudaFuncSetAttribute(gemm4<false, true,  false>, cudaFuncAttributeMaxDynamicSharedMemorySize, GEMM_SMEM);
    cudaFuncSetAttribute(gemm5<true >, cudaFuncAttributeMaxDynamicSharedMemorySize, GEMM_SMEM);
    cudaFuncSetAttribute(gemm5<false>, cudaFuncAttributeMaxDynamicSharedMemorySize, GEMM_SMEM);

    static cudaStream_t s2 = nullptr;
    static cudaEvent_t evFork = nullptr, evJoin = nullptr;
    if (!s2) {
        cudaStreamCreateWithFlags(&s2, cudaStreamNonBlocking);
        cudaEventCreateWithFlags(&evFork, cudaEventDisableTiming);
        cudaEventCreateWithFlags(&evJoin, cudaEventDisableTiming);
    }

    // fork at graph root: shared chain is independent of routing
    cudaEventRecord(evFork, 0);
    cudaStreamWaitEvent(s2, evFork, 0);

    // s0 (slots 1-3): routing
    init_k<<<1, 64>>>();
    router_k<<<T_TOK, 256>>>(x, w_gate);
    scan_assign_k<<<1, 256>>>();

    // s0 slot 4: MoE gate_up tf32 (profiled by ncu)
    gemm4<true, true, true><<<dim3(IDIM / 64, 8, NEXP), 128, GEMM_SMEM>>>(
        x, w13, p_h, HDIM, IDIM, (long)2 * IDIM * HDIM, IDIM, 0);

    // s0 slot 5: MoE down tf32
    gemm4<false, true, false><<<dim3(HDIM / BN, 8, NEXP), 128, GEMM_SMEM>>>(
        p_h, w2, p_down, IDIM, HDIM, (long)HDIM * IDIM, 0, 0);

    // s2: shared chain in fp16 (converts + 2 GEMMs), fully overlapped
    cvt_k<<<1024, 256, 0, s2>>>((const float4*)x,   (uint2*)p_xh,   (long)T_TOK * HDIM / 4);
    cvt_k<<<2048, 256, 0, s2>>>((const float4*)wsg, (uint2*)p_wsgh, (long)2 * SIDIM * HDIM / 4);
    cvt_k<<<2048, 256, 0, s2>>>((const float4*)wsd, (uint2*)p_wsdh, (long)HDIM * SIDIM / 4);
    gemm5<true ><<<dim3(SIDIM / 64, T_TOK / BM, 1), 128, GEMM_SMEM, s2>>>(
        p_xh, p_wsgh, p_h_s, HDIM, SIDIM, SIDIM, T_TOK);
    gemm5<false><<<dim3(HDIM / BN, T_TOK / BM, 1), 128, GEMM_SMEM, s2>>>(
        p_h_s, p_wsdh, p_sh_out, SIDIM, HDIM, 0, T_TOK);
    cudaEventRecord(evJoin, s2);

    // join + combine
    cudaStreamWaitEvent(0, evJoin, 0);
    combine_k<<<T_TOK, 256>>>(out);
}

// round 9
// speedup vs baseline: 1.7300x; 1.3164x over previous
#include <cuda_runtime.h>
#include <cuda_fp16.h>
#include <cstdint>
#include <cmath>

// Problem constants
#define T_TOK 1024
#define HDIM  2048
#define NEXP  64
#define IDIM  1024
#define SIDIM 4096
#define KSEL  8
#define NROWS (T_TOK * KSEL)

// Tile config: CTA 128x128, 4 warps (2Mx2N), warp tile 64x64, fp16 BK=64 (128B rows)
#define BM 128
#define BN 128
#define NSTAGE 3
#define STAGE_BYTES ((BM + BN) * 128)                // 32768
#define GEMM_SMEM (NSTAGE * STAGE_BYTES + 512)       // 98816

// ---------------------------------------------------------------------------
// Device-global scratch
// ---------------------------------------------------------------------------
__device__ __align__(256) __half g_w13h[(size_t)NEXP * 2 * IDIM * HDIM]; // 512MB
__device__ __align__(256) __half g_w2h [(size_t)NEXP * HDIM * IDIM];     // 256MB
__device__ __align__(256) __half g_wsgh[(size_t)2 * SIDIM * HDIM];       // 32MB
__device__ __align__(256) __half g_wsdh[(size_t)HDIM * SIDIM];           // 16MB
__device__ __align__(256) __half g_xh  [(size_t)T_TOK * HDIM];
__device__ __align__(256) __half g_h   [(size_t)NROWS * IDIM];
__device__ __align__(256) __half g_h_s [(size_t)T_TOK * SIDIM];
__device__ __align__(256) float  g_down[(size_t)NROWS * HDIM];
__device__ __align__(256) float  g_sh_out[(size_t)T_TOK * HDIM];

__device__ int   g_counts[NEXP];
__device__ int   g_offsets[NEXP];
__device__ int   g_fill[NEXP];
__device__ int   g_rowmap[NROWS];
__device__ int   g_row_of_tk[NROWS];
__device__ int   g_top_e[NROWS];
__device__ float g_top_w[NROWS];

// ---------------------------------------------------------------------------
// Helpers
// ---------------------------------------------------------------------------
__device__ __forceinline__ void cp_async16(void* smem, const void* gmem) {
    uint32_t s = (uint32_t)__cvta_generic_to_shared(smem);
    asm volatile("cp.async.cg.shared.global [%0], [%1], 16;\n" :: "r"(s), "l"(gmem));
}
__device__ __forceinline__ void cp_commit() { asm volatile("cp.async.commit_group;\n"); }
__device__ __forceinline__ void cp_wait1()  { asm volatile("cp.async.wait_group 1;\n"); }

__device__ __forceinline__ void ldm_x4(uint32_t& r0, uint32_t& r1, uint32_t& r2, uint32_t& r3,
                                       uint32_t addr) {
    asm volatile("ldmatrix.sync.aligned.m8n8.x4.shared.b16 {%0,%1,%2,%3}, [%4];"
                 : "=r"(r0), "=r"(r1), "=r"(r2), "=r"(r3) : "r"(addr));
}

__device__ __forceinline__ void mma_f16(float c[4],
                                        uint32_t a0, uint32_t a1, uint32_t a2, uint32_t a3,
                                        uint32_t b0, uint32_t b1) {
    asm volatile(
        "mma.sync.aligned.m16n8k16.row.col.f32.f16.f16.f32 "
        "{%0,%1,%2,%3},{%4,%5,%6,%7},{%8,%9},{%0,%1,%2,%3};\n"
        : "+f"(c[0]), "+f"(c[1]), "+f"(c[2]), "+f"(c[3])
        : "r"(a0), "r"(a1), "r"(a2), "r"(a3), "r"(b0), "r"(b1));
}

__device__ __forceinline__ float silu_mul(float g, float u) {
    return g * u / (1.f + expf(-g));
}

// ---------------------------------------------------------------------------
// fp32 -> fp16 convert (pure bandwidth). Variant with router-count init fused.
// ---------------------------------------------------------------------------
__global__ void cvt_k(const float4* __restrict__ in, uint2* __restrict__ outp, long n4) {
    long i = (long)blockIdx.x * blockDim.x + threadIdx.x;
    long stride = (long)gridDim.x * blockDim.x;
    for (; i < n4; i += stride) {
        float4 v = in[i];
        __half2 h0 = __floats2half2_rn(v.x, v.y);
        __half2 h1 = __floats2half2_rn(v.z, v.w);
        uint2 o;
        o.x = *(uint32_t*)&h0;
        o.y = *(uint32_t*)&h1;
        outp[i] = o;
    }
}

__global__ void cvt_init_k(const float4* __restrict__ in, uint2* __restrict__ outp, long n4) {
    if (blockIdx.x == 0 && threadIdx.x < NEXP) g_counts[threadIdx.x] = 0;
    long i = (long)blockIdx.x * blockDim.x + threadIdx.x;
    long stride = (long)gridDim.x * blockDim.x;
    for (; i < n4; i += stride) {
        float4 v = in[i];
        __half2 h0 = __floats2half2_rn(v.x, v.y);
        __half2 h1 = __floats2half2_rn(v.z, v.w);
        uint2 o;
        o.x = *(uint32_t*)&h0;
        o.y = *(uint32_t*)&h1;
        outp[i] = o;
    }
}

// ---------------------------------------------------------------------------
// Routing kernels
// ---------------------------------------------------------------------------
__global__ void router_k(const float* __restrict__ x, const float* __restrict__ wg) {
    int t = blockIdx.x;
    __shared__ float xs[HDIM];
    __shared__ float sc[NEXP];
    for (int d = threadIdx.x; d < HDIM; d += blockDim.x) xs[d] = x[(size_t)t * HDIM + d];
    __syncthreads();

    int w = threadIdx.x >> 5, lane = threadIdx.x & 31;
    for (int e = w * 8; e < w * 8 + 8; e++) {
        const float* wr = wg + (size_t)e * HDIM;
        float s = 0.f;
        for (int d = lane; d < HDIM; d += 32) s += xs[d] * wr[d];
        #pragma unroll
        for (int o = 16; o; o >>= 1) s += __shfl_xor_sync(0xffffffffu, s, o);
        if (lane == 0) sc[e] = 1.f / (1.f + expf(-s));
    }
    __syncthreads();

    if (threadIdx.x == 0) {
        for (int k = 0; k < KSEL; k++) {
            int best = 0; float bv = sc[0];
            for (int e = 1; e < NEXP; e++)
                if (sc[e] > bv) { bv = sc[e]; best = e; }
            g_top_e[t * KSEL + k] = best;
            g_top_w[t * KSEL + k] = bv;
            atomicAdd(&g_counts[best], 1);
            sc[best] = -1.f;
        }
    }
}

__global__ void scan_assign_k() {
    if (threadIdx.x == 0) {
        int acc = 0;
        for (int e = 0; e < NEXP; e++) {
            g_offsets[e] = acc;
            g_fill[e] = acc;
            acc += g_counts[e];
        }
    }
    __syncthreads();
    for (int idx = threadIdx.x; idx < NROWS; idx += blockDim.x) {
        int e = g_top_e[idx];
        int r = atomicAdd(&g_fill[e], 1);
        g_rowmap[r] = idx >> 3;
        g_row_of_tk[idx] = r;
    }
}

// ---------------------------------------------------------------------------
// gemm6 — FP16 mma.sync, full template. CTA 128x128, 4 warps, warp 64x64,
// BK=64 fp16 (128B rows), 3-stage cp.async ring, XOR-swizzled 16B chunks,
// ldmatrix.x4 fragments. C[m,n] = sum_k A[m,k]*B[n,k]; fp32 accum.
// ACT: B tile = 64 gate + 64 up rows; epilogue silu(g)*u -> __half.
// non-ACT epilogue -> fp32.
// ---------------------------------------------------------------------------
template <bool GATHER, bool EXPERT, bool ACT>
__global__ void __launch_bounds__(128, 2)
gemm6(const __half* __restrict__ A, const __half* __restrict__ Bw, void* __restrict__ Cv,
      int Kd, int Nout, size_t strideBe, int upOff, int Mdense)
{
    extern __shared__ char sm[];
    int e = EXPERT ? blockIdx.z : 0;
    int M, off;
    if (EXPERT) { M = g_counts[e]; off = g_offsets[e]; }
    else        { M = Mdense;      off = 0; }
    int m0 = blockIdx.y * BM;
    if (m0 >= M) return;
    int nb = blockIdx.x;
    const __half* B = Bw + (size_t)e * strideBe;

    int tid = threadIdx.x, warp = tid >> 5, lane = tid & 31;
    int* arows = (int*)(sm + NSTAGE * STAGE_BYTES);

    {
        int gr = m0 + tid;
        int ar = -1;
        if (gr < M) ar = GATHER ? g_rowmap[off + gr] : (off + gr);
        arows[tid] = ar;
    }
    __syncthreads();

    const __half *srcA, *srcB;
    {
        int ar = arows[tid];
        if (ar < 0) ar = arows[0] >= 0 ? arows[0] : 0;   // clamp; masked in epilogue
        srcA = A + (size_t)ar * Kd;
        int prow = tid;
        int brglob;
        if (ACT) brglob = (prow < 64) ? (nb * 64 + prow) : (upOff + nb * 64 + (prow - 64));
        else     brglob = nb * BN + prow;
        srcB = B + (size_t)brglob * Kd;
    }
    int rs = tid & 7;
    char* myA = sm + tid * 128;
    char* myB = sm + (BM + tid) * 128;

    auto stage_load = [&](int kt, int s) {
        const __half* ga = srcA + kt * 64;
        const __half* gb = srcB + kt * 64;
        char* dA = myA + s * STAGE_BYTES;
        char* dB = myB + s * STAGE_BYTES;
        #pragma unroll
        for (int c = 0; c < 8; c++)
            cp_async16(dA + ((c ^ rs) << 4), ga + c * 8);
        #pragma unroll
        for (int c = 0; c < 8; c++)
            cp_async16(dB + ((c ^ rs) << 4), gb + c * 8);
    };

    int wm = warp & 1;
    int wn = warp >> 1;
    int g  = lane >> 2, tg = lane & 3;

    uint32_t smem_base = (uint32_t)__cvta_generic_to_shared(sm);

    int aro  = (lane & 7) + ((lane >> 3) & 1) * 8;
    int acs  = (lane >> 4) & 1;
    int bro  = (lane & 7) + ((lane >> 4) & 1) * 8;
    int bcs  = (lane >> 3) & 1;

    uint32_t aRow[4], aMod[4];
    #pragma unroll
    for (int mi = 0; mi < 4; mi++) {
        int r = wm * 64 + mi * 16 + aro;
        aRow[mi] = (uint32_t)r * 128u;
        aMod[mi] = (uint32_t)(r & 7);
    }
    uint32_t bRow[4], bMod[4];
    #pragma unroll
    for (int p = 0; p < 4; p++) {
        int base;
        if (ACT) base = (p < 2) ? (wn * 32 + p * 16) : (64 + wn * 32 + (p - 2) * 16);
        else     base = wn * 64 + p * 16;
        int r = base + bro;
        bRow[p] = (uint32_t)(BM * 128 + r * 128);
        bMod[p] = (uint32_t)(r & 7);
    }

    float acc[4][8][4];
    #pragma unroll
    for (int i = 0; i < 4; i++)
        #pragma unroll
        for (int j = 0; j < 8; j++)
            #pragma unroll
            for (int q = 0; q < 4; q++) acc[i][j][q] = 0.f;

    int ktiles = Kd / 64;

    stage_load(0, 0); cp_commit();
    stage_load(1, 1); cp_commit();

    for (int kt = 0; kt < ktiles; kt++) {
        cp_wait1();
        __syncthreads();
        uint32_t stg = smem_base + (uint32_t)((kt % NSTAGE) * STAGE_BYTES);

        #pragma unroll
        for (int kk = 0; kk < 4; kk++) {
            uint32_t c0 = (uint32_t)(kk * 2);

            uint32_t afr[4][4];
            #pragma unroll
            for (int mi = 0; mi < 4; mi++) {
                uint32_t addr = stg + aRow[mi] + ((((c0 + acs) ^ aMod[mi])) << 4);
                ldm_x4(afr[mi][0], afr[mi][1], afr[mi][2], afr[mi][3], addr);
            }
            uint32_t bfr[4][4];
            #pragma unroll
            for (int p = 0; p < 4; p++) {
                uint32_t addr = stg + bRow[p] + ((((c0 + bcs) ^ bMod[p])) << 4);
                ldm_x4(bfr[p][0], bfr[p][1], bfr[p][2], bfr[p][3], addr);
            }
            #pragma unroll
            for (int p = 0; p < 4; p++) {
                #pragma unroll
                for (int h = 0; h < 2; h++) {
                    int ni = p * 2 + h;
                    uint32_t b0 = bfr[p][2 * h], b1 = bfr[p][2 * h + 1];
                    #pragma unroll
                    for (int mi = 0; mi < 4; mi++)
                        mma_f16(acc[mi][ni], afr[mi][0], afr[mi][1], afr[mi][2], afr[mi][3], b0, b1);
                }
            }
        }
        if (kt + 2 < ktiles) stage_load(kt + 2, (kt + 2) % NSTAGE);
        cp_commit();
    }

    #pragma unroll
    for (int mi = 0; mi < 4; mi++) {
        int r0 = m0 + wm * 64 + mi * 16 + g;
        bool v0 = r0 < M, v1 = (r0 + 8) < M;
        size_t base0 = (size_t)(off + r0) * Nout;
        size_t base1 = (size_t)(off + r0 + 8) * Nout;
        if (ACT) {
            __half* Ch = (__half*)Cv;
            #pragma unroll
            for (int ni = 0; ni < 4; ni++) {
                int col = nb * 64 + wn * 32 + ni * 8 + tg * 2;
                if (v0) {
                    __half2 o = __floats2half2_rn(
                        silu_mul(acc[mi][ni][0], acc[mi][ni + 4][0]),
                        silu_mul(acc[mi][ni][1], acc[mi][ni + 4][1]));
                    *(__half2*)(Ch + base0 + col) = o;
                }
                if (v1) {
                    __half2 o = __floats2half2_rn(
                        silu_mul(acc[mi][ni][2], acc[mi][ni + 4][2]),
                        silu_mul(acc[mi][ni][3], acc[mi][ni + 4][3]));
                    *(__half2*)(Ch + base1 + col) = o;
                }
            }
        } else {
            float* Cf = (float*)Cv;
            #pragma unroll
            for (int ni = 0; ni < 8; ni++) {
                int col = nb * BN + wn * 64 + ni * 8 + tg * 2;
                if (v0) {
                    float2 o; o.x = acc[mi][ni][0]; o.y = acc[mi][ni][1];
                    *(float2*)(Cf + base0 + col) = o;
                }
                if (v1) {
                    float2 o; o.x = acc[mi][ni][2]; o.y = acc[mi][ni][3];
                    *(float2*)(Cf + base1 + col) = o;
                }
            }
        }
    }
}

// ---------------------------------------------------------------------------
// Combine
// ---------------------------------------------------------------------------
__global__ void combine_k(float* __restrict__ out) {
    int t = blockIdx.x;
    __shared__ int   rws[KSEL];
    __shared__ float ws[KSEL];
    if (threadIdx.x < KSEL) {
        rws[threadIdx.x] = g_row_of_tk[t * KSEL + threadIdx.x];
        ws[threadIdx.x]  = g_top_w[t * KSEL + threadIdx.x];
    }
    __syncthreads();
    for (int d = threadIdx.x; d < HDIM; d += blockDim.x) {
        float a = g_sh_out[(size_t)t * HDIM + d];
        float m = 0.f;
        #pragma unroll
        for (int k = 0; k < KSEL; k++)
            m += ws[k] * g_down[(size_t)rws[k] * HDIM + d];
        out[(size_t)t * HDIM + d] = (a + 8.f * m) * (1.f / 9.f);
    }
}

// ---------------------------------------------------------------------------
// kernel_launch — graph-capturable, allocation-free, two-stream DAG.
//  s0: cvt x (+count init) | router | scan_assign | [w13 ready] moe_gu |
//      [w2 ready] moe_down | [shared done] combine
//  s2: cvt w13 | cvt w2 | cvt wsg | cvt wsd | sh_gu | sh_down
// ---------------------------------------------------------------------------
extern "C" void kernel_launch(void* const* d_in, const int* in_sizes, int n_in,
                              void* d_out, int out_size)
{
    const float* x      = (const float*)d_in[0];
    const float* w_gate = (const float*)d_in[1];
    const float* w13    = (const float*)d_in[2];
    const float* w2     = (const float*)d_in[3];
    const float* wsg    = (const float*)d_in[4];
    const float* wsd    = (const float*)d_in[5];
    float* out = (float*)d_out;

    __half *p_w13h, *p_w2h, *p_wsgh, *p_wsdh, *p_xh, *p_h, *p_h_s;
    float  *p_down, *p_sh_out;
    cudaGetSymbolAddress((void**)&p_w13h,   g_w13h);
    cudaGetSymbolAddress((void**)&p_w2h,    g_w2h);
    cudaGetSymbolAddress((void**)&p_wsgh,   g_wsgh);
    cudaGetSymbolAddress((void**)&p_wsdh,   g_wsdh);
    cudaGetSymbolAddress((void**)&p_xh,     g_xh);
    cudaGetSymbolAddress((void**)&p_h,      g_h);
    cudaGetSymbolAddress((void**)&p_h_s,    g_h_s);
    cudaGetSymbolAddress((void**)&p_down,   g_down);
    cudaGetSymbolAddress((void**)&p_sh_out, g_sh_out);

    cudaFuncSetAttribute(gemm6<true,  true,  true >, cudaFuncAttributeMaxDynamicSharedMemorySize, GEMM_SMEM);
    cudaFuncSetAttribute(gemm6<false, true,  false>, cudaFuncAttributeMaxDynamicSharedMemorySize, GEMM_SMEM);
    cudaFuncSetAttribute(gemm6<false, false, true >, cudaFuncAttributeMaxDynamicSharedMemorySize, GEMM_SMEM);
    cudaFuncSetAttribute(gemm6<false, false, false>, cudaFuncAttributeMaxDynamicSharedMemorySize, GEMM_SMEM);

    static cudaStream_t s2 = nullptr;
    static cudaEvent_t evFork = nullptr, evW13 = nullptr, evW2 = nullptr, evJoin = nullptr;
    if (!s2) {
        cudaStreamCreateWithFlags(&s2, cudaStreamNonBlocking);
        cudaEventCreateWithFlags(&evFork, cudaEventDisableTiming);
        cudaEventCreateWithFlags(&evW13,  cudaEventDisableTiming);
        cudaEventCreateWithFlags(&evW2,   cudaEventDisableTiming);
        cudaEventCreateWithFlags(&evJoin, cudaEventDisableTiming);
    }

    // s0: convert x (fuses router-count init); fork s2 after it (s2's shared
    // chain reads p_xh, so the fork must order-after cvt x).
    cvt_init_k<<<1024, 256>>>((const float4*)x, (uint2*)p_xh, (long)T_TOK * HDIM / 4);
    cudaEventRecord(evFork, 0);
    cudaStreamWaitEvent(s2, evFork, 0);

    // s2: all weight converts, then the shared chain
    cvt_k<<<8192, 256, 0, s2>>>((const float4*)w13, (uint2*)p_w13h, (long)NEXP * 2 * IDIM * HDIM / 4);
    cudaEventRecord(evW13, s2);
    cvt_k<<<8192, 256, 0, s2>>>((const float4*)w2,  (uint2*)p_w2h,  (long)NEXP * HDIM * IDIM / 4);
    cudaEventRecord(evW2, s2);
    cvt_k<<<2048, 256, 0, s2>>>((const float4*)wsg, (uint2*)p_wsgh, (long)2 * SIDIM * HDIM / 4);
    cvt_k<<<2048, 256, 0, s2>>>((const float4*)wsd, (uint2*)p_wsdh, (long)HDIM * SIDIM / 4);
    gemm6<false, false, true ><<<dim3(SIDIM / 64, T_TOK / BM, 1), 128, GEMM_SMEM, s2>>>(
        p_xh, p_wsgh, p_h_s, HDIM, SIDIM, 0, SIDIM, T_TOK);
    gemm6<false, false, false><<<dim3(HDIM / BN, T_TOK / BM, 1), 128, GEMM_SMEM, s2>>>(
        p_h_s, p_wsdh, p_sh_out, SIDIM, HDIM, 0, 0, T_TOK);
    cudaEventRecord(evJoin, s2);

    // s0: routing (overlaps s2's converts)
    router_k<<<T_TOK, 256>>>(x, w_gate);
    scan_assign_k<<<1, 256>>>();

    // s0: MoE gate_up (needs w13h)
    cudaStreamWaitEvent(0, evW13, 0);
    gemm6<true, true, true><<<dim3(IDIM / 64, 8, NEXP), 128, GEMM_SMEM>>>(
        p_xh, p_w13h, p_h, HDIM, IDIM, (size_t)2 * IDIM * HDIM, IDIM, 0);

    // s0: MoE down (needs w2h)
    cudaStreamWaitEvent(0, evW2, 0);
    gemm6<false, true, false><<<dim3(HDIM / BN, 8, NEXP), 128, GEMM_SMEM>>>(
        p_h, p_w2h, p_down, IDIM, HDIM, (size_t)HDIM * IDIM, 0, 0);

    // join + combine
    cudaStreamWaitEvent(0, evJoin, 0);
    combine_k<<<T_TOK, 256>>>(out);
}

// round 10
// speedup vs baseline: 1.7700x; 1.0231x over previous
#include <cuda_runtime.h>
#include <cuda_fp16.h>
#include <cstdint>
#include <cmath>

// Problem constants
#define T_TOK 1024
#define HDIM  2048
#define NEXP  64
#define IDIM  1024
#define SIDIM 4096
#define KSEL  8
#define NROWS (T_TOK * KSEL)

// Tile config: CTA 128x128, 8 warps (4Mx2N), warp tile 32x64, fp16 BK=64 (128B rows)
#define BM 128
#define BN 128
#define NSTAGE 3
#define STAGE_BYTES ((BM + BN) * 128)                // 32768
#define GEMM_SMEM (NSTAGE * STAGE_BYTES + 512)       // 98816

// ---------------------------------------------------------------------------
// Device-global scratch
// ---------------------------------------------------------------------------
__device__ __align__(256) __half g_w13h[(size_t)NEXP * 2 * IDIM * HDIM]; // 512MB
__device__ __align__(256) __half g_w2h [(size_t)NEXP * HDIM * IDIM];     // 256MB
__device__ __align__(256) __half g_wsgh[(size_t)2 * SIDIM * HDIM];       // 32MB
__device__ __align__(256) __half g_wsdh[(size_t)HDIM * SIDIM];           // 16MB
__device__ __align__(256) __half g_xh  [(size_t)T_TOK * HDIM];
__device__ __align__(256) __half g_h   [(size_t)NROWS * IDIM];
__device__ __align__(256) __half g_h_s [(size_t)T_TOK * SIDIM];
__device__ __align__(256) float  g_down[(size_t)NROWS * HDIM];
__device__ __align__(256) float  g_sh_out[(size_t)T_TOK * HDIM];

__device__ int   g_counts[NEXP];
__device__ int   g_offsets[NEXP];
__device__ int   g_fill[NEXP];
__device__ int   g_rowmap[NROWS];
__device__ int   g_row_of_tk[NROWS];
__device__ int   g_top_e[NROWS];
__device__ float g_top_w[NROWS];

// ---------------------------------------------------------------------------
// Helpers
// ---------------------------------------------------------------------------
__device__ __forceinline__ void cp_async16(void* smem, const void* gmem) {
    uint32_t s = (uint32_t)__cvta_generic_to_shared(smem);
    asm volatile("cp.async.cg.shared.global [%0], [%1], 16;\n" :: "r"(s), "l"(gmem));
}
__device__ __forceinline__ void cp_commit() { asm volatile("cp.async.commit_group;\n"); }
__device__ __forceinline__ void cp_wait1()  { asm volatile("cp.async.wait_group 1;\n"); }

__device__ __forceinline__ void ldm_x4(uint32_t& r0, uint32_t& r1, uint32_t& r2, uint32_t& r3,
                                       uint32_t addr) {
    asm volatile("ldmatrix.sync.aligned.m8n8.x4.shared.b16 {%0,%1,%2,%3}, [%4];"
                 : "=r"(r0), "=r"(r1), "=r"(r2), "=r"(r3) : "r"(addr));
}

__device__ __forceinline__ void mma_f16(float c[4],
                                        uint32_t a0, uint32_t a1, uint32_t a2, uint32_t a3,
                                        uint32_t b0, uint32_t b1) {
    asm volatile(
        "mma.sync.aligned.m16n8k16.row.col.f32.f16.f16.f32 "
        "{%0,%1,%2,%3},{%4,%5,%6,%7},{%8,%9},{%0,%1,%2,%3};\n"
        : "+f"(c[0]), "+f"(c[1]), "+f"(c[2]), "+f"(c[3])
        : "r"(a0), "r"(a1), "r"(a2), "r"(a3), "r"(b0), "r"(b1));
}

__device__ __forceinline__ float silu_mul(float g, float u) {
    return g * u / (1.f + expf(-g));
}

// ---------------------------------------------------------------------------
// fp32 -> fp16 convert kernels
// ---------------------------------------------------------------------------
__global__ void cvt_k(const float4* __restrict__ in, uint2* __restrict__ outp, long n4) {
    long i = (long)blockIdx.x * blockDim.x + threadIdx.x;
    long stride = (long)gridDim.x * blockDim.x;
    for (; i < n4; i += stride) {
        float4 v = in[i];
        __half2 h0 = __floats2half2_rn(v.x, v.y);
        __half2 h1 = __floats2half2_rn(v.z, v.w);
        uint2 o;
        o.x = *(uint32_t*)&h0;
        o.y = *(uint32_t*)&h1;
        outp[i] = o;
    }
}

__global__ void cvt_init_k(const float4* __restrict__ in, uint2* __restrict__ outp, long n4) {
    if (blockIdx.x == 0 && threadIdx.x < NEXP) g_counts[threadIdx.x] = 0;
    long i = (long)blockIdx.x * blockDim.x + threadIdx.x;
    long stride = (long)gridDim.x * blockDim.x;
    for (; i < n4; i += stride) {
        float4 v = in[i];
        __half2 h0 = __floats2half2_rn(v.x, v.y);
        __half2 h1 = __floats2half2_rn(v.z, v.w);
        uint2 o;
        o.x = *(uint32_t*)&h0;
        o.y = *(uint32_t*)&h1;
        outp[i] = o;
    }
}

// ---------------------------------------------------------------------------
// Routing kernels
// ---------------------------------------------------------------------------
__global__ void router_k(const float* __restrict__ x, const float* __restrict__ wg) {
    int t = blockIdx.x;
    __shared__ float xs[HDIM];
    __shared__ float sc[NEXP];
    for (int d = threadIdx.x; d < HDIM; d += blockDim.x) xs[d] = x[(size_t)t * HDIM + d];
    __syncthreads();

    int w = threadIdx.x >> 5, lane = threadIdx.x & 31;
    for (int e = w * 8; e < w * 8 + 8; e++) {
        const float* wr = wg + (size_t)e * HDIM;
        float s = 0.f;
        for (int d = lane; d < HDIM; d += 32) s += xs[d] * wr[d];
        #pragma unroll
        for (int o = 16; o; o >>= 1) s += __shfl_xor_sync(0xffffffffu, s, o);
        if (lane == 0) sc[e] = 1.f / (1.f + expf(-s));
    }
    __syncthreads();

    if (threadIdx.x == 0) {
        for (int k = 0; k < KSEL; k++) {
            int best = 0; float bv = sc[0];
            for (int e = 1; e < NEXP; e++)
                if (sc[e] > bv) { bv = sc[e]; best = e; }
            g_top_e[t * KSEL + k] = best;
            g_top_w[t * KSEL + k] = bv;
            atomicAdd(&g_counts[best], 1);
            sc[best] = -1.f;
        }
    }
}

__global__ void scan_assign_k() {
    if (threadIdx.x == 0) {
        int acc = 0;
        for (int e = 0; e < NEXP; e++) {
            g_offsets[e] = acc;
            g_fill[e] = acc;
            acc += g_counts[e];
        }
    }
    __syncthreads();
    for (int idx = threadIdx.x; idx < NROWS; idx += blockDim.x) {
        int e = g_top_e[idx];
        int r = atomicAdd(&g_fill[e], 1);
        g_rowmap[r] = idx >> 3;
        g_row_of_tk[idx] = r;
    }
}

// ---------------------------------------------------------------------------
// gemm7 — FP16 mma.sync, 8 warps (4Mx2N), warp tile 32x64, BK=64 fp16.
// 3-stage cp.async ring; per-stage 256 rows (128 A + 128 B) x 128B;
// 16B-chunk XOR-swizzled by (row & 7); ldmatrix.x4 fragments; fp32 accum.
//   C[m,n] = sum_k A[m,k]*B[n,k]
//   ACT: B tile = 64 gate + 64 up rows; epilogue silu(g)*u -> __half (64 cols/CTA)
//   non-ACT: -> fp32 (128 cols/CTA)
// ---------------------------------------------------------------------------
template <bool GATHER, bool EXPERT, bool ACT>
__global__ void __launch_bounds__(256, 2)
gemm7(const __half* __restrict__ A, const __half* __restrict__ Bw, void* __restrict__ Cv,
      int Kd, int Nout, size_t strideBe, int upOff, int Mdense)
{
    extern __shared__ char sm[];
    int e = EXPERT ? blockIdx.z : 0;
    int M, off;
    if (EXPERT) { M = g_counts[e]; off = g_offsets[e]; }
    else        { M = Mdense;      off = 0; }
    int m0 = blockIdx.y * BM;
    if (m0 >= M) return;
    int nb = blockIdx.x;
    const __half* B = Bw + (size_t)e * strideBe;

    int tid = threadIdx.x, warp = tid >> 5, lane = tid & 31;
    int* arows = (int*)(sm + NSTAGE * STAGE_BYTES);

    if (tid < BM) {
        int gr = m0 + tid;
        int ar = -1;
        if (gr < M) ar = GATHER ? g_rowmap[off + gr] : (off + gr);
        arows[tid] = ar;
    }
    __syncthreads();

    // ---- producer: thread tid owns smem row tid (0-127 A, 128-255 B);
    //      copies its 128B (8 x 16B chunks, XOR-swizzled) per stage.
    const __half* srcp;
    if (tid < BM) {
        int ar = arows[tid];
        if (ar < 0) ar = arows[0] >= 0 ? arows[0] : 0;   // clamp; masked in epilogue
        srcp = A + (size_t)ar * Kd;
    } else {
        int prow = tid - BM;
        int brglob;
        if (ACT) brglob = (prow < 64) ? (nb * 64 + prow) : (upOff + nb * 64 + (prow - 64));
        else     brglob = nb * BN + prow;
        srcp = B + (size_t)brglob * Kd;
    }
    int rs = tid & 7;
    char* myrow = sm + tid * 128;

    auto stage_load = [&](int kt, int s) {
        const __half* g = srcp + kt * 64;
        char* d = myrow + s * STAGE_BYTES;
        #pragma unroll
        for (int c = 0; c < 8; c++)
            cp_async16(d + ((c ^ rs) << 4), g + c * 8);
    };

    // ---- consumer constants (round-5 mapping; chunk = k8 block)
    int wm = warp & 3;               // M slice (32 rows)
    int wn = warp >> 2;              // N slice (64 B rows)
    int g  = lane >> 2, tg = lane & 3;

    uint32_t smem_base = (uint32_t)__cvta_generic_to_shared(sm);

    int aro  = (lane & 7) + ((lane >> 3) & 1) * 8;   // A row offset within 16
    int acs  = (lane >> 4) & 1;                      // A k8-chunk select
    int bro  = (lane & 7) + ((lane >> 4) & 1) * 8;   // B row offset within 16
    int bcs  = (lane >> 3) & 1;                      // B k8-chunk select

    uint32_t aRow[2], aMod[2];
    #pragma unroll
    for (int mi = 0; mi < 2; mi++) {
        int r = wm * 32 + mi * 16 + aro;
        aRow[mi] = (uint32_t)r * 128u;
        aMod[mi] = (uint32_t)(r & 7);
    }
    uint32_t bRow[4], bMod[4];
    #pragma unroll
    for (int p = 0; p < 4; p++) {
        int base;
        if (ACT) base = (p < 2) ? (wn * 32 + p * 16) : (64 + wn * 32 + (p - 2) * 16);
        else     base = wn * 64 + p * 16;
        int r = base + bro;
        bRow[p] = (uint32_t)(BM * 128 + r * 128);
        bMod[p] = (uint32_t)(r & 7);
    }

    float acc[2][8][4];
    #pragma unroll
    for (int i = 0; i < 2; i++)
        #pragma unroll
        for (int j = 0; j < 8; j++)
            #pragma unroll
            for (int q = 0; q < 4; q++) acc[i][j][q] = 0.f;

    int ktiles = Kd / 64;

    stage_load(0, 0); cp_commit();
    stage_load(1, 1); cp_commit();

    for (int kt = 0; kt < ktiles; kt++) {
        cp_wait1();
        __syncthreads();
        uint32_t stg = smem_base + (uint32_t)((kt % NSTAGE) * STAGE_BYTES);

        #pragma unroll
        for (int kk = 0; kk < 4; kk++) {            // four k16 blocks per ktile
            uint32_t c0 = (uint32_t)(kk * 2);

            uint32_t afr[2][4];
            #pragma unroll
            for (int mi = 0; mi < 2; mi++) {
                uint32_t addr = stg + aRow[mi] + ((((c0 + acs) ^ aMod[mi])) << 4);
                ldm_x4(afr[mi][0], afr[mi][1], afr[mi][2], afr[mi][3], addr);
            }
            uint32_t bfr[4][4];
            #pragma unroll
            for (int p = 0; p < 4; p++) {
                uint32_t addr = stg + bRow[p] + ((((c0 + bcs) ^ bMod[p])) << 4);
                ldm_x4(bfr[p][0], bfr[p][1], bfr[p][2], bfr[p][3], addr);
            }
            #pragma unroll
            for (int p = 0; p < 4; p++) {
                #pragma unroll
                for (int h = 0; h < 2; h++) {
                    int ni = p * 2 + h;
                    uint32_t b0 = bfr[p][2 * h], b1 = bfr[p][2 * h + 1];
                    mma_f16(acc[0][ni], afr[0][0], afr[0][1], afr[0][2], afr[0][3], b0, b1);
                    mma_f16(acc[1][ni], afr[1][0], afr[1][1], afr[1][2], afr[1][3], b0, b1);
                }
            }
        }
        if (kt + 2 < ktiles) stage_load(kt + 2, (kt + 2) % NSTAGE);
        cp_commit();
    }

    // ---- epilogue
    #pragma unroll
    for (int mi = 0; mi < 2; mi++) {
        int r0 = m0 + wm * 32 + mi * 16 + g;
        bool v0 = r0 < M, v1 = (r0 + 8) < M;
        size_t base0 = (size_t)(off + r0) * Nout;
        size_t base1 = (size_t)(off + r0 + 8) * Nout;
        if (ACT) {
            __half* Ch = (__half*)Cv;
            #pragma unroll
            for (int ni = 0; ni < 4; ni++) {
                int col = nb * 64 + wn * 32 + ni * 8 + tg * 2;
                if (v0) {
                    __half2 o = __floats2half2_rn(
                        silu_mul(acc[mi][ni][0], acc[mi][ni + 4][0]),
                        silu_mul(acc[mi][ni][1], acc[mi][ni + 4][1]));
                    *(__half2*)(Ch + base0 + col) = o;
                }
                if (v1) {
                    __half2 o = __floats2half2_rn(
                        silu_mul(acc[mi][ni][2], acc[mi][ni + 4][2]),
                        silu_mul(acc[mi][ni][3], acc[mi][ni + 4][3]));
                    *(__half2*)(Ch + base1 + col) = o;
                }
            }
        } else {
            float* Cf = (float*)Cv;
            #pragma unroll
            for (int ni = 0; ni < 8; ni++) {
                int col = nb * BN + wn * 64 + ni * 8 + tg * 2;
                if (v0) {
                    float2 o; o.x = acc[mi][ni][0]; o.y = acc[mi][ni][1];
                    *(float2*)(Cf + base0 + col) = o;
                }
                if (v1) {
                    float2 o; o.x = acc[mi][ni][2]; o.y = acc[mi][ni][3];
                    *(float2*)(Cf + base1 + col) = o;
                }
            }
        }
    }
}

// ---------------------------------------------------------------------------
// Combine
// ---------------------------------------------------------------------------
__global__ void combine_k(float* __restrict__ out) {
    int t = blockIdx.x;
    __shared__ int   rws[KSEL];
    __shared__ float ws[KSEL];
    if (threadIdx.x < KSEL) {
        rws[threadIdx.x] = g_row_of_tk[t * KSEL + threadIdx.x];
        ws[threadIdx.x]  = g_top_w[t * KSEL + threadIdx.x];
    }
    __syncthreads();
    for (int d = threadIdx.x; d < HDIM; d += blockDim.x) {
        float a = g_sh_out[(size_t)t * HDIM + d];
        float m = 0.f;
        #pragma unroll
        for (int k = 0; k < KSEL; k++)
            m += ws[k] * g_down[(size_t)rws[k] * HDIM + d];
        out[(size_t)t * HDIM + d] = (a + 8.f * m) * (1.f / 9.f);
    }
}

// ---------------------------------------------------------------------------
// kernel_launch — graph-capturable, allocation-free, two-stream DAG.
//  s0: cvt x (+count init) [evX] | router | scan_assign | [evW13] moe_gu |
//      [evW2] moe_down | [evJoin] combine
//  s2: cvt w13 [evW13] | cvt w2 [evW2] | cvt wsg | cvt wsd | [evX] sh_gu | sh_down [evJoin]
//  Fork recorded at t=0 so the w13 convert starts immediately.
// ---------------------------------------------------------------------------
extern "C" void kernel_launch(void* const* d_in, const int* in_sizes, int n_in,
                              void* d_out, int out_size)
{
    const float* x      = (const float*)d_in[0];
    const float* w_gate = (const float*)d_in[1];
    const float* w13    = (const float*)d_in[2];
    const float* w2     = (const float*)d_in[3];
    const float* wsg    = (const float*)d_in[4];
    const float* wsd    = (const float*)d_in[5];
    float* out = (float*)d_out;

    __half *p_w13h, *p_w2h, *p_wsgh, *p_wsdh, *p_xh, *p_h, *p_h_s;
    float  *p_down, *p_sh_out;
    cudaGetSymbolAddress((void**)&p_w13h,   g_w13h);
    cudaGetSymbolAddress((void**)&p_w2h,    g_w2h);
    cudaGetSymbolAddress((void**)&p_wsgh,   g_wsgh);
    cudaGetSymbolAddress((void**)&p_wsdh,   g_wsdh);
    cudaGetSymbolAddress((void**)&p_xh,     g_xh);
    cudaGetSymbolAddress((void**)&p_h,      g_h);
    cudaGetSymbolAddress((void**)&p_h_s,    g_h_s);
    cudaGetSymbolAddress((void**)&p_down,   g_down);
    cudaGetSymbolAddress((void**)&p_sh_out, g_sh_out);

    cudaFuncSetAttribute(gemm7<true,  true,  true >, cudaFuncAttributeMaxDynamicSharedMemorySize, GEMM_SMEM);
    cudaFuncSetAttribute(gemm7<false, true,  false>, cudaFuncAttributeMaxDynamicSharedMemorySize, GEMM_SMEM);
    cudaFuncSetAttribute(gemm7<false, false, true >, cudaFuncAttributeMaxDynamicSharedMemorySize, GEMM_SMEM);
    cudaFuncSetAttribute(gemm7<false, false, false>, cudaFuncAttributeMaxDynamicSharedMemorySize, GEMM_SMEM);

    static cudaStream_t s2 = nullptr;
    static cudaEvent_t evFork = nullptr, evX = nullptr, evW13 = nullptr, evW2 = nullptr, evJoin = nullptr;
    if (!s2) {
        cudaStreamCreateWithFlags(&s2, cudaStreamNonBlocking);
        cudaEventCreateWithFlags(&evFork, cudaEventDisableTiming);
        cudaEventCreateWithFlags(&evX,    cudaEventDisableTiming);
        cudaEventCreateWithFlags(&evW13,  cudaEventDisableTiming);
        cudaEventCreateWithFlags(&evW2,   cudaEventDisableTiming);
        cudaEventCreateWithFlags(&evJoin, cudaEventDisableTiming);
    }

    // fork at t=0 so s2's w13 convert starts immediately
    cudaEventRecord(evFork, 0);
    cudaStreamWaitEvent(s2, evFork, 0);

    // s0: cvt x (fuses router-count init), mark evX, then routing
    cvt_init_k<<<1024, 256>>>((const float4*)x, (uint2*)p_xh, (long)T_TOK * HDIM / 4);
    cudaEventRecord(evX, 0);
    router_k<<<T_TOK, 256>>>(x, w_gate);
    scan_assign_k<<<1, 256>>>();

    // s2: weight converts (w13 first — it gates the MoE chain)
    cvt_k<<<8192, 256, 0, s2>>>((const float4*)w13, (uint2*)p_w13h, (long)NEXP * 2 * IDIM * HDIM / 4);
    cudaEventRecord(evW13, s2);
    cvt_k<<<8192, 256, 0, s2>>>((const float4*)w2,  (uint2*)p_w2h,  (long)NEXP * HDIM * IDIM / 4);
    cudaEventRecord(evW2, s2);
    cvt_k<<<2048, 256, 0, s2>>>((const float4*)wsg, (uint2*)p_wsgh, (long)2 * SIDIM * HDIM / 4);
    cvt_k<<<2048, 256, 0, s2>>>((const float4*)wsd, (uint2*)p_wsdh, (long)HDIM * SIDIM / 4);

    // s2: shared chain (needs xh)
    cudaStreamWaitEvent(s2, evX, 0);
    gemm7<false, false, true ><<<dim3(SIDIM / 64, T_TOK / BM, 1), 256, GEMM_SMEM, s2>>>(
        p_xh, p_wsgh, p_h_s, HDIM, SIDIM, 0, SIDIM, T_TOK);
    gemm7<false, false, false><<<dim3(HDIM / BN, T_TOK / BM, 1), 256, GEMM_SMEM, s2>>>(
        p_h_s, p_wsdh, p_sh_out, SIDIM, HDIM, 0, 0, T_TOK);
    cudaEventRecord(evJoin, s2);

    // s0: MoE gate_up (needs w13h)
    cudaStreamWaitEvent(0, evW13, 0);
    gemm7<true, true, true><<<dim3(IDIM / 64, 8, NEXP), 256, GEMM_SMEM>>>(
        p_xh, p_w13h, p_h, HDIM, IDIM, (size_t)2 * IDIM * HDIM, IDIM, 0);

    // s0: MoE down (needs w2h)
    cudaStreamWaitEvent(0, evW2, 0);
    gemm7<false, true, false><<<dim3(HDIM / BN, 8, NEXP), 256, GEMM_SMEM>>>(
        p_h, p_w2h, p_down, IDIM, HDIM, (size_t)HDIM * IDIM, 0, 0);

    // join + combine
    cudaStreamWaitEvent(0, evJoin, 0);
    combine_k<<<T_TOK, 256>>>(out);
}

// round 11
// speedup vs baseline: 2.2274x; 1.2585x over previous
#include <cuda_runtime.h>
#include <cuda_fp16.h>
#include <cstdint>
#include <cmath>

// Problem constants
#define T_TOK 1024
#define HDIM  2048
#define NEXP  64
#define IDIM  1024
#define SIDIM 4096
#define KSEL  8
#define NROWS (T_TOK * KSEL)

// Tile config: CTA 128x128, 8 warps (4Mx2N), warp tile 32x64, fp16 BK=64.
// Rows staged with 144B pitch (bank-rotation => ldmatrix conflict-free).
#define BM 128
#define BN 128
#define NSTAGE 3
#define ROWPITCH 144
#define STAGE_BYTES ((BM + BN) * ROWPITCH)          // 36864
#define STAGE_TX ((BM + BN) * 128)                  // 32768 actual bytes copied
#define MBAR_OFF (NSTAGE * STAGE_BYTES)             // 110592
#define AROWS_OFF (MBAR_OFF + 64)
#define GEMM_SMEM (AROWS_OFF + BM * 4)              // 111168

// ---------------------------------------------------------------------------
// Device-global scratch
// ---------------------------------------------------------------------------
__device__ __align__(256) __half g_w13h[(size_t)NEXP * 2 * IDIM * HDIM]; // 512MB
__device__ __align__(256) __half g_w2h [(size_t)NEXP * HDIM * IDIM];     // 256MB
__device__ __align__(256) __half g_wsgh[(size_t)2 * SIDIM * HDIM];       // 32MB
__device__ __align__(256) __half g_wsdh[(size_t)HDIM * SIDIM];           // 16MB
__device__ __align__(256) __half g_xh  [(size_t)T_TOK * HDIM];
__device__ __align__(256) __half g_h   [(size_t)NROWS * IDIM];
__device__ __align__(256) __half g_h_s [(size_t)T_TOK * SIDIM];
__device__ __align__(256) float  g_down[(size_t)NROWS * HDIM];
__device__ __align__(256) float  g_sh_out[(size_t)T_TOK * HDIM];

__device__ int   g_counts[NEXP];
__device__ int   g_offsets[NEXP];
__device__ int   g_fill[NEXP];
__device__ int   g_rowmap[NROWS];
__device__ int   g_row_of_tk[NROWS];
__device__ int   g_top_e[NROWS];
__device__ float g_top_w[NROWS];
__device__ int   g_ticket;

// ---------------------------------------------------------------------------
// Helpers
// ---------------------------------------------------------------------------
#define MBARRIER_INIT(addr, cnt) \
    asm volatile("mbarrier.init.shared.b64 [%0], %1;" :: "r"((uint32_t)(addr)), "r"((uint32_t)(cnt)) : "memory")

#define MBARRIER_EXPECT_TX(addr, bytes) \
    asm volatile("mbarrier.arrive.expect_tx.shared.b64 _, [%0], %1;" \
        :: "r"((uint32_t)(addr)), "r"((uint32_t)(bytes)) : "memory")

#define MBARRIER_WAIT_PARITY(addr, parity) do {                                         \
    uint32_t _m = (uint32_t)(addr); uint32_t _p = (uint32_t)(parity); uint32_t _d;      \
    asm volatile("{ .reg .pred p; mbarrier.try_wait.parity.acquire.cta.shared::cta.b64 p, [%1], %2; selp.b32 %0,1,0,p; }" \
        : "=r"(_d) : "r"(_m), "r"(_p) : "memory");                                      \
    if (!_d) {                                                                          \
        asm volatile("{ .reg .pred P1; WL_%=: mbarrier.try_wait.parity.acquire.cta.shared::cta.b64 P1, [%0], %1, 0x989680; @P1 bra.uni WD_%=; bra.uni WL_%=; WD_%=: }" \
            :: "r"(_m), "r"(_p) : "memory");                                            \
    }                                                                                   \
} while (0)

#define FENCE_ASYNC() asm volatile("fence.proxy.async.shared::cta;" ::: "memory")

__device__ __forceinline__ void bulk_g2s(uint32_t dst, const void* src, uint32_t bytes, uint32_t mbar) {
    asm volatile("cp.async.bulk.shared::cluster.global.mbarrier::complete_tx::bytes [%0], [%1], %2, [%3];"
                 :: "r"(dst), "l"(src), "r"(bytes), "r"(mbar) : "memory");
}

__device__ __forceinline__ void ldm_x4(uint32_t& r0, uint32_t& r1, uint32_t& r2, uint32_t& r3,
                                       uint32_t addr) {
    asm volatile("ldmatrix.sync.aligned.m8n8.x4.shared.b16 {%0,%1,%2,%3}, [%4];"
                 : "=r"(r0), "=r"(r1), "=r"(r2), "=r"(r3) : "r"(addr));
}

__device__ __forceinline__ void mma_f16(float c[4],
                                        uint32_t a0, uint32_t a1, uint32_t a2, uint32_t a3,
                                        uint32_t b0, uint32_t b1) {
    asm volatile(
        "mma.sync.aligned.m16n8k16.row.col.f32.f16.f16.f32 "
        "{%0,%1,%2,%3},{%4,%5,%6,%7},{%8,%9},{%0,%1,%2,%3};\n"
        : "+f"(c[0]), "+f"(c[1]), "+f"(c[2]), "+f"(c[3])
        : "r"(a0), "r"(a1), "r"(a2), "r"(a3), "r"(b0), "r"(b1));
}

__device__ __forceinline__ float silu_mul(float g, float u) {
    return g * u / (1.f + expf(-g));
}

// ---------------------------------------------------------------------------
// fp32 -> fp16 convert kernels
// ---------------------------------------------------------------------------
__global__ void cvt_k(const float4* __restrict__ in, uint2* __restrict__ outp, long n4) {
    long i = (long)blockIdx.x * blockDim.x + threadIdx.x;
    long stride = (long)gridDim.x * blockDim.x;
    for (; i < n4; i += stride) {
        float4 v = in[i];
        __half2 h0 = __floats2half2_rn(v.x, v.y);
        __half2 h1 = __floats2half2_rn(v.z, v.w);
        uint2 o;
        o.x = *(uint32_t*)&h0;
        o.y = *(uint32_t*)&h1;
        outp[i] = o;
    }
}

__global__ void cvt_init_k(const float4* __restrict__ in, uint2* __restrict__ outp, long n4) {
    if (blockIdx.x == 0 && threadIdx.x < NEXP) g_counts[threadIdx.x] = 0;
    long i = (long)blockIdx.x * blockDim.x + threadIdx.x;
    long stride = (long)gridDim.x * blockDim.x;
    for (; i < n4; i += stride) {
        float4 v = in[i];
        __half2 h0 = __floats2half2_rn(v.x, v.y);
        __half2 h1 = __floats2half2_rn(v.z, v.w);
        uint2 o;
        o.x = *(uint32_t*)&h0;
        o.y = *(uint32_t*)&h1;
        outp[i] = o;
    }
}

// ---------------------------------------------------------------------------
// Fused router + scan + assign (ticket: last block finalizes)
// ---------------------------------------------------------------------------
__global__ void router_fused_k(const float* __restrict__ x, const float* __restrict__ wg) {
    int t = blockIdx.x;
    __shared__ float xs[HDIM];
    __shared__ float sc[NEXP];
    __shared__ int isLast;
    for (int d = threadIdx.x; d < HDIM; d += blockDim.x) xs[d] = x[(size_t)t * HDIM + d];
    __syncthreads();

    int w = threadIdx.x >> 5, lane = threadIdx.x & 31;
    for (int e = w * 8; e < w * 8 + 8; e++) {
        const float* wr = wg + (size_t)e * HDIM;
        float s = 0.f;
        for (int d = lane; d < HDIM; d += 32) s += xs[d] * wr[d];
        #pragma unroll
        for (int o = 16; o; o >>= 1) s += __shfl_xor_sync(0xffffffffu, s, o);
        if (lane == 0) sc[e] = 1.f / (1.f + expf(-s));
    }
    __syncthreads();

    if (threadIdx.x == 0) {
        for (int k = 0; k < KSEL; k++) {
            int best = 0; float bv = sc[0];
            for (int e = 1; e < NEXP; e++)
                if (sc[e] > bv) { bv = sc[e]; best = e; }
            g_top_e[t * KSEL + k] = best;
            g_top_w[t * KSEL + k] = bv;
            atomicAdd(&g_counts[best], 1);
            sc[best] = -1.f;
        }
    }

    // completion ticket — last block performs scan + assign
    __threadfence();
    if (threadIdx.x == 0) {
        int tk = atomicAdd(&g_ticket, 1);
        isLast = (tk == (int)gridDim.x - 1);
        if (isLast) g_ticket = 0;              // reset for graph replay
    }
    __syncthreads();
    if (!isLast) return;

    if (threadIdx.x == 0) {
        int acc = 0;
        for (int e = 0; e < NEXP; e++) {
            g_offsets[e] = acc;
            g_fill[e] = acc;
            acc += g_counts[e];
        }
    }
    __syncthreads();
    for (int idx = threadIdx.x; idx < NROWS; idx += blockDim.x) {
        int e = g_top_e[idx];
        int r = atomicAdd(&g_fill[e], 1);
        g_rowmap[r] = idx >> 3;
        g_row_of_tk[idx] = r;
    }
}

// ---------------------------------------------------------------------------
// gemm8 — FP16 mma.sync + cp.async.bulk producers + mbarrier pipeline.
// CTA 128x128, 8 warps (4Mx2N), warp tile 32x64, BK=64 fp16.
// 3-stage ring; each thread bulk-copies its 128B row per stage (144B pitch).
//   C[m,n] = sum_k A[m,k]*B[n,k]; fp32 accum.
//   ACT: B tile = 64 gate + 64 up rows; epilogue silu(g)*u -> __half.
// ---------------------------------------------------------------------------
template <bool GATHER, bool EXPERT, bool ACT>
__global__ void __launch_bounds__(256, 2)
gemm8(const __half* __restrict__ A, const __half* __restrict__ Bw, void* __restrict__ Cv,
      int Kd, int Nout, size_t strideBe, int upOff, int Mdense, int eBase)
{
    extern __shared__ char sm[];
    int e = EXPERT ? (eBase + blockIdx.z) : 0;
    int M, off;
    if (EXPERT) { M = g_counts[e]; off = g_offsets[e]; }
    else        { M = Mdense;      off = 0; }
    int m0 = blockIdx.y * BM;
    if (m0 >= M) return;
    int nb = blockIdx.x;
    const __half* B = Bw + (size_t)e * strideBe;

    int tid = threadIdx.x, warp = tid >> 5, lane = tid & 31;
    uint32_t smem_base = (uint32_t)__cvta_generic_to_shared(sm);
    int* arows = (int*)(sm + AROWS_OFF);

    if (tid == 0) {
        #pragma unroll
        for (int s = 0; s < NSTAGE; s++) MBARRIER_INIT(smem_base + MBAR_OFF + s * 8, 1);
        FENCE_ASYNC();
    }
    if (tid < BM) {
        int gr = m0 + tid;
        int ar = -1;
        if (gr < M) ar = GATHER ? g_rowmap[off + gr] : (off + gr);
        arows[tid] = ar;
    }
    __syncthreads();

    // ---- producer: thread tid owns row tid (0-127 A, 128-255 B); one
    //      cp.async.bulk of 128B per stage into its 144B-pitch slot.
    const __half* srcp;
    if (tid < BM) {
        int ar = arows[tid];
        if (ar < 0) ar = arows[0] >= 0 ? arows[0] : 0;   // clamp; masked in epilogue
        srcp = A + (size_t)ar * Kd;
    } else {
        int prow = tid - BM;
        int brglob;
        if (ACT) brglob = (prow < 64) ? (nb * 64 + prow) : (upOff + nb * 64 + (prow - 64));
        else     brglob = nb * BN + prow;
        srcp = B + (size_t)brglob * Kd;
    }
    uint32_t myslot = smem_base + (uint32_t)(tid * ROWPITCH);

    auto stage_issue = [&](int kt, int s) {
        uint32_t mb = smem_base + (uint32_t)(MBAR_OFF + s * 8);
        if (tid == 0) MBARRIER_EXPECT_TX(mb, STAGE_TX);
        bulk_g2s(myslot + s * STAGE_BYTES, srcp + (size_t)kt * 64, 128u, mb);
    };

    // ---- consumer constants (same fragment mapping as verified rounds)
    int wm = warp & 3;               // M slice (32 rows)
    int wn = warp >> 2;              // N slice (64 B rows)
    int g  = lane >> 2, tg = lane & 3;

    int aro  = (lane & 7) + ((lane >> 3) & 1) * 8;   // A row offset within 16
    int acs  = (lane >> 4) & 1;                      // A k8-chunk select
    int bro  = (lane & 7) + ((lane >> 4) & 1) * 8;   // B row offset within 16
    int bcs  = (lane >> 3) & 1;                      // B k8-chunk select

    uint32_t aRow[2];
    #pragma unroll
    for (int mi = 0; mi < 2; mi++)
        aRow[mi] = (uint32_t)((wm * 32 + mi * 16 + aro) * ROWPITCH);
    uint32_t bRow[4];
    #pragma unroll
    for (int p = 0; p < 4; p++) {
        int base;
        if (ACT) base = (p < 2) ? (wn * 32 + p * 16) : (64 + wn * 32 + (p - 2) * 16);
        else     base = wn * 64 + p * 16;
        bRow[p] = (uint32_t)((BM + base + bro) * ROWPITCH);
    }

    float acc[2][8][4];
    #pragma unroll
    for (int i = 0; i < 2; i++)
        #pragma unroll
        for (int j = 0; j < 8; j++)
            #pragma unroll
            for (int q = 0; q < 4; q++) acc[i][j][q] = 0.f;

    int ktiles = Kd / 64;
    stage_issue(0, 0);
    stage_issue(1, 1);
    uint32_t phases = 0;

    for (int kt = 0; kt < ktiles; kt++) {
        int s = kt % NSTAGE;
        uint32_t mb = smem_base + (uint32_t)(MBAR_OFF + s * 8);
        MBARRIER_WAIT_PARITY(mb, (phases >> s) & 1);
        phases ^= (1u << s);
        uint32_t stg = smem_base + (uint32_t)(s * STAGE_BYTES);

        #pragma unroll
        for (int kk = 0; kk < 4; kk++) {            // four k16 blocks per ktile
            uint32_t c0 = (uint32_t)(kk * 2);

            uint32_t afr[2][4];
            #pragma unroll
            for (int mi = 0; mi < 2; mi++) {
                uint32_t addr = stg + aRow[mi] + ((c0 + acs) << 4);
                ldm_x4(afr[mi][0], afr[mi][1], afr[mi][2], afr[mi][3], addr);
            }
            uint32_t bfr[4][4];
            #pragma unroll
            for (int p = 0; p < 4; p++) {
                uint32_t addr = stg + bRow[p] + ((c0 + bcs) << 4);
                ldm_x4(bfr[p][0], bfr[p][1], bfr[p][2], bfr[p][3], addr);
            }
            #pragma unroll
            for (int p = 0; p < 4; p++) {
                #pragma unroll
                for (int h = 0; h < 2; h++) {
                    int ni = p * 2 + h;
                    uint32_t b0 = bfr[p][2 * h], b1 = bfr[p][2 * h + 1];
                    mma_f16(acc[0][ni], afr[0][0], afr[0][1], afr[0][2], afr[0][3], b0, b1);
                    mma_f16(acc[1][ni], afr[1][0], afr[1][1], afr[1][2], afr[1][3], b0, b1);
                }
            }
        }
        __syncthreads();                 // all warps done reading stage (kt+2)%3's old data
        if (kt + 2 < ktiles) stage_issue(kt + 2, (kt + 2) % NSTAGE);
    }

    // ---- epilogue
    #pragma unroll
    for (int mi = 0; mi < 2; mi++) {
        int r0 = m0 + wm * 32 + mi * 16 + g;
        bool v0 = r0 < M, v1 = (r0 + 8) < M;
        size_t base0 = (size_t)(off + r0) * Nout;
        size_t base1 = (size_t)(off + r0 + 8) * Nout;
        if (ACT) {
            __half* Ch = (__half*)Cv;
            #pragma unroll
            for (int ni = 0; ni < 4; ni++) {
                int col = nb * 64 + wn * 32 + ni * 8 + tg * 2;
                if (v0) {
                    __half2 o = __floats2half2_rn(
                        silu_mul(acc[mi][ni][0], acc[mi][ni + 4][0]),
                        silu_mul(acc[mi][ni][1], acc[mi][ni + 4][1]));
                    *(__half2*)(Ch + base0 + col) = o;
                }
                if (v1) {
                    __half2 o = __floats2half2_rn(
                        silu_mul(acc[mi][ni][2], acc[mi][ni + 4][2]),
                        silu_mul(acc[mi][ni][3], acc[mi][ni + 4][3]));
                    *(__half2*)(Ch + base1 + col) = o;
                }
            }
        } else {
            float* Cf = (float*)Cv;
            #pragma unroll
            for (int ni = 0; ni < 8; ni++) {
                int col = nb * BN + wn * 64 + ni * 8 + tg * 2;
                if (v0) {
                    float2 o; o.x = acc[mi][ni][0]; o.y = acc[mi][ni][1];
                    *(float2*)(Cf + base0 + col) = o;
                }
                if (v1) {
                    float2 o; o.x = acc[mi][ni][2]; o.y = acc[mi][ni][3];
                    *(float2*)(Cf + base1 + col) = o;
                }
            }
        }
    }
}

// ---------------------------------------------------------------------------
// Combine
// ---------------------------------------------------------------------------
__global__ void combine_k(float* __restrict__ out) {
    int t = blockIdx.x;
    __shared__ int   rws[KSEL];
    __shared__ float ws[KSEL];
    if (threadIdx.x < KSEL) {
        rws[threadIdx.x] = g_row_of_tk[t * KSEL + threadIdx.x];
        ws[threadIdx.x]  = g_top_w[t * KSEL + threadIdx.x];
    }
    __syncthreads();
    for (int d = threadIdx.x; d < HDIM; d += blockDim.x) {
        float a = g_sh_out[(size_t)t * HDIM + d];
        float m = 0.f;
        #pragma unroll
        for (int k = 0; k < KSEL; k++)
            m += ws[k] * g_down[(size_t)rws[k] * HDIM + d];
        out[(size_t)t * HDIM + d] = (a + 8.f * m) * (1.f / 9.f);
    }
}

// ---------------------------------------------------------------------------
// kernel_launch — graph-capturable, allocation-free, three-stream DAG.
// Host launch order makes moe_gu(first half) launch #4 (the ncu slot).
// ---------------------------------------------------------------------------
extern "C" void kernel_launch(void* const* d_in, const int* in_sizes, int n_in,
                              void* d_out, int out_size)
{
    const float* x      = (const float*)d_in[0];
    const float* w_gate = (const float*)d_in[1];
    const float* w13    = (const float*)d_in[2];
    const float* w2     = (const float*)d_in[3];
    const float* wsg    = (const float*)d_in[4];
    const float* wsd    = (const float*)d_in[5];
    float* out = (float*)d_out;

    __half *p_w13h, *p_w2h, *p_wsgh, *p_wsdh, *p_xh, *p_h, *p_h_s;
    float  *p_down, *p_sh_out;
    cudaGetSymbolAddress((void**)&p_w13h,   g_w13h);
    cudaGetSymbolAddress((void**)&p_w2h,    g_w2h);
    cudaGetSymbolAddress((void**)&p_wsgh,   g_wsgh);
    cudaGetSymbolAddress((void**)&p_wsdh,   g_wsdh);
    cudaGetSymbolAddress((void**)&p_xh,     g_xh);
    cudaGetSymbolAddress((void**)&p_h,      g_h);
    cudaGetSymbolAddress((void**)&p_h_s,    g_h_s);
    cudaGetSymbolAddress((void**)&p_down,   g_down);
    cudaGetSymbolAddress((void**)&p_sh_out, g_sh_out);

    cudaFuncSetAttribute(gemm8<true,  true,  true >, cudaFuncAttributeMaxDynamicSharedMemorySize, GEMM_SMEM);
    cudaFuncSetAttribute(gemm8<false, true,  false>, cudaFuncAttributeMaxDynamicSharedMemorySize, GEMM_SMEM);
    cudaFuncSetAttribute(gemm8<false, false, true >, cudaFuncAttributeMaxDynamicSharedMemorySize, GEMM_SMEM);
    cudaFuncSetAttribute(gemm8<false, false, false>, cudaFuncAttributeMaxDynamicSharedMemorySize, GEMM_SMEM);

    static cudaStream_t s2 = nullptr, s3 = nullptr;
    static cudaEvent_t evFork = nullptr, evX = nullptr, evW13a = nullptr,
                       evW13b = nullptr, evW2 = nullptr, evJoin = nullptr;
    if (!s2) {
        cudaStreamCreateWithFlags(&s2, cudaStreamNonBlocking);
        cudaStreamCreateWithFlags(&s3, cudaStreamNonBlocking);
        cudaEventCreateWithFlags(&evFork,  cudaEventDisableTiming);
        cudaEventCreateWithFlags(&evX,     cudaEventDisableTiming);
        cudaEventCreateWithFlags(&evW13a,  cudaEventDisableTiming);
        cudaEventCreateWithFlags(&evW13b,  cudaEventDisableTiming);
        cudaEventCreateWithFlags(&evW2,    cudaEventDisableTiming);
        cudaEventCreateWithFlags(&evJoin,  cudaEventDisableTiming);
    }

    const size_t W13_HALF = (size_t)(NEXP / 2) * 2 * IDIM * HDIM;   // elements

    // fork at t=0
    cudaEventRecord(evFork, 0);
    cudaStreamWaitEvent(s2, evFork, 0);
    cudaStreamWaitEvent(s3, evFork, 0);

    // s0 #1: cvt x (zeros router counts), mark evX
    cvt_init_k<<<1024, 256>>>((const float4*)x, (uint2*)p_xh, (long)T_TOK * HDIM / 4);
    cudaEventRecord(evX, 0);

    // s0 #2: fused router + scan + assign
    router_fused_k<<<T_TOK, 256>>>(x, w_gate);

    // s2 #3: w13 first half convert
    cvt_k<<<8192, 256, 0, s2>>>((const float4*)w13, (uint2*)p_w13h, (long)(W13_HALF / 4));
    cudaEventRecord(evW13a, s2);

    // s0 #4: MoE gate_up, experts 0-31  (ncu profile slot)
    cudaStreamWaitEvent(0, evW13a, 0);
    gemm8<true, true, true><<<dim3(IDIM / 64, 8, NEXP / 2), 256, GEMM_SMEM>>>(
        p_xh, p_w13h, p_h, HDIM, IDIM, (size_t)2 * IDIM * HDIM, IDIM, 0, 0);

    // s2 #5: w13 second half convert
    cvt_k<<<8192, 256, 0, s2>>>((const float4*)(w13 + W13_HALF), (uint2*)(p_w13h + W13_HALF),
                                (long)(W13_HALF / 4));
    cudaEventRecord(evW13b, s2);

    // s0 #6: MoE gate_up, experts 32-63
    cudaStreamWaitEvent(0, evW13b, 0);
    gemm8<true, true, true><<<dim3(IDIM / 64, 8, NEXP / 2), 256, GEMM_SMEM>>>(
        p_xh, p_w13h, p_h, HDIM, IDIM, (size_t)2 * IDIM * HDIM, IDIM, 0, NEXP / 2);

    // s2 #7: w2 convert
    cvt_k<<<8192, 256, 0, s2>>>((const float4*)w2, (uint2*)p_w2h, (long)NEXP * HDIM * IDIM / 4);
    cudaEventRecord(evW2, s2);

    // s3 #8-#11: shared chain
    cvt_k<<<2048, 256, 0, s3>>>((const float4*)wsg, (uint2*)p_wsgh, (long)2 * SIDIM * HDIM / 4);
    cvt_k<<<2048, 256, 0, s3>>>((const float4*)wsd, (uint2*)p_wsdh, (long)HDIM * SIDIM / 4);
    cudaStreamWaitEvent(s3, evX, 0);
    gemm8<false, false, true ><<<dim3(SIDIM / 64, T_TOK / BM, 1), 256, GEMM_SMEM, s3>>>(
        p_xh, p_wsgh, p_h_s, HDIM, SIDIM, 0, SIDIM, T_TOK, 0);
    gemm8<false, false, false><<<dim3(HDIM / BN, T_TOK / BM, 1), 256, GEMM_SMEM, s3>>>(
        p_h_s, p_wsdh, p_sh_out, SIDIM, HDIM, 0, 0, T_TOK, 0);
    cudaEventRecord(evJoin, s3);

    // s0 #12: MoE down
    cudaStreamWaitEvent(0, evW2, 0);
    gemm8<false, true, false><<<dim3(HDIM / BN, 8, NEXP), 256, GEMM_SMEM>>>(
        p_h, p_w2h, p_down, IDIM, HDIM, (size_t)HDIM * IDIM, 0, 0, 0);

    // s0 #13: combine
    cudaStreamWaitEvent(0, evJoin, 0);
    combine_k<<<T_TOK, 256>>>(out);
}

// round 13
// speedup vs baseline: 2.6682x; 1.1979x over previous
#include <cuda_runtime.h>
#include <cuda.h>
#include <cuda_fp16.h>
#include <cstdint>
#include <cmath>

// Problem constants
#define T_TOK 1024
#define HDIM  2048
#define NEXP  64
#define IDIM  1024
#define SIDIM 4096
#define KSEL  8
#define NROWS (T_TOK * KSEL)

// Tile config: CTA 128x128, 8 warps (4Mx2N), warp tile 32x64, fp16 BK=64.
#define BM 128
#define BN 128
#define NSTAGE 3
#define STAGE_TX 32768                         // bytes delivered per stage (A+B)
#define GS_GATHER 105024                       // 3*(128*144+16384)+64+512
#define GS_DENSE  98880                        // 3*32768+64+512

// ---------------------------------------------------------------------------
// Device-global scratch
// ---------------------------------------------------------------------------
__device__ __align__(256) __half g_w13h[(size_t)NEXP * 2 * IDIM * HDIM]; // 512MB
__device__ __align__(256) __half g_w2h [(size_t)NEXP * HDIM * IDIM];     // 256MB
__device__ __align__(256) __half g_wsgh[(size_t)2 * SIDIM * HDIM];       // 32MB
__device__ __align__(256) __half g_wsdh[(size_t)HDIM * SIDIM];           // 16MB
__device__ __align__(256) __half g_xh  [(size_t)T_TOK * HDIM];
__device__ __align__(256) __half g_h   [(size_t)NROWS * IDIM];
__device__ __align__(256) __half g_h_s [(size_t)T_TOK * SIDIM];
__device__ __align__(256) float  g_down[(size_t)NROWS * HDIM];
__device__ __align__(256) float  g_sh_out[(size_t)T_TOK * HDIM];

__device__ int   g_counts[NEXP];
__device__ int   g_offsets[NEXP];
__device__ int   g_fill[NEXP];
__device__ int   g_rowmap[NROWS];
__device__ int   g_row_of_tk[NROWS];
__device__ int   g_top_e[NROWS];
__device__ float g_top_w[NROWS];
__device__ int   g_ticket;

// ---------------------------------------------------------------------------
// Helpers
// ---------------------------------------------------------------------------
#define MBARRIER_INIT(addr, cnt) \
    asm volatile("mbarrier.init.shared.b64 [%0], %1;" :: "r"((uint32_t)(addr)), "r"((uint32_t)(cnt)) : "memory")

#define MBARRIER_EXPECT_TX(addr, bytes) \
    asm volatile("mbarrier.arrive.expect_tx.shared.b64 _, [%0], %1;" \
        :: "r"((uint32_t)(addr)), "r"((uint32_t)(bytes)) : "memory")

#define MBARRIER_WAIT_PARITY(addr, parity) do {                                         \
    uint32_t _m = (uint32_t)(addr); uint32_t _p = (uint32_t)(parity); uint32_t _d;      \
    asm volatile("{ .reg .pred p; mbarrier.try_wait.parity.acquire.cta.shared::cta.b64 p, [%1], %2; selp.b32 %0,1,0,p; }" \
        : "=r"(_d) : "r"(_m), "r"(_p) : "memory");                                      \
    if (!_d) {                                                                          \
        asm volatile("{ .reg .pred P1; WL_%=: mbarrier.try_wait.parity.acquire.cta.shared::cta.b64 P1, [%0], %1, 0x989680; @P1 bra.uni WD_%=; bra.uni WL_%=; WD_%=: }" \
            :: "r"(_m), "r"(_p) : "memory");                                            \
    }                                                                                   \
} while (0)

#define FENCE_ASYNC() asm volatile("fence.proxy.async.shared::cta;" ::: "memory")

__device__ __forceinline__ void bulk_g2s(uint32_t dst, const void* src, uint32_t bytes, uint32_t mbar) {
    asm volatile("cp.async.bulk.shared::cluster.global.mbarrier::complete_tx::bytes [%0], [%1], %2, [%3];"
                 :: "r"(dst), "l"(src), "r"(bytes), "r"(mbar) : "memory");
}

__device__ __forceinline__ void tma2d(uint32_t dst, const CUtensorMap* tm, int x, int y, uint32_t mbar) {
    asm volatile("cp.async.bulk.tensor.2d.shared::cta.global.tile.mbarrier::complete_tx::bytes "
                 "[%0], [%1, {%2, %3}], [%4];"
                 :: "r"(dst), "l"(tm), "r"(x), "r"(y), "r"(mbar) : "memory");
}

__device__ __forceinline__ void ldm_x4(uint32_t& r0, uint32_t& r1, uint32_t& r2, uint32_t& r3,
                                       uint32_t addr) {
    asm volatile("ldmatrix.sync.aligned.m8n8.x4.shared.b16 {%0,%1,%2,%3}, [%4];"
                 : "=r"(r0), "=r"(r1), "=r"(r2), "=r"(r3) : "r"(addr));
}

__device__ __forceinline__ void mma_f16(float c[4],
                                        uint32_t a0, uint32_t a1, uint32_t a2, uint32_t a3,
                                        uint32_t b0, uint32_t b1) {
    asm volatile(
        "mma.sync.aligned.m16n8k16.row.col.f32.f16.f16.f32 "
        "{%0,%1,%2,%3},{%4,%5,%6,%7},{%8,%9},{%0,%1,%2,%3};\n"
        : "+f"(c[0]), "+f"(c[1]), "+f"(c[2]), "+f"(c[3])
        : "r"(a0), "r"(a1), "r"(a2), "r"(a3), "r"(b0), "r"(b1));
}

__device__ __forceinline__ float silu_mul(float g, float u) {
    return g * u / (1.f + expf(-g));
}

// ---------------------------------------------------------------------------
// fp32 -> fp16 convert kernels
// ---------------------------------------------------------------------------
__global__ void cvt_k(const float4* __restrict__ in, uint2* __restrict__ outp, long n4) {
    long i = (long)blockIdx.x * blockDim.x + threadIdx.x;
    long stride = (long)gridDim.x * blockDim.x;
    for (; i < n4; i += stride) {
        float4 v = in[i];
        __half2 h0 = __floats2half2_rn(v.x, v.y);
        __half2 h1 = __floats2half2_rn(v.z, v.w);
        uint2 o;
        o.x = *(uint32_t*)&h0;
        o.y = *(uint32_t*)&h1;
        outp[i] = o;
    }
}

__global__ void cvt_init_k(const float4* __restrict__ in, uint2* __restrict__ outp, long n4) {
    if (blockIdx.x == 0 && threadIdx.x < NEXP) g_counts[threadIdx.x] = 0;
    long i = (long)blockIdx.x * blockDim.x + threadIdx.x;
    long stride = (long)gridDim.x * blockDim.x;
    for (; i < n4; i += stride) {
        float4 v = in[i];
        __half2 h0 = __floats2half2_rn(v.x, v.y);
        __half2 h1 = __floats2half2_rn(v.z, v.w);
        uint2 o;
        o.x = *(uint32_t*)&h0;
        o.y = *(uint32_t*)&h1;
        outp[i] = o;
    }
}

// ---------------------------------------------------------------------------
// Fused router + scan + assign (ticket: last block finalizes)
// ---------------------------------------------------------------------------
__global__ void router_fused_k(const float* __restrict__ x, const float* __restrict__ wg) {
    int t = blockIdx.x;
    __shared__ float xs[HDIM];
    __shared__ float sc[NEXP];
    __shared__ int isLast;
    for (int d = threadIdx.x; d < HDIM; d += blockDim.x) xs[d] = x[(size_t)t * HDIM + d];
    __syncthreads();

    int w = threadIdx.x >> 5, lane = threadIdx.x & 31;
    for (int e = w * 8; e < w * 8 + 8; e++) {
        const float* wr = wg + (size_t)e * HDIM;
        float s = 0.f;
        for (int d = lane; d < HDIM; d += 32) s += xs[d] * wr[d];
        #pragma unroll
        for (int o = 16; o; o >>= 1) s += __shfl_xor_sync(0xffffffffu, s, o);
        if (lane == 0) sc[e] = 1.f / (1.f + expf(-s));
    }
    __syncthreads();

    if (threadIdx.x == 0) {
        for (int k = 0; k < KSEL; k++) {
            int best = 0; float bv = sc[0];
            for (int e = 1; e < NEXP; e++)
                if (sc[e] > bv) { bv = sc[e]; best = e; }
            g_top_e[t * KSEL + k] = best;
            g_top_w[t * KSEL + k] = bv;
            atomicAdd(&g_counts[best], 1);
            sc[best] = -1.f;
        }
    }

    __threadfence();
    if (threadIdx.x == 0) {
        int tk = atomicAdd(&g_ticket, 1);
        isLast = (tk == (int)gridDim.x - 1);
        if (isLast) g_ticket = 0;
    }
    __syncthreads();
    if (!isLast) return;

    if (threadIdx.x == 0) {
        int acc = 0;
        for (int e = 0; e < NEXP; e++) {
            g_offsets[e] = acc;
            g_fill[e] = acc;
            acc += g_counts[e];
        }
    }
    __syncthreads();
    for (int idx = threadIdx.x; idx < NROWS; idx += blockDim.x) {
        int e = g_top_e[idx];
        int r = atomicAdd(&g_fill[e], 1);
        g_rowmap[r] = idx >> 3;
        g_row_of_tk[idx] = r;
    }
}

// ---------------------------------------------------------------------------
// gemm9 — FP16 mma.sync + TMA tensor-load producers.
// CTA 128x128, 8 warps (4Mx2N), warp tile 32x64, BK=64 fp16, 3-stage ring.
// B (and dense A) staged via cp.async.bulk.tensor.2d with SW128 swizzle
// (chunk c of row r at c^(r&7) — same mapping verified in rounds 5-11).
// Gathered A staged via per-thread cp.async.bulk, 144B pitch, unswizzled.
// ---------------------------------------------------------------------------
template <bool GATHER, bool EXPERT, bool ACT>
__global__ void __launch_bounds__(256, 2)
gemm9(const __half* __restrict__ A,
      const __grid_constant__ CUtensorMap tmA,
      const __grid_constant__ CUtensorMap tmB,
      void* __restrict__ Cv,
      int Kd, int Nout, int rowsBe, int upOff, int Mdense, int eBase)
{
    constexpr int APITCH = GATHER ? 144 : 128;
    constexpr int ABYTES = 128 * APITCH;
    constexpr int STG_B  = ABYTES + 128 * 128;
    constexpr int MBOFF  = NSTAGE * STG_B;
    constexpr int AROFF  = MBOFF + 64;

    extern __shared__ char sm[];
    int e = EXPERT ? (eBase + blockIdx.z) : 0;
    int M, off;
    if (EXPERT) { M = g_counts[e]; off = g_offsets[e]; }
    else        { M = Mdense;      off = 0; }
    int m0 = blockIdx.y * BM;
    if (m0 >= M) return;
    int nb = blockIdx.x;

    int tid = threadIdx.x, warp = tid >> 5, lane = tid & 31;
    uint32_t smem_base = (uint32_t)__cvta_generic_to_shared(sm);
    const CUtensorMap* tmAp = &tmA;
    const CUtensorMap* tmBp = &tmB;
    int rowBase = EXPERT ? e * rowsBe : 0;
    int aRow0 = off + m0;

    if (tid == 0) {
        #pragma unroll
        for (int s = 0; s < NSTAGE; s++) MBARRIER_INIT(smem_base + MBOFF + s * 8, 1);
        FENCE_ASYNC();
    }

    const __half* srcp = A;
    if (GATHER) {
        int* arows = (int*)(sm + AROFF);
        if (tid < BM) {
            int gr = m0 + tid;
            int ar = -1;
            if (gr < M) ar = g_rowmap[off + gr];
            arows[tid] = ar;
        }
        __syncthreads();
        if (tid < BM) {
            int ar = arows[tid];
            if (ar < 0) ar = arows[0] >= 0 ? arows[0] : 0;   // clamp; masked in epilogue
            srcp = A + (size_t)ar * Kd;
        }
    } else {
        __syncthreads();
    }
    uint32_t myslotA = smem_base + (uint32_t)(tid * APITCH);

    auto stage_issue = [&](int kt, int s) {
        uint32_t mb = smem_base + (uint32_t)(MBOFF + s * 8);
        uint32_t stg = smem_base + (uint32_t)(s * STG_B);
        int k0 = kt * 64;
        if (tid == 0) {
            MBARRIER_EXPECT_TX(mb, STAGE_TX);
            if (!GATHER)
                tma2d(stg, tmAp, k0, aRow0, mb);
            if (ACT) {
                tma2d(stg + ABYTES,            tmBp, k0, rowBase + nb * 64,         mb);
                tma2d(stg + ABYTES + 64 * 128, tmBp, k0, rowBase + upOff + nb * 64, mb);
            } else {
                tma2d(stg + ABYTES, tmBp, k0, rowBase + nb * BN, mb);
            }
        }
        if (GATHER && tid < BM)
            bulk_g2s(myslotA + (uint32_t)(s * STG_B), srcp + (size_t)k0, 128u, mb);
    };

    // ---- consumer constants
    int wm = warp & 3;               // M slice (32 rows)
    int wn = warp >> 2;              // N slice (64 B rows)
    int g  = lane >> 2, tg = lane & 3;

    int aro  = (lane & 7) + ((lane >> 3) & 1) * 8;
    int acs  = (lane >> 4) & 1;
    int bro  = (lane & 7) + ((lane >> 4) & 1) * 8;
    int bcs  = (lane >> 3) & 1;

    uint32_t aRow[2], aMod[2];
    #pragma unroll
    for (int mi = 0; mi < 2; mi++) {
        int r = wm * 32 + mi * 16 + aro;
        aRow[mi] = (uint32_t)(r * APITCH);
        aMod[mi] = GATHER ? 0u : (uint32_t)(r & 7);
    }
    uint32_t bRow[4], bMod[4];
    #pragma unroll
    for (int p = 0; p < 4; p++) {
        int base;
        if (ACT) base = (p < 2) ? (wn * 32 + p * 16) : (64 + wn * 32 + (p - 2) * 16);
        else     base = wn * 64 + p * 16;
        int r = base + bro;
        bRow[p] = (uint32_t)(ABYTES + r * 128);
        bMod[p] = (uint32_t)(r & 7);
    }

    float acc[2][8][4];
    #pragma unroll
    for (int i = 0; i < 2; i++)
        #pragma unroll
        for (int j = 0; j < 8; j++)
            #pragma unroll
            for (int q = 0; q < 4; q++) acc[i][j][q] = 0.f;

    int ktiles = Kd / 64;
    stage_issue(0, 0);
    stage_issue(1, 1);
    uint32_t phases = 0;

    for (int kt = 0; kt < ktiles; kt++) {
        int s = kt % NSTAGE;
        uint32_t mb = smem_base + (uint32_t)(MBOFF + s * 8);
        MBARRIER_WAIT_PARITY(mb, (phases >> s) & 1);
        phases ^= (1u << s);
        uint32_t stg = smem_base + (uint32_t)(s * STG_B);

        #pragma unroll
        for (int kk = 0; kk < 4; kk++) {
            uint32_t c0 = (uint32_t)(kk * 2);

            uint32_t afr[2][4];
            #pragma unroll
            for (int mi = 0; mi < 2; mi++) {
                uint32_t addr = stg + aRow[mi] + ((((c0 + acs) ^ aMod[mi])) << 4);
                ldm_x4(afr[mi][0], afr[mi][1], afr[mi][2], afr[mi][3], addr);
            }
            uint32_t bfr[4][4];
            #pragma unroll
            for (int p = 0; p < 4; p++) {
                uint32_t addr = stg + bRow[p] + ((((c0 + bcs) ^ bMod[p])) << 4);
                ldm_x4(bfr[p][0], bfr[p][1], bfr[p][2], bfr[p][3], addr);
            }
            #pragma unroll
            for (int p = 0; p < 4; p++) {
                #pragma unroll
                for (int h = 0; h < 2; h++) {
                    int ni = p * 2 + h;
                    uint32_t b0 = bfr[p][2 * h], b1 = bfr[p][2 * h + 1];
                    mma_f16(acc[0][ni], afr[0][0], afr[0][1], afr[0][2], afr[0][3], b0, b1);
                    mma_f16(acc[1][ni], afr[1][0], afr[1][1], afr[1][2], afr[1][3], b0, b1);
                }
            }
        }
        __syncthreads();
        if (kt + 2 < ktiles) stage_issue(kt + 2, (kt + 2) % NSTAGE);
    }

    // ---- epilogue
    #pragma unroll
    for (int mi = 0; mi < 2; mi++) {
        int r0 = m0 + wm * 32 + mi * 16 + g;
        bool v0 = r0 < M, v1 = (r0 + 8) < M;
        size_t base0 = (size_t)(off + r0) * Nout;
        size_t base1 = (size_t)(off + r0 + 8) * Nout;
        if (ACT) {
            __half* Ch = (__half*)Cv;
            #pragma unroll
            for (int ni = 0; ni < 4; ni++) {
                int col = nb * 64 + wn * 32 + ni * 8 + tg * 2;
                if (v0) {
                    __half2 o = __floats2half2_rn(
                        silu_mul(acc[mi][ni][0], acc[mi][ni + 4][0]),
                        silu_mul(acc[mi][ni][1], acc[mi][ni + 4][1]));
                    *(__half2*)(Ch + base0 + col) = o;
                }
                if (v1) {
                    __half2 o = __floats2half2_rn(
                        silu_mul(acc[mi][ni][2], acc[mi][ni + 4][2]),
                        silu_mul(acc[mi][ni][3], acc[mi][ni + 4][3]));
                    *(__half2*)(Ch + base1 + col) = o;
                }
            }
        } else {
            float* Cf = (float*)Cv;
            #pragma unroll
            for (int ni = 0; ni < 8; ni++) {
                int col = nb * BN + wn * 64 + ni * 8 + tg * 2;
                if (v0) {
                    float2 o; o.x = acc[mi][ni][0]; o.y = acc[mi][ni][1];
                    *(float2*)(Cf + base0 + col) = o;
                }
                if (v1) {
                    float2 o; o.x = acc[mi][ni][2]; o.y = acc[mi][ni][3];
                    *(float2*)(Cf + base1 + col) = o;
                }
            }
        }
    }
}

// ---------------------------------------------------------------------------
// Combine
// ---------------------------------------------------------------------------
__global__ void combine_k(float* __restrict__ out) {
    int t = blockIdx.x;
    __shared__ int   rws[KSEL];
    __shared__ float ws[KSEL];
    if (threadIdx.x < KSEL) {
        rws[threadIdx.x] = g_row_of_tk[t * KSEL + threadIdx.x];
        ws[threadIdx.x]  = g_top_w[t * KSEL + threadIdx.x];
    }
    __syncthreads();
    for (int d = threadIdx.x; d < HDIM; d += blockDim.x) {
        float a = g_sh_out[(size_t)t * HDIM + d];
        float m = 0.f;
        #pragma unroll
        for (int k = 0; k < KSEL; k++)
            m += ws[k] * g_down[(size_t)rws[k] * HDIM + d];
        out[(size_t)t * HDIM + d] = (a + 8.f * m) * (1.f / 9.f);
    }
}

// ---------------------------------------------------------------------------
// kernel_launch — graph-capturable, allocation-free, three-stream DAG.
// Tensormaps built host-side once via driver entry point (no -lcuda link).
// ---------------------------------------------------------------------------
typedef CUresult (CUDAAPI *PFN_encodeTiled)(
    CUtensorMap*, CUtensorMapDataType, cuuint32_t, void*,
    const cuuint64_t*, const cuuint64_t*, const cuuint32_t*, const cuuint32_t*,
    CUtensorMapInterleave, CUtensorMapSwizzle, CUtensorMapL2promotion,
    CUtensorMapFloatOOBfill);

extern "C" void kernel_launch(void* const* d_in, const int* in_sizes, int n_in,
                              void* d_out, int out_size)
{
    const float* x      = (const float*)d_in[0];
    const float* w_gate = (const float*)d_in[1];
    const float* w13    = (const float*)d_in[2];
    const float* w2     = (const float*)d_in[3];
    const float* wsg    = (const float*)d_in[4];
    const float* wsd    = (const float*)d_in[5];
    float* out = (float*)d_out;

    __half *p_w13h, *p_w2h, *p_wsgh, *p_wsdh, *p_xh, *p_h, *p_h_s;
    float  *p_down, *p_sh_out;
    cudaGetSymbolAddress((void**)&p_w13h,   g_w13h);
    cudaGetSymbolAddress((void**)&p_w2h,    g_w2h);
    cudaGetSymbolAddress((void**)&p_wsgh,   g_wsgh);
    cudaGetSymbolAddress((void**)&p_wsdh,   g_wsdh);
    cudaGetSymbolAddress((void**)&p_xh,     g_xh);
    cudaGetSymbolAddress((void**)&p_h,      g_h);
    cudaGetSymbolAddress((void**)&p_h_s,    g_h_s);
    cudaGetSymbolAddress((void**)&p_down,   g_down);
    cudaGetSymbolAddress((void**)&p_sh_out, g_sh_out);

    static bool tmInit = false;
    static CUtensorMap tmXh, tmH, tmHs, tmW13, tmW2, tmWsg, tmWsd;
    if (!tmInit) {
        PFN_encodeTiled enc = nullptr;
        cudaDriverEntryPointQueryResult qr;
        cudaGetDriverEntryPoint("cuTensorMapEncodeTiled", (void**)&enc, cudaEnableDefault, &qr);
        auto mk = [&](CUtensorMap* tm, void* ptr, unsigned long long d0, unsigned long long d1,
                      unsigned b0, unsigned b1) {
            cuuint64_t dims[2]    = {d0, d1};
            cuuint64_t strides[1] = {d0 * 2};
            cuuint32_t box[2]     = {b0, b1};
            cuuint32_t es[2]      = {1, 1};
            enc(tm, CU_TENSOR_MAP_DATA_TYPE_FLOAT16, 2, ptr, dims, strides, box, es,
                CU_TENSOR_MAP_INTERLEAVE_NONE, CU_TENSOR_MAP_SWIZZLE_128B,
                CU_TENSOR_MAP_L2_PROMOTION_L2_128B, CU_TENSOR_MAP_FLOAT_OOB_FILL_NONE);
        };
        mk(&tmXh,  p_xh,   HDIM,  T_TOK,                             64, 128);
        mk(&tmH,   p_h,    IDIM,  NROWS,                             64, 128);
        mk(&tmHs,  p_h_s,  SIDIM, T_TOK,                             64, 128);
        mk(&tmW13, p_w13h, HDIM,  (unsigned long long)NEXP * 2 * IDIM, 64, 64);
        mk(&tmW2,  p_w2h,  IDIM,  (unsigned long long)NEXP * HDIM,     64, 128);
        mk(&tmWsg, p_wsgh, HDIM,  2 * SIDIM,                         64, 64);
        mk(&tmWsd, p_wsdh, SIDIM, HDIM,                              64, 128);
        tmInit = true;
    }

    cudaFuncSetAttribute(gemm9<true,  true,  true >, cudaFuncAttributeMaxDynamicSharedMemorySize, GS_GATHER);
    cudaFuncSetAttribute(gemm9<false, true,  false>, cudaFuncAttributeMaxDynamicSharedMemorySize, GS_DENSE);
    cudaFuncSetAttribute(gemm9<false, false, true >, cudaFuncAttributeMaxDynamicSharedMemorySize, GS_DENSE);
    cudaFuncSetAttribute(gemm9<false, false, false>, cudaFuncAttributeMaxDynamicSharedMemorySize, GS_DENSE);

    static cudaStream_t s2 = nullptr, s3 = nullptr;
    static cudaEvent_t evFork = nullptr, evX = nullptr, evW13a = nullptr,
                       evW13b = nullptr, evW2 = nullptr, evJoin = nullptr;
    if (!s2) {
        cudaStreamCreateWithFlags(&s2, cudaStreamNonBlocking);
        cudaStreamCreateWithFlags(&s3, cudaStreamNonBlocking);
        cudaEventCreateWithFlags(&evFork,  cudaEventDisableTiming);
        cudaEventCreateWithFlags(&evX,     cudaEventDisableTiming);
        cudaEventCreateWithFlags(&evW13a,  cudaEventDisableTiming);
        cudaEventCreateWithFlags(&evW13b,  cudaEventDisableTiming);
        cudaEventCreateWithFlags(&evW2,    cudaEventDisableTiming);
        cudaEventCreateWithFlags(&evJoin,  cudaEventDisableTiming);
    }

    const size_t W13_HALF = (size_t)(NEXP / 2) * 2 * IDIM * HDIM;   // elements

    // fork at t=0
    cudaEventRecord(evFork, 0);
    cudaStreamWaitEvent(s2, evFork, 0);
    cudaStreamWaitEvent(s3, evFork, 0);

    // s0 #1: cvt x (zeros router counts)
    cvt_init_k<<<1024, 256>>>((const float4*)x, (uint2*)p_xh, (long)T_TOK * HDIM / 4);
    cudaEventRecord(evX, 0);

    // s0 #2: fused router + scan + assign
    router_fused_k<<<T_TOK, 256>>>(x, w_gate);

    // s2 #3: w13 first half convert
    cvt_k<<<8192, 256, 0, s2>>>((const float4*)w13, (uint2*)p_w13h, (long)(W13_HALF / 4));
    cudaEventRecord(evW13a, s2);

    // s0 #4: MoE gate_up, experts 0-31 (ncu profile slot)
    cudaStreamWaitEvent(0, evW13a, 0);
    gemm9<true, true, true><<<dim3(IDIM / 64, 8, NEXP / 2), 256, GS_GATHER>>>(
        p_xh, tmXh, tmW13, p_h, HDIM, IDIM, 2 * IDIM, IDIM, 0, 0);

    // s2 #5: w13 second half convert
    cvt_k<<<8192, 256, 0, s2>>>((const float4*)(w13 + W13_HALF), (uint2*)(p_w13h + W13_HALF),
                                (long)(W13_HALF / 4));
    cudaEventRecord(evW13b, s2);

    // s0 #6: MoE gate_up, experts 32-63
    cudaStreamWaitEvent(0, evW13b, 0);
    gemm9<true, true, true><<<dim3(IDIM / 64, 8, NEXP / 2), 256, GS_GATHER>>>(
        p_xh, tmXh, tmW13, p_h, HDIM, IDIM, 2 * IDIM, IDIM, 0, NEXP / 2);

    // s2 #7: w2 convert
    cvt_k<<<8192, 256, 0, s2>>>((const float4*)w2, (uint2*)p_w2h, (long)NEXP * HDIM * IDIM / 4);
    cudaEventRecord(evW2, s2);

    // s3: shared chain
    cvt_k<<<2048, 256, 0, s3>>>((const float4*)wsg, (uint2*)p_wsgh, (long)2 * SIDIM * HDIM / 4);
    cvt_k<<<2048, 256, 0, s3>>>((const float4*)wsd, (uint2*)p_wsdh, (long)HDIM * SIDIM / 4);
    cudaStreamWaitEvent(s3, evX, 0);
    gemm9<false, false, true ><<<dim3(SIDIM / 64, T_TOK / BM, 1), 256, GS_DENSE, s3>>>(
        p_xh, tmXh, tmWsg, p_h_s, HDIM, SIDIM, 0, SIDIM, T_TOK, 0);
    gemm9<false, false, false><<<dim3(HDIM / BN, T_TOK / BM, 1), 256, GS_DENSE, s3>>>(
        p_h_s, tmHs, tmWsd, p_sh_out, SIDIM, HDIM, 0, 0, T_TOK, 0);
    cudaEventRecord(evJoin, s3);

    // s0: MoE down
    cudaStreamWaitEvent(0, evW2, 0);
    gemm9<false, true, false><<<dim3(HDIM / BN, 8, NEXP), 256, GS_DENSE>>>(
        p_h, tmH, tmW2, p_down, IDIM, HDIM, HDIM, 0, 0, 0);

    // s0: combine
    cudaStreamWaitEvent(0, evJoin, 0);
    combine_k<<<T_TOK, 256>>>(out);
}

// round 14
// speedup vs baseline: 2.9249x; 1.0962x over previous
#include <cuda_runtime.h>
#include <cuda.h>
#include <cuda_fp16.h>
#include <cstdint>
#include <cmath>

// Problem constants
#define T_TOK 1024
#define HDIM  2048
#define NEXP  64
#define IDIM  1024
#define SIDIM 4096
#define KSEL  8
#define NROWS (T_TOK * KSEL)

// Tile config: CTA 128x128, 8 warps (4Mx2N), warp tile 32x64, fp16 BK=64.
#define BM 128
#define BN 128
#define NSTAGE 3
#define STG_B   32768                          // bytes per stage (A 16KB + B 16KB)
#define MBOFF   (NSTAGE * STG_B)               // 98304
#define GS_DENSE (MBOFF + 64 + 128)            // 98496

// ---------------------------------------------------------------------------
// Device-global scratch
// ---------------------------------------------------------------------------
__device__ __align__(256) __half g_w13h[(size_t)NEXP * 2 * IDIM * HDIM]; // 512MB
__device__ __align__(256) __half g_w2h [(size_t)NEXP * HDIM * IDIM];     // 256MB
__device__ __align__(256) __half g_wsgh[(size_t)2 * SIDIM * HDIM];       // 32MB
__device__ __align__(256) __half g_wsdh[(size_t)HDIM * SIDIM];           // 16MB
__device__ __align__(256) __half g_xh  [(size_t)T_TOK * HDIM];           // 4MB
__device__ __align__(256) __half g_xg  [(size_t)NROWS * HDIM];           // 32MB gathered x
__device__ __align__(256) __half g_h   [(size_t)NROWS * IDIM];
__device__ __align__(256) __half g_h_s [(size_t)T_TOK * SIDIM];
__device__ __align__(256) float  g_down[(size_t)NROWS * HDIM];
__device__ __align__(256) float  g_sh_out[(size_t)T_TOK * HDIM];

__device__ int   g_counts[NEXP];
__device__ int   g_offsets[NEXP];
__device__ int   g_fill[NEXP];
__device__ int   g_rowmap[NROWS];
__device__ int   g_row_of_tk[NROWS];
__device__ int   g_top_e[NROWS];
__device__ float g_top_w[NROWS];
__device__ int   g_ticket;

// ---------------------------------------------------------------------------
// Helpers
// ---------------------------------------------------------------------------
#define MBARRIER_INIT(addr, cnt) \
    asm volatile("mbarrier.init.shared.b64 [%0], %1;" :: "r"((uint32_t)(addr)), "r"((uint32_t)(cnt)) : "memory")

#define MBARRIER_EXPECT_TX(addr, bytes) \
    asm volatile("mbarrier.arrive.expect_tx.shared.b64 _, [%0], %1;" \
        :: "r"((uint32_t)(addr)), "r"((uint32_t)(bytes)) : "memory")

#define MBARRIER_WAIT_PARITY(addr, parity) do {                                         \
    uint32_t _m = (uint32_t)(addr); uint32_t _p = (uint32_t)(parity); uint32_t _d;      \
    asm volatile("{ .reg .pred p; mbarrier.try_wait.parity.acquire.cta.shared::cta.b64 p, [%1], %2; selp.b32 %0,1,0,p; }" \
        : "=r"(_d) : "r"(_m), "r"(_p) : "memory");                                      \
    if (!_d) {                                                                          \
        asm volatile("{ .reg .pred P1; WL_%=: mbarrier.try_wait.parity.acquire.cta.shared::cta.b64 P1, [%0], %1, 0x989680; @P1 bra.uni WD_%=; bra.uni WL_%=; WD_%=: }" \
            :: "r"(_m), "r"(_p) : "memory");                                            \
    }                                                                                   \
} while (0)

#define FENCE_ASYNC() asm volatile("fence.proxy.async.shared::cta;" ::: "memory")

__device__ __forceinline__ void tma2d(uint32_t dst, const CUtensorMap* tm, int x, int y, uint32_t mbar) {
    asm volatile("cp.async.bulk.tensor.2d.shared::cta.global.tile.mbarrier::complete_tx::bytes "
                 "[%0], [%1, {%2, %3}], [%4];"
                 :: "r"(dst), "l"(tm), "r"(x), "r"(y), "r"(mbar) : "memory");
}

__device__ __forceinline__ void ldm_x4(uint32_t& r0, uint32_t& r1, uint32_t& r2, uint32_t& r3,
                                       uint32_t addr) {
    asm volatile("ldmatrix.sync.aligned.m8n8.x4.shared.b16 {%0,%1,%2,%3}, [%4];"
                 : "=r"(r0), "=r"(r1), "=r"(r2), "=r"(r3) : "r"(addr));
}

__device__ __forceinline__ void mma_f16(float c[4],
                                        uint32_t a0, uint32_t a1, uint32_t a2, uint32_t a3,
                                        uint32_t b0, uint32_t b1) {
    asm volatile(
        "mma.sync.aligned.m16n8k16.row.col.f32.f16.f16.f32 "
        "{%0,%1,%2,%3},{%4,%5,%6,%7},{%8,%9},{%0,%1,%2,%3};\n"
        : "+f"(c[0]), "+f"(c[1]), "+f"(c[2]), "+f"(c[3])
        : "r"(a0), "r"(a1), "r"(a2), "r"(a3), "r"(b0), "r"(b1));
}

__device__ __forceinline__ float silu_mul(float g, float u) {
    return g * u / (1.f + expf(-g));
}

// ---------------------------------------------------------------------------
// fp32 -> fp16 convert kernels
// ---------------------------------------------------------------------------
__global__ void cvt_k(const float4* __restrict__ in, uint2* __restrict__ outp, long n4) {
    long i = (long)blockIdx.x * blockDim.x + threadIdx.x;
    long stride = (long)gridDim.x * blockDim.x;
    for (; i < n4; i += stride) {
        float4 v = in[i];
        __half2 h0 = __floats2half2_rn(v.x, v.y);
        __half2 h1 = __floats2half2_rn(v.z, v.w);
        uint2 o;
        o.x = *(uint32_t*)&h0;
        o.y = *(uint32_t*)&h1;
        outp[i] = o;
    }
}

__global__ void cvt_init_k(const float4* __restrict__ in, uint2* __restrict__ outp, long n4) {
    if (blockIdx.x == 0 && threadIdx.x < NEXP) g_counts[threadIdx.x] = 0;
    long i = (long)blockIdx.x * blockDim.x + threadIdx.x;
    long stride = (long)gridDim.x * blockDim.x;
    for (; i < n4; i += stride) {
        float4 v = in[i];
        __half2 h0 = __floats2half2_rn(v.x, v.y);
        __half2 h1 = __floats2half2_rn(v.z, v.w);
        uint2 o;
        o.x = *(uint32_t*)&h0;
        o.y = *(uint32_t*)&h1;
        outp[i] = o;
    }
}

// ---------------------------------------------------------------------------
// Fused router + scan + assign (ticket: last block finalizes)
// ---------------------------------------------------------------------------
__global__ void router_fused_k(const float* __restrict__ x, const float* __restrict__ wg) {
    int t = blockIdx.x;
    __shared__ float xs[HDIM];
    __shared__ float sc[NEXP];
    __shared__ int isLast;
    for (int d = threadIdx.x; d < HDIM; d += blockDim.x) xs[d] = x[(size_t)t * HDIM + d];
    __syncthreads();

    int w = threadIdx.x >> 5, lane = threadIdx.x & 31;
    for (int e = w * 8; e < w * 8 + 8; e++) {
        const float* wr = wg + (size_t)e * HDIM;
        float s = 0.f;
        for (int d = lane; d < HDIM; d += 32) s += xs[d] * wr[d];
        #pragma unroll
        for (int o = 16; o; o >>= 1) s += __shfl_xor_sync(0xffffffffu, s, o);
        if (lane == 0) sc[e] = 1.f / (1.f + expf(-s));
    }
    __syncthreads();

    if (threadIdx.x == 0) {
        for (int k = 0; k < KSEL; k++) {
            int best = 0; float bv = sc[0];
            for (int e = 1; e < NEXP; e++)
                if (sc[e] > bv) { bv = sc[e]; best = e; }
            g_top_e[t * KSEL + k] = best;
            g_top_w[t * KSEL + k] = bv;
            atomicAdd(&g_counts[best], 1);
            sc[best] = -1.f;
        }
    }

    __threadfence();
    if (threadIdx.x == 0) {
        int tk = atomicAdd(&g_ticket, 1);
        isLast = (tk == (int)gridDim.x - 1);
        if (isLast) g_ticket = 0;
    }
    __syncthreads();
    if (!isLast) return;

    if (threadIdx.x == 0) {
        int acc = 0;
        for (int e = 0; e < NEXP; e++) {
            g_offsets[e] = acc;
            g_fill[e] = acc;
            acc += g_counts[e];
        }
    }
    __syncthreads();
    for (int idx = threadIdx.x; idx < NROWS; idx += blockDim.x) {
        int e = g_top_e[idx];
        int r = atomicAdd(&g_fill[e], 1);
        g_rowmap[r] = idx >> 3;
        g_row_of_tk[idx] = r;
    }
}

// ---------------------------------------------------------------------------
// gather_k — materialize gathered A: g_xg[r] = g_xh[rowmap[r]] (fp16 rows)
// One block per packed row; 256 threads x 16B = 4096B row.
// ---------------------------------------------------------------------------
__global__ void gather_k() {
    int r = blockIdx.x;
    int src = g_rowmap[r];
    const uint4* s = (const uint4*)(g_xh + (size_t)src * HDIM);
    uint4* d = (uint4*)(g_xg + (size_t)r * HDIM);
    d[threadIdx.x] = s[threadIdx.x];
}

// ---------------------------------------------------------------------------
// gemm10 — FP16 mma.sync, ALL operands via TMA tensor loads (SW128 swizzle =
// the chunk c^(r&7) mapping verified rounds 5-13). CTA 128x128, 8 warps
// (4Mx2N), warp tile 32x64, BK=64 fp16, 3-stage mbarrier ring.
//   C[m,n] = sum_k A[m,k]*B[n,k]; fp32 accum.
//   ACT: B tile = 64 gate + 64 up rows; epilogue silu(g)*u -> __half.
// ---------------------------------------------------------------------------
template <bool EXPERT, bool ACT>
__global__ void __launch_bounds__(256, 2)
gemm10(const __grid_constant__ CUtensorMap tmA,
       const __grid_constant__ CUtensorMap tmB,
       void* __restrict__ Cv,
       int Kd, int Nout, int rowsBe, int upOff, int Mdense, int eBase)
{
    extern __shared__ char sm[];
    int e = EXPERT ? (eBase + blockIdx.z) : 0;
    int M, off;
    if (EXPERT) { M = g_counts[e]; off = g_offsets[e]; }
    else        { M = Mdense;      off = 0; }
    int m0 = blockIdx.y * BM;
    if (m0 >= M) return;
    int nb = blockIdx.x;

    int tid = threadIdx.x, warp = tid >> 5, lane = tid & 31;
    uint32_t smem_base = (uint32_t)__cvta_generic_to_shared(sm);
    const CUtensorMap* tmAp = &tmA;
    const CUtensorMap* tmBp = &tmB;
    int rowBase = EXPERT ? e * rowsBe : 0;
    int aRow0 = off + m0;

    if (tid == 0) {
        #pragma unroll
        for (int s = 0; s < NSTAGE; s++) MBARRIER_INIT(smem_base + MBOFF + s * 8, 1);
        FENCE_ASYNC();
    }
    __syncthreads();

    auto stage_issue = [&](int kt, int s) {
        if (tid == 0) {
            uint32_t mb = smem_base + (uint32_t)(MBOFF + s * 8);
            uint32_t stg = smem_base + (uint32_t)(s * STG_B);
            int k0 = kt * 64;
            MBARRIER_EXPECT_TX(mb, STG_B);
            tma2d(stg, tmAp, k0, aRow0, mb);
            if (ACT) {
                tma2d(stg + 16384,            tmBp, k0, rowBase + nb * 64,         mb);
                tma2d(stg + 16384 + 64 * 128, tmBp, k0, rowBase + upOff + nb * 64, mb);
            } else {
                tma2d(stg + 16384, tmBp, k0, rowBase + nb * BN, mb);
            }
        }
    };

    // ---- consumer constants (verified fragment mapping; chunk = k8 block)
    int wm = warp & 3;               // M slice (32 rows)
    int wn = warp >> 2;              // N slice (64 B rows)
    int g  = lane >> 2, tg = lane & 3;

    int aro  = (lane & 7) + ((lane >> 3) & 1) * 8;
    int acs  = (lane >> 4) & 1;
    int bro  = (lane & 7) + ((lane >> 4) & 1) * 8;
    int bcs  = (lane >> 3) & 1;

    uint32_t aRow[2], aMod[2];
    #pragma unroll
    for (int mi = 0; mi < 2; mi++) {
        int r = wm * 32 + mi * 16 + aro;
        aRow[mi] = (uint32_t)(r * 128);
        aMod[mi] = (uint32_t)(r & 7);
    }
    uint32_t bRow[4], bMod[4];
    #pragma unroll
    for (int p = 0; p < 4; p++) {
        int base;
        if (ACT) base = (p < 2) ? (wn * 32 + p * 16) : (64 + wn * 32 + (p - 2) * 16);
        else     base = wn * 64 + p * 16;
        int r = base + bro;
        bRow[p] = (uint32_t)(16384 + r * 128);
        bMod[p] = (uint32_t)(r & 7);
    }

    float acc[2][8][4];
    #pragma unroll
    for (int i = 0; i < 2; i++)
        #pragma unroll
        for (int j = 0; j < 8; j++)
            #pragma unroll
            for (int q = 0; q < 4; q++) acc[i][j][q] = 0.f;

    int ktiles = Kd / 64;
    stage_issue(0, 0);
    stage_issue(1, 1);
    uint32_t phases = 0;

    for (int kt = 0; kt < ktiles; kt++) {
        int s = kt % NSTAGE;
        uint32_t mb = smem_base + (uint32_t)(MBOFF + s * 8);
        MBARRIER_WAIT_PARITY(mb, (phases >> s) & 1);
        phases ^= (1u << s);
        uint32_t stg = smem_base + (uint32_t)(s * STG_B);

        #pragma unroll
        for (int kk = 0; kk < 4; kk++) {
            uint32_t c0 = (uint32_t)(kk * 2);

            uint32_t afr[2][4];
            #pragma unroll
            for (int mi = 0; mi < 2; mi++) {
                uint32_t addr = stg + aRow[mi] + ((((c0 + acs) ^ aMod[mi])) << 4);
                ldm_x4(afr[mi][0], afr[mi][1], afr[mi][2], afr[mi][3], addr);
            }
            uint32_t bfr[4][4];
            #pragma unroll
            for (int p = 0; p < 4; p++) {
                uint32_t addr = stg + bRow[p] + ((((c0 + bcs) ^ bMod[p])) << 4);
                ldm_x4(bfr[p][0], bfr[p][1], bfr[p][2], bfr[p][3], addr);
            }
            #pragma unroll
            for (int p = 0; p < 4; p++) {
                #pragma unroll
                for (int h = 0; h < 2; h++) {
                    int ni = p * 2 + h;
                    uint32_t b0 = bfr[p][2 * h], b1 = bfr[p][2 * h + 1];
                    mma_f16(acc[0][ni], afr[0][0], afr[0][1], afr[0][2], afr[0][3], b0, b1);
                    mma_f16(acc[1][ni], afr[1][0], afr[1][1], afr[1][2], afr[1][3], b0, b1);
                }
            }
        }
        __syncthreads();
        if (kt + 2 < ktiles) stage_issue(kt + 2, (kt + 2) % NSTAGE);
    }

    // ---- epilogue
    #pragma unroll
    for (int mi = 0; mi < 2; mi++) {
        int r0 = m0 + wm * 32 + mi * 16 + g;
        bool v0 = r0 < M, v1 = (r0 + 8) < M;
        size_t base0 = (size_t)(off + r0) * Nout;
        size_t base1 = (size_t)(off + r0 + 8) * Nout;
        if (ACT) {
            __half* Ch = (__half*)Cv;
            #pragma unroll
            for (int ni = 0; ni < 4; ni++) {
                int col = nb * 64 + wn * 32 + ni * 8 + tg * 2;
                if (v0) {
                    __half2 o = __floats2half2_rn(
                        silu_mul(acc[mi][ni][0], acc[mi][ni + 4][0]),
                        silu_mul(acc[mi][ni][1], acc[mi][ni + 4][1]));
                    *(__half2*)(Ch + base0 + col) = o;
                }
                if (v1) {
                    __half2 o = __floats2half2_rn(
                        silu_mul(acc[mi][ni][2], acc[mi][ni + 4][2]),
                        silu_mul(acc[mi][ni][3], acc[mi][ni + 4][3]));
                    *(__half2*)(Ch + base1 + col) = o;
                }
            }
        } else {
            float* Cf = (float*)Cv;
            #pragma unroll
            for (int ni = 0; ni < 8; ni++) {
                int col = nb * BN + wn * 64 + ni * 8 + tg * 2;
                if (v0) {
                    float2 o; o.x = acc[mi][ni][0]; o.y = acc[mi][ni][1];
                    *(float2*)(Cf + base0 + col) = o;
                }
                if (v1) {
                    float2 o; o.x = acc[mi][ni][2]; o.y = acc[mi][ni][3];
                    *(float2*)(Cf + base1 + col) = o;
                }
            }
        }
    }
}

// ---------------------------------------------------------------------------
// Combine
// ---------------------------------------------------------------------------
__global__ void combine_k(float* __restrict__ out) {
    int t = blockIdx.x;
    __shared__ int   rws[KSEL];
    __shared__ float ws[KSEL];
    if (threadIdx.x < KSEL) {
        rws[threadIdx.x] = g_row_of_tk[t * KSEL + threadIdx.x];
        ws[threadIdx.x]  = g_top_w[t * KSEL + threadIdx.x];
    }
    __syncthreads();
    for (int d = threadIdx.x; d < HDIM; d += blockDim.x) {
        float a = g_sh_out[(size_t)t * HDIM + d];
        float m = 0.f;
        #pragma unroll
        for (int k = 0; k < KSEL; k++)
            m += ws[k] * g_down[(size_t)rws[k] * HDIM + d];
        out[(size_t)t * HDIM + d] = (a + 8.f * m) * (1.f / 9.f);
    }
}

// ---------------------------------------------------------------------------
// kernel_launch — graph-capturable, allocation-free, three-stream DAG.
// ---------------------------------------------------------------------------
typedef CUresult (CUDAAPI *PFN_encodeTiled)(
    CUtensorMap*, CUtensorMapDataType, cuuint32_t, void*,
    const cuuint64_t*, const cuuint64_t*, const cuuint32_t*, const cuuint32_t*,
    CUtensorMapInterleave, CUtensorMapSwizzle, CUtensorMapL2promotion,
    CUtensorMapFloatOOBfill);

extern "C" void kernel_launch(void* const* d_in, const int* in_sizes, int n_in,
                              void* d_out, int out_size)
{
    const float* x      = (const float*)d_in[0];
    const float* w_gate = (const float*)d_in[1];
    const float* w13    = (const float*)d_in[2];
    const float* w2     = (const float*)d_in[3];
    const float* wsg    = (const float*)d_in[4];
    const float* wsd    = (const float*)d_in[5];
    float* out = (float*)d_out;

    __half *p_w13h, *p_w2h, *p_wsgh, *p_wsdh, *p_xh, *p_xg, *p_h, *p_h_s;
    float  *p_down, *p_sh_out;
    cudaGetSymbolAddress((void**)&p_w13h,   g_w13h);
    cudaGetSymbolAddress((void**)&p_w2h,    g_w2h);
    cudaGetSymbolAddress((void**)&p_wsgh,   g_wsgh);
    cudaGetSymbolAddress((void**)&p_wsdh,   g_wsdh);
    cudaGetSymbolAddress((void**)&p_xh,     g_xh);
    cudaGetSymbolAddress((void**)&p_xg,     g_xg);
    cudaGetSymbolAddress((void**)&p_h,      g_h);
    cudaGetSymbolAddress((void**)&p_h_s,    g_h_s);
    cudaGetSymbolAddress((void**)&p_down,   g_down);
    cudaGetSymbolAddress((void**)&p_sh_out, g_sh_out);

    static bool tmInit = false;
    static CUtensorMap tmXh, tmXg, tmH, tmHs, tmW13, tmW2, tmWsg, tmWsd;
    if (!tmInit) {
        PFN_encodeTiled enc = nullptr;
        cudaDriverEntryPointQueryResult qr;
        cudaGetDriverEntryPoint("cuTensorMapEncodeTiled", (void**)&enc, cudaEnableDefault, &qr);
        auto mk = [&](CUtensorMap* tm, void* ptr, unsigned long long d0, unsigned long long d1,
                      unsigned b0, unsigned b1) {
            cuuint64_t dims[2]    = {d0, d1};
            cuuint64_t strides[1] = {d0 * 2};
            cuuint32_t box[2]     = {b0, b1};
            cuuint32_t es[2]      = {1, 1};
            enc(tm, CU_TENSOR_MAP_DATA_TYPE_FLOAT16, 2, ptr, dims, strides, box, es,
                CU_TENSOR_MAP_INTERLEAVE_NONE, CU_TENSOR_MAP_SWIZZLE_128B,
                CU_TENSOR_MAP_L2_PROMOTION_L2_128B, CU_TENSOR_MAP_FLOAT_OOB_FILL_NONE);
        };
        mk(&tmXh,  p_xh,   HDIM,  T_TOK,                               64, 128);
        mk(&tmXg,  p_xg,   HDIM,  NROWS,                               64, 128);
        mk(&tmH,   p_h,    IDIM,  NROWS,                               64, 128);
        mk(&tmHs,  p_h_s,  SIDIM, T_TOK,                               64, 128);
        mk(&tmW13, p_w13h, HDIM,  (unsigned long long)NEXP * 2 * IDIM, 64, 64);
        mk(&tmW2,  p_w2h,  IDIM,  (unsigned long long)NEXP * HDIM,     64, 128);
        mk(&tmWsg, p_wsgh, HDIM,  2 * SIDIM,                           64, 64);
        mk(&tmWsd, p_wsdh, SIDIM, HDIM,                                64, 128);
        tmInit = true;
    }

    cudaFuncSetAttribute(gemm10<true,  true >, cudaFuncAttributeMaxDynamicSharedMemorySize, GS_DENSE);
    cudaFuncSetAttribute(gemm10<true,  false>, cudaFuncAttributeMaxDynamicSharedMemorySize, GS_DENSE);
    cudaFuncSetAttribute(gemm10<false, true >, cudaFuncAttributeMaxDynamicSharedMemorySize, GS_DENSE);
    cudaFuncSetAttribute(gemm10<false, false>, cudaFuncAttributeMaxDynamicSharedMemorySize, GS_DENSE);

    static cudaStream_t s2 = nullptr, s3 = nullptr;
    static cudaEvent_t evFork = nullptr, evX = nullptr, evW13a = nullptr,
                       evW13b = nullptr, evW2 = nullptr, evJoin = nullptr;
    if (!s2) {
        cudaStreamCreateWithFlags(&s2, cudaStreamNonBlocking);
        cudaStreamCreateWithFlags(&s3, cudaStreamNonBlocking);
        cudaEventCreateWithFlags(&evFork,  cudaEventDisableTiming);
        cudaEventCreateWithFlags(&evX,     cudaEventDisableTiming);
        cudaEventCreateWithFlags(&evW13a,  cudaEventDisableTiming);
        cudaEventCreateWithFlags(&evW13b,  cudaEventDisableTiming);
        cudaEventCreateWithFlags(&evW2,    cudaEventDisableTiming);
        cudaEventCreateWithFlags(&evJoin,  cudaEventDisableTiming);
    }

    const size_t W13_HALF = (size_t)(NEXP / 2) * 2 * IDIM * HDIM;   // elements

    // fork at t=0
    cudaEventRecord(evFork, 0);
    cudaStreamWaitEvent(s2, evFork, 0);
    cudaStreamWaitEvent(s3, evFork, 0);

    // #1 s0: cvt x (zeros router counts)
    cvt_init_k<<<1024, 256>>>((const float4*)x, (uint2*)p_xh, (long)T_TOK * HDIM / 4);
    cudaEventRecord(evX, 0);

    // #2 s0: fused router + scan + assign
    router_fused_k<<<T_TOK, 256>>>(x, w_gate);

    // #3 s2: w13 first-half convert
    cvt_k<<<8192, 256, 0, s2>>>((const float4*)w13, (uint2*)p_w13h, (long)(W13_HALF / 4));
    cudaEventRecord(evW13a, s2);

    // #4 s0: materialize gathered A (needs router + xh, both in s0 order)
    gather_k<<<NROWS, 256>>>();

    // #5 s2: w13 second-half convert
    cvt_k<<<8192, 256, 0, s2>>>((const float4*)(w13 + W13_HALF), (uint2*)(p_w13h + W13_HALF),
                                (long)(W13_HALF / 4));
    cudaEventRecord(evW13b, s2);

    // #6 s0: MoE gate_up, experts 0-31 (ncu profile slot)
    cudaStreamWaitEvent(0, evW13a, 0);
    gemm10<true, true><<<dim3(IDIM / 64, 8, NEXP / 2), 256, GS_DENSE>>>(
        tmXg, tmW13, p_h, HDIM, IDIM, 2 * IDIM, IDIM, 0, 0);

    // #7 s0: MoE gate_up, experts 32-63
    cudaStreamWaitEvent(0, evW13b, 0);
    gemm10<true, true><<<dim3(IDIM / 64, 8, NEXP / 2), 256, GS_DENSE>>>(
        tmXg, tmW13, p_h, HDIM, IDIM, 2 * IDIM, IDIM, 0, NEXP / 2);

    // #8 s2: w2 convert
    cvt_k<<<8192, 256, 0, s2>>>((const float4*)w2, (uint2*)p_w2h, (long)NEXP * HDIM * IDIM / 4);
    cudaEventRecord(evW2, s2);

    // s3: shared chain
    cvt_k<<<2048, 256, 0, s3>>>((const float4*)wsg, (uint2*)p_wsgh, (long)2 * SIDIM * HDIM / 4);
    cvt_k<<<2048, 256, 0, s3>>>((const float4*)wsd, (uint2*)p_wsdh, (long)HDIM * SIDIM / 4);
    cudaStreamWaitEvent(s3, evX, 0);
    gemm10<false, true ><<<dim3(SIDIM / 64, T_TOK / BM, 1), 256, GS_DENSE, s3>>>(
        tmXh, tmWsg, p_h_s, HDIM, SIDIM, 0, SIDIM, T_TOK, 0);
    gemm10<false, false><<<dim3(HDIM / BN, T_TOK / BM, 1), 256, GS_DENSE, s3>>>(
        tmHs, tmWsd, p_sh_out, SIDIM, HDIM, 0, 0, T_TOK, 0);
    cudaEventRecord(evJoin, s3);

    // s0: MoE down
    cudaStreamWaitEvent(0, evW2, 0);
    gemm10<true, false><<<dim3(HDIM / BN, 8, NEXP), 256, GS_DENSE>>>(
        tmH, tmW2, p_down, IDIM, HDIM, HDIM, 0, 0, 0);

    // s0: combine
    cudaStreamWaitEvent(0, evJoin, 0);
    combine_k<<<T_TOK, 256>>>(out);
}